// round 2
// baseline (speedup 1.0000x reference)
#include <cuda_runtime.h>
#include <cstddef>

constexpr int Cc   = 64;
constexpr int Np   = 65536;
constexpr int Lnum = 4;
constexpr int Bn   = 2;
constexpr int WTP  = 260;   // WT smem pitch
constexpr int XP   = 68;    // Xs pitch
constexpr int YP   = 65;    // Ykv pitch
constexpr int SMEM_P2 = (64*WTP + 256 + 64 + 64 + 64*XP + 128*YP) * 4; // 118784 B

__device__ float  g_feat[(size_t)Bn * Cc * Np];
__device__ double g_stats[Bn * 8 * 2];
__device__ float  g_afold[Bn * Cc];
__device__ float  g_bfold[Bn * Cc];
__device__ float  g_know[Bn * Cc * Cc];
__device__ float  g_fsum[Bn * Cc];
__device__ float  g_M2[Bn * Cc * Cc];
__device__ float  g_d2[Bn * Cc];

__global__ void zero_kernel() {
    int i = blockIdx.x * 256 + threadIdx.x;
    if (i < Bn * Cc * Cc) g_know[i] = 0.f;
    if (i < Bn * Cc)      g_fsum[i] = 0.f;
    if (i < Bn * 16)      g_stats[i] = 0.0;
}

// -------- conv3x3 in: x[2,2,256,256] -> g_feat[2,64,256,256], one row/block
__global__ void __launch_bounds__(256) conv_in_kernel(
    const float* __restrict__ x, const float* __restrict__ W,
    const float* __restrict__ bias)
{
    __shared__ float xs[2 * 3 * 258];
    __shared__ float ws[64 * 18];
    __shared__ float bsh[64];
    int b = blockIdx.y, y = blockIdx.x, tid = threadIdx.x;
    for (int i = tid; i < 64 * 18; i += 256) ws[i] = W[i];
    if (tid < 64) bsh[tid] = bias[tid];
    for (int i = tid; i < 2 * 3 * 258; i += 256) {
        int c = i / 774, rem = i % 774, r = rem / 258, col = rem % 258;
        int yy = y + r - 1, xx = col - 1;
        float v = 0.f;
        if (yy >= 0 && yy < 256 && xx >= 0 && xx < 256)
            v = x[((size_t)(b * 2 + c) * 256 + yy) * 256 + xx];
        xs[i] = v;
    }
    __syncthreads();
    float in[18];
#pragma unroll
    for (int c = 0; c < 2; c++)
#pragma unroll
        for (int r = 0; r < 3; r++)
#pragma unroll
            for (int k = 0; k < 3; k++)
                in[c * 9 + r * 3 + k] = xs[c * 774 + r * 258 + tid + k];
    size_t ob = (size_t)b * Cc * Np + y * 256 + tid;
    for (int oc = 0; oc < 64; oc++) {
        float acc = bsh[oc];
#pragma unroll
        for (int t = 0; t < 18; t++) acc += ws[oc * 18 + t] * in[t];
        g_feat[ob + (size_t)oc * Np] = acc;
    }
}

// -------- GN stats: per (b,g) sum/sumsq over contiguous 8*Np slab
__global__ void __launch_bounds__(256) stats_kernel() {
    int bg = blockIdx.y;
    const float* base = g_feat + (size_t)bg * 8 * Np;
    int start = blockIdx.x * 8192;
    float s = 0.f, q = 0.f;
    for (int i = start + threadIdx.x; i < start + 8192; i += 256) {
        float v = base[i]; s += v; q += v * v;
    }
    __shared__ float rs[256], rq[256];
    rs[threadIdx.x] = s; rq[threadIdx.x] = q;
    __syncthreads();
    for (int off = 128; off > 0; off >>= 1) {
        if (threadIdx.x < off) {
            rs[threadIdx.x] += rs[threadIdx.x + off];
            rq[threadIdx.x] += rq[threadIdx.x + off];
        }
        __syncthreads();
    }
    if (threadIdx.x == 0) {
        atomicAdd(&g_stats[bg * 2 + 0], (double)rs[0]);
        atomicAdd(&g_stats[bg * 2 + 1], (double)rq[0]);
    }
}

__global__ void fold_kernel(const float* __restrict__ gamma,
                            const float* __restrict__ beta)
{
    int b = blockIdx.x, c = threadIdx.x, g = c >> 3;
    double inv = 1.0 / (8.0 * 65536.0);
    double mu  = g_stats[(b * 8 + g) * 2 + 0] * inv;
    double var = g_stats[(b * 8 + g) * 2 + 1] * inv - mu * mu;
    float a = gamma[c] * rsqrtf((float)var + 1e-5f);
    g_afold[b * 64 + c] = a;
    g_bfold[b * 64 + c] = beta[c] - (float)mu * a;
}

// -------- pass 2: fused [k,v,f,i] GEMM + gates + knowledge outer product
__device__ __forceinline__ void gemm_chunk(const float* WT, const float* bias,
                                           const float* Xs, int chunkBase,
                                           int ty, int pb, float acc[8][4])
{
    int ocb = chunkBase + ty * 8;
#pragma unroll
    for (int j = 0; j < 8; j++) {
        float bb = bias[ocb + j];
#pragma unroll
        for (int q = 0; q < 4; q++) acc[j][q] = bb;
    }
#pragma unroll 4
    for (int c = 0; c < 64; c++) {
        float4 xv4 = *(const float4*)&Xs[c * XP + pb];
        float4 w0  = *(const float4*)&WT[c * WTP + ocb];
        float4 w1  = *(const float4*)&WT[c * WTP + ocb + 4];
        float xv[4] = {xv4.x, xv4.y, xv4.z, xv4.w};
        float wv[8] = {w0.x, w0.y, w0.z, w0.w, w1.x, w1.y, w1.z, w1.w};
#pragma unroll
        for (int j = 0; j < 8; j++)
#pragma unroll
            for (int q = 0; q < 4; q++) acc[j][q] += wv[j] * xv[q];
    }
}

__global__ void __launch_bounds__(256, 1) pass2_kernel(
    const float* __restrict__ Wk, const float* __restrict__ bk,
    const float* __restrict__ Wv, const float* __restrict__ bv,
    const float* __restrict__ Wg, const float* __restrict__ bg)
{
    extern __shared__ float sm[];
    float* WT   = sm;                  // [64][WTP]
    float* bias = WT + 64 * WTP;       // 256
    float* av   = bias + 256;          // 64
    float* bs   = av + 64;             // 64
    float* Xs   = bs + 64;             // [64][XP]
    float* Ykv  = Xs + 64 * XP;        // [128][YP] rows 0..63 kgated, 64..127 v

    int b = blockIdx.y, tid = threadIdx.x;
    for (int i = tid; i < 4096; i += 256) {
        int oc = i >> 6, c = i & 63;
        WT[c * WTP + oc]      = Wk[i];
        WT[c * WTP + 64 + oc] = Wv[i];
    }
    for (int i = tid; i < 8192; i += 256) {
        int oc = i >> 6, c = i & 63;
        WT[c * WTP + 128 + oc] = Wg[i];
    }
    if (tid < 64) {
        bias[tid]       = bk[tid];
        bias[64 + tid]  = bv[tid];
        bias[128 + tid] = bg[tid];
        bias[192 + tid] = bg[64 + tid];
        av[tid] = g_afold[b * 64 + tid];
        bs[tid] = g_bfold[b * 64 + tid];
    }

    int ty = tid >> 4, tx = tid & 15, pb = tx * 4;
    float kacc[4][4];
#pragma unroll
    for (int i = 0; i < 4; i++)
#pragma unroll
        for (int j = 0; j < 4; j++) kacc[i][j] = 0.f;
    float fpart[8];
#pragma unroll
    for (int j = 0; j < 8; j++) fpart[j] = 0.f;

    const float* fb = g_feat + (size_t)b * Cc * Np;

    for (int tile = blockIdx.x; tile < 1024; tile += gridDim.x) {
        int n0 = tile * 64;
        __syncthreads();
        for (int i = tid; i < 4096; i += 256) {
            int c = i >> 6, p = i & 63;
            Xs[c * XP + p] = fb[(size_t)c * Np + n0 + p] * av[c] + bs[c];
        }
        __syncthreads();
        {   // k rows 0..63, v rows 64..127
            float acc[8][4];
            gemm_chunk(WT, bias, Xs, 0, ty, pb, acc);
            int ocb = ty * 8;
#pragma unroll
            for (int j = 0; j < 8; j++)
#pragma unroll
                for (int q = 0; q < 4; q++)
                    Ykv[(ocb + j) * YP + pb + q] = acc[j][q];
        }
        __syncthreads();
        {   // gate rows: f (128..191) mean; i (192..255) gate k
            float acc[8][4];
            gemm_chunk(WT, bias, Xs, 128, ty, pb, acc);
            if (ty < 8) {
#pragma unroll
                for (int j = 0; j < 8; j++)
#pragma unroll
                    for (int q = 0; q < 4; q++)
                        fpart[j] += 1.f / (1.f + __expf(-acc[j][q]));
            } else {
                int chb = ty * 8 - 64;
#pragma unroll
                for (int j = 0; j < 8; j++)
#pragma unroll
                    for (int q = 0; q < 4; q++)
                        Ykv[(chb + j) * YP + pb + q] *=
                            1.f / (1.f + __expf(-acc[j][q]));
            }
        }
        __syncthreads();
        {   // knowledge[c][d] += kg[c][p]*v[d][p]
            int cb = ty * 4;
#pragma unroll 2
            for (int p = 0; p < 64; p++) {
                float k0 = Ykv[(cb + 0) * YP + p];
                float k1 = Ykv[(cb + 1) * YP + p];
                float k2 = Ykv[(cb + 2) * YP + p];
                float k3 = Ykv[(cb + 3) * YP + p];
                float v0 = Ykv[(64 + tx +  0) * YP + p];
                float v1 = Ykv[(64 + tx + 16) * YP + p];
                float v2 = Ykv[(64 + tx + 32) * YP + p];
                float v3 = Ykv[(64 + tx + 48) * YP + p];
                kacc[0][0] += k0*v0; kacc[0][1] += k0*v1; kacc[0][2] += k0*v2; kacc[0][3] += k0*v3;
                kacc[1][0] += k1*v0; kacc[1][1] += k1*v1; kacc[1][2] += k1*v2; kacc[1][3] += k1*v3;
                kacc[2][0] += k2*v0; kacc[2][1] += k2*v1; kacc[2][2] += k2*v2; kacc[2][3] += k2*v3;
                kacc[3][0] += k3*v0; kacc[3][1] += k3*v1; kacc[3][2] += k3*v2; kacc[3][3] += k3*v3;
            }
        }
    }
    float* kb = g_know + b * 4096;
    int cb = ty * 4;
#pragma unroll
    for (int i = 0; i < 4; i++)
#pragma unroll
        for (int j = 0; j < 4; j++)
            atomicAdd(&kb[(cb + i) * 64 + tx + 16 * j], kacc[i][j]);
    if (ty < 8) {
#pragma unroll
        for (int j = 0; j < 8; j++)
            atomicAdd(&g_fsum[b * 64 + ty * 8 + j], fpart[j]);
    }
}

// -------- new_mem + fold pass-3 into M2 [e][o] and d2[o]
__global__ void __launch_bounds__(256) memfold_kernel(
    const float* __restrict__ hidden, const float* __restrict__ Wq,
    const float* __restrict__ bq, const float* __restrict__ Wp,
    const float* __restrict__ bp, float* __restrict__ hid_out)
{
    int b = blockIdx.x, tid = threadIdx.x;
    __shared__ float memS[4096], T[4096], rS[64], uS[64], fm[64];
    if (tid < 64) fm[tid] = g_fsum[b * 64 + tid] * (1.f / 65536.f);
    __syncthreads();
    const float* kb = g_know + b * 4096;
    const float* hb = hidden + (size_t)b * Lnum * 4096;
    float* ho = hid_out + (size_t)b * Lnum * 4096;
    for (int i = tid; i < 4096; i += 256) {
        int c = i >> 6;
        float m = fm[c] * hb[i] + kb[i] * (1.f / 65536.f);
        memS[i] = m; ho[i] = m;
    }
    if (tid < 64) {
        float u = bq[tid];
        for (int e = 0; e < 64; e++) u += Wq[tid * 64 + e] * g_bfold[b * 64 + e];
        uS[tid] = u;
    }
    __syncthreads();
    if (tid < 64) {
        float r = 0.f;
        for (int c = 0; c < 64; c++) r += memS[c * 64 + tid] * uS[c];
        rS[tid] = r;
    }
    for (int i = tid; i < 4096; i += 256) {     // T[d][e] = sum_c M[c][d]Wq[c][e]*a[e]
        int d = i >> 6, e = i & 63;
        float t = 0.f;
        for (int c = 0; c < 64; c++) t += memS[c * 64 + d] * Wq[c * 64 + e];
        T[i] = t * g_afold[b * 64 + e];
    }
    __syncthreads();
    for (int i = tid; i < 4096; i += 256)       // memS <- Wp^T  (WpT[d][o])
        memS[i] = Wp[(i & 63) * 64 + (i >> 6)];
    __syncthreads();
    const float scale = 0.125f;
    for (int i = tid; i < 4096; i += 256) {     // g_M2[e*64+o]
        int e = i >> 6, o = i & 63;
        float m = 0.f;
        for (int d = 0; d < 64; d++) m += memS[d * 64 + o] * T[d * 64 + e];
        g_M2[b * 4096 + i] = m * scale;
    }
    if (tid < 64) {
        float s = 0.f;
        for (int d = 0; d < 64; d++) s += memS[d * 64 + tid] * rS[d];
        g_d2[b * 64 + tid] = s * scale + bp[tid];
    }
}

// -------- pass 3: feat <- feat + M2*feat + d2 (per 64-pixel tile, in place)
__global__ void __launch_bounds__(256) pass3_kernel() {
    __shared__ float M2s[4096], Xs[64 * XP], d2s[64];
    int b = blockIdx.y, n0 = blockIdx.x * 64, tid = threadIdx.x;
    for (int i = tid; i < 4096; i += 256) M2s[i] = g_M2[b * 4096 + i];
    if (tid < 64) d2s[tid] = g_d2[b * 64 + tid];
    float* fb = g_feat + (size_t)b * Cc * Np;
    for (int i = tid; i < 4096; i += 256) {
        int c = i >> 6, p = i & 63;
        Xs[c * XP + p] = fb[(size_t)c * Np + n0 + p];
    }
    __syncthreads();
    int ty = tid >> 4, tx = tid & 15, ob = ty * 4, pb = tx * 4;
    float acc[4][4];
#pragma unroll
    for (int i = 0; i < 4; i++) {
        float d = d2s[ob + i];
#pragma unroll
        for (int q = 0; q < 4; q++) acc[i][q] = d;
    }
#pragma unroll 4
    for (int e = 0; e < 64; e++) {
        float4 xv4 = *(const float4*)&Xs[e * XP + pb];
        float4 mv4 = *(const float4*)&M2s[e * 64 + ob];
        float xv[4] = {xv4.x, xv4.y, xv4.z, xv4.w};
        float mv[4] = {mv4.x, mv4.y, mv4.z, mv4.w};
#pragma unroll
        for (int i = 0; i < 4; i++)
#pragma unroll
            for (int q = 0; q < 4; q++) acc[i][q] += mv[i] * xv[q];
    }
#pragma unroll
    for (int i = 0; i < 4; i++)
#pragma unroll
        for (int q = 0; q < 4; q++)
            fb[(size_t)(ob + i) * Np + n0 + pb + q] =
                acc[i][q] + Xs[(ob + i) * XP + pb + q];
}

// -------- conv3x3 out + residual
__global__ void __launch_bounds__(256) conv_out_kernel(
    const float* __restrict__ x, const float* __restrict__ W,
    const float* __restrict__ bias, float* __restrict__ out)
{
    __shared__ float fs[8 * 3 * 258];
    __shared__ float ws[1152];
    int b = blockIdx.y, y = blockIdx.x, tid = threadIdx.x;
    for (int i = tid; i < 1152; i += 256) ws[i] = W[i];
    float acc0 = bias[0], acc1 = bias[1];
    const float* fb = g_feat + (size_t)b * Cc * Np;
    for (int cc = 0; cc < 64; cc += 8) {
        __syncthreads();
        for (int i = tid; i < 6192; i += 256) {
            int c = i / 774, rem = i % 774, r = rem / 258, col = rem % 258;
            int yy = y + r - 1, xx = col - 1;
            float v = 0.f;
            if (yy >= 0 && yy < 256 && xx >= 0 && xx < 256)
                v = fb[(size_t)(cc + c) * Np + yy * 256 + xx];
            fs[i] = v;
        }
        __syncthreads();
#pragma unroll
        for (int c = 0; c < 8; c++) {
            float in[9];
#pragma unroll
            for (int r = 0; r < 3; r++)
#pragma unroll
                for (int k = 0; k < 3; k++)
                    in[r * 3 + k] = fs[c * 774 + r * 258 + tid + k];
            const float* w0 = &ws[(cc + c) * 9];
            const float* w1 = &ws[(64 + cc + c) * 9];
#pragma unroll
            for (int t = 0; t < 9; t++) { acc0 += w0[t] * in[t]; acc1 += w1[t] * in[t]; }
        }
    }
    int o = y * 256 + tid;
    out[(size_t)(b * 2 + 0) * Np + o] = acc0 + x[(size_t)(b * 2 + 0) * Np + o];
    out[(size_t)(b * 2 + 1) * Np + o] = acc1 + x[(size_t)(b * 2 + 1) * Np + o];
}

extern "C" void kernel_launch(void* const* d_in, const int* in_sizes, int n_in,
                              void* d_out, int out_size)
{
    const float* x      = (const float*)d_in[0];
    const float* hidden = (const float*)d_in[1];
    const float* W_in   = (const float*)d_in[2];
    const float* b_in   = (const float*)d_in[3];
    const float* gamma  = (const float*)d_in[4];
    const float* beta   = (const float*)d_in[5];
    const float* Wq     = (const float*)d_in[6];
    const float* bq     = (const float*)d_in[7];
    const float* Wk     = (const float*)d_in[8];
    const float* bk     = (const float*)d_in[9];
    const float* Wv     = (const float*)d_in[10];
    const float* bv     = (const float*)d_in[11];
    const float* Wg     = (const float*)d_in[12];
    const float* bg     = (const float*)d_in[13];
    const float* Wp     = (const float*)d_in[14];
    const float* bp     = (const float*)d_in[15];
    const float* W_out  = (const float*)d_in[16];
    const float* b_out  = (const float*)d_in[17];
    float* out = (float*)d_out;
    float* hid_out = out + 262144;  // new_hidden [2,4,64,64] after out [2,2,256,256]

    cudaFuncSetAttribute(pass2_kernel,
                         cudaFuncAttributeMaxDynamicSharedMemorySize, SMEM_P2);

    conv_in_kernel<<<dim3(256, 2), 256>>>(x, W_in, b_in);
    for (int l = 0; l < Lnum; l++) {
        zero_kernel<<<32, 256>>>();
        stats_kernel<<<dim3(64, 16), 256>>>();
        fold_kernel<<<2, 64>>>(gamma + l * 64, beta + l * 64);
        pass2_kernel<<<dim3(74, 2), 256, SMEM_P2>>>(
            Wk + l * 4096, bk + l * 64, Wv + l * 4096, bv + l * 64,
            Wg + l * 8192, bg + l * 128);
        memfold_kernel<<<2, 256>>>(hidden + l * 4096, Wq + l * 4096, bq + l * 64,
                                   Wp + l * 4096, bp + l * 64, hid_out + l * 4096);
        pass3_kernel<<<dim3(1024, 2), 256>>>();
    }
    conv_out_kernel<<<dim3(256, 2), 256>>>(x, W_out, b_out, out);
}

// round 3
// speedup vs baseline: 1.6128x; 1.6128x over previous
#include <cuda_runtime.h>
#include <cstddef>

constexpr int Cc   = 64;
constexpr int Np   = 65536;
constexpr int Lnum = 4;
constexpr int Bn   = 2;
constexpr int WTP  = 260;   // WT smem pitch (floats)
constexpr int XP   = 68;    // Xs pitch
constexpr int YP   = 66;    // Ykv pitch (even for 8B loads)
constexpr int SMEM_P2 = (64*WTP + 256 + 64 + 64 + 64*XP + 128*YP) * 4;

__device__ float g_feat[(size_t)Bn * Cc * Np];
__device__ float g_stats[Bn * 8 * 2];     // per (b,g): sum, sumsq
__device__ float g_afold[Bn * Cc];
__device__ float g_bfold[Bn * Cc];
__device__ float g_know[Bn * Cc * Cc];
__device__ float g_fsum[Bn * Cc];
__device__ float g_M2[Bn * Cc * Cc];
__device__ float g_d2[Bn * Cc];

typedef unsigned long long u64;
__device__ __forceinline__ u64 ffma2(u64 a, u64 b, u64 c) {
    u64 d; asm("fma.rn.f32x2 %0,%1,%2,%3;" : "=l"(d) : "l"(a), "l"(b), "l"(c));
    return d;
}
__device__ __forceinline__ u64 pack2(float x, float y) {
    u64 d; asm("mov.b64 %0,{%1,%2};" : "=l"(d) : "f"(x), "f"(y));
    return d;
}
__device__ __forceinline__ float2 unpack2(u64 v) {
    float2 r; asm("mov.b64 {%0,%1},%2;" : "=f"(r.x), "=f"(r.y) : "l"(v));
    return r;
}
__device__ __forceinline__ float wred(float v) {
#pragma unroll
    for (int o = 16; o > 0; o >>= 1) v += __shfl_xor_sync(0xffffffffu, v, o);
    return v;
}

// -------- init zeros: stats only (once)
__global__ void zero_init_kernel() {
    int i = threadIdx.x;
    if (i < Bn * 16) g_stats[i] = 0.f;
}
// -------- per-layer zeros: knowledge + fsum
__global__ void zero_kf_kernel() {
    int i = blockIdx.x * 256 + threadIdx.x;
    if (i < Bn * Cc * Cc) g_know[i] = 0.f;
    if (i < Bn * Cc)      g_fsum[i] = 0.f;
}

// -------- conv3x3 in + layer-0 GN stats
__global__ void __launch_bounds__(256) conv_in_kernel(
    const float* __restrict__ x, const float* __restrict__ W,
    const float* __restrict__ bias)
{
    __shared__ float xs[2 * 3 * 258];
    __shared__ float ws[64 * 18];
    __shared__ float bsh[64];
    int b = blockIdx.y, y = blockIdx.x, tid = threadIdx.x;
    for (int i = tid; i < 64 * 18; i += 256) ws[i] = W[i];
    if (tid < 64) bsh[tid] = bias[tid];
    for (int i = tid; i < 2 * 3 * 258; i += 256) {
        int c = i / 774, rem = i % 774, r = rem / 258, col = rem % 258;
        int yy = y + r - 1, xx = col - 1;
        float v = 0.f;
        if (yy >= 0 && yy < 256 && xx >= 0 && xx < 256)
            v = x[((size_t)(b * 2 + c) * 256 + yy) * 256 + xx];
        xs[i] = v;
    }
    __syncthreads();
    float in[18];
#pragma unroll
    for (int c = 0; c < 2; c++)
#pragma unroll
        for (int r = 0; r < 3; r++)
#pragma unroll
            for (int k = 0; k < 3; k++)
                in[c * 9 + r * 3 + k] = xs[c * 774 + r * 258 + tid + k];
    size_t ob = (size_t)b * Cc * Np + y * 256 + tid;
    float sg[8], qg[8];
#pragma unroll
    for (int g = 0; g < 8; g++) { sg[g] = 0.f; qg[g] = 0.f; }
#pragma unroll
    for (int g = 0; g < 8; g++) {
#pragma unroll
        for (int j = 0; j < 8; j++) {
            int oc = g * 8 + j;
            float acc = bsh[oc];
#pragma unroll
            for (int t = 0; t < 18; t++) acc += ws[oc * 18 + t] * in[t];
            g_feat[ob + (size_t)oc * Np] = acc;
            sg[g] += acc; qg[g] += acc * acc;
        }
    }
#pragma unroll
    for (int g = 0; g < 8; g++) {
        float s = wred(sg[g]), q = wred(qg[g]);
        if ((tid & 31) == 0) {
            atomicAdd(&g_stats[(b * 8 + g) * 2 + 0], s);
            atomicAdd(&g_stats[(b * 8 + g) * 2 + 1], q);
        }
    }
}

// -------- fold GN into per-(b,c) affine
__global__ void fold_kernel(const float* __restrict__ gamma,
                            const float* __restrict__ beta)
{
    int b = blockIdx.x, c = threadIdx.x, g = c >> 3;
    float inv = 1.f / (8.f * 65536.f);
    float mu  = g_stats[(b * 8 + g) * 2 + 0] * inv;
    float var = g_stats[(b * 8 + g) * 2 + 1] * inv - mu * mu;
    float a = gamma[c] * rsqrtf(var + 1e-5f);
    g_afold[b * 64 + c] = a;
    g_bfold[b * 64 + c] = beta[c] - mu * a;
}

// -------- pass 2: fused [k,v,f,i] GEMM (FFMA2, channel-pair packed),
//          gates, knowledge outer product (FFMA2, pixel-pair packed)
__global__ void __launch_bounds__(512, 1) pass2_kernel(
    const float* __restrict__ Wk, const float* __restrict__ bk,
    const float* __restrict__ Wv, const float* __restrict__ bv,
    const float* __restrict__ Wg, const float* __restrict__ bg)
{
    extern __shared__ float sm[];
    float* WT   = sm;                  // [64][WTP] rows: 0-63 k, 64-127 v, 128-191 f, 192-255 i
    float* bias = WT + 64 * WTP;       // 256
    float* av   = bias + 256;          // 64
    float* bs   = av + 64;             // 64
    float* Xs   = bs + 64;             // [64][XP]
    float* Ykv  = Xs + 64 * XP;        // [128][YP] rows 0-63 kgated, 64-127 v

    int b = blockIdx.y, tid = threadIdx.x;
    for (int i = tid; i < 4096; i += 512) {
        int oc = i >> 6, c = i & 63;
        WT[c * WTP + oc]      = Wk[i];
        WT[c * WTP + 64 + oc] = Wv[i];
    }
    for (int i = tid; i < 8192; i += 512) {
        int oc = i >> 6, c = i & 63;
        WT[c * WTP + 128 + oc] = Wg[i];
    }
    if (tid < 64) {
        bias[tid]       = bk[tid];
        bias[64 + tid]  = bv[tid];
        bias[128 + tid] = bg[tid];        // f-gate
        bias[192 + tid] = bg[64 + tid];   // i-gate
        av[tid] = g_afold[b * 64 + tid];
        bs[tid] = g_bfold[b * 64 + tid];
    }

    int wy = tid >> 4, tx = tid & 15, pb = tx * 4;
    int ocb = wy * 8;
    u64 kacc2[2][4];
#pragma unroll
    for (int i = 0; i < 2; i++)
#pragma unroll
        for (int j = 0; j < 4; j++) kacc2[i][j] = 0ull;
    float fpart[8];
#pragma unroll
    for (int j = 0; j < 8; j++) fpart[j] = 0.f;

    const float* fb = g_feat + (size_t)b * Cc * Np;

    for (int tile = blockIdx.x; tile < 1024; tile += gridDim.x) {
        int n0 = tile * 64;
        __syncthreads();   // prev phase C done with Ykv / Xs free
        for (int i = tid; i < 4096; i += 512) {
            int c = i >> 6, p = i & 63;
            Xs[c * XP + p] = fb[(size_t)c * Np + n0 + p] * av[c] + bs[c];
        }
        __syncthreads();
        // ---- GEMM: rows ocb..ocb+7, pixels pb..pb+3
        u64 acc[4][4];
#pragma unroll
        for (int m = 0; m < 4; m++) {
            u64 bp2 = pack2(bias[ocb + 2 * m], bias[ocb + 2 * m + 1]);
#pragma unroll
            for (int q = 0; q < 4; q++) acc[m][q] = bp2;
        }
#pragma unroll 4
        for (int c = 0; c < 64; c++) {
            float4 x4 = *(const float4*)&Xs[c * XP + pb];
            u64 xp[4] = {pack2(x4.x, x4.x), pack2(x4.y, x4.y),
                         pack2(x4.z, x4.z), pack2(x4.w, x4.w)};
            ulonglong2 wA = *(const ulonglong2*)&WT[c * WTP + ocb];
            ulonglong2 wB = *(const ulonglong2*)&WT[c * WTP + ocb + 4];
            u64 wp[4] = {wA.x, wA.y, wB.x, wB.y};
#pragma unroll
            for (int m = 0; m < 4; m++)
#pragma unroll
                for (int q = 0; q < 4; q++)
                    acc[m][q] = ffma2(wp[m], xp[q], acc[m][q]);
        }
        // ---- distribute: v store, i-gate sigmoid store, f-gate accumulate
        if (wy >= 8 && wy < 16) {           // v rows 64..127
#pragma unroll
            for (int m = 0; m < 4; m++)
#pragma unroll
                for (int q = 0; q < 4; q++) {
                    float2 r = unpack2(acc[m][q]);
                    Ykv[(ocb + 2 * m)     * YP + pb + q] = r.x;
                    Ykv[(ocb + 2 * m + 1) * YP + pb + q] = r.y;
                }
        } else if (wy >= 24) {              // i rows -> sigmoid into k region
            int rb = ocb - 192;
#pragma unroll
            for (int m = 0; m < 4; m++)
#pragma unroll
                for (int q = 0; q < 4; q++) {
                    float2 r = unpack2(acc[m][q]);
                    Ykv[(rb + 2 * m)     * YP + pb + q] = 1.f / (1.f + __expf(-r.x));
                    Ykv[(rb + 2 * m + 1) * YP + pb + q] = 1.f / (1.f + __expf(-r.y));
                }
        } else if (wy >= 16) {              // f rows -> partial means
#pragma unroll
            for (int m = 0; m < 4; m++)
#pragma unroll
                for (int q = 0; q < 4; q++) {
                    float2 r = unpack2(acc[m][q]);
                    fpart[2 * m]     += 1.f / (1.f + __expf(-r.x));
                    fpart[2 * m + 1] += 1.f / (1.f + __expf(-r.y));
                }
        }
        __syncthreads();
        if (wy < 8) {                       // k rows: gate and store
#pragma unroll
            for (int m = 0; m < 4; m++)
#pragma unroll
                for (int q = 0; q < 4; q++) {
                    float2 r = unpack2(acc[m][q]);
                    int r0 = ocb + 2 * m, r1 = r0 + 1;
                    Ykv[r0 * YP + pb + q] = r.x * Ykv[r0 * YP + pb + q];
                    Ykv[r1 * YP + pb + q] = r.y * Ykv[r1 * YP + pb + q];
                }
        }
        __syncthreads();
        // ---- phase C: knowledge[c][d] += kg[c][p]*v[d][p], p-pair packed
        {
            int cb = wy * 2;
#pragma unroll 2
            for (int pp = 0; pp < 32; pp++) {
                u64 k0 = *(const u64*)&Ykv[(cb + 0) * YP + 2 * pp];
                u64 k1 = *(const u64*)&Ykv[(cb + 1) * YP + 2 * pp];
                u64 v0 = *(const u64*)&Ykv[(64 + tx)      * YP + 2 * pp];
                u64 v1 = *(const u64*)&Ykv[(64 + tx + 16) * YP + 2 * pp];
                u64 v2 = *(const u64*)&Ykv[(64 + tx + 32) * YP + 2 * pp];
                u64 v3 = *(const u64*)&Ykv[(64 + tx + 48) * YP + 2 * pp];
                kacc2[0][0] = ffma2(k0, v0, kacc2[0][0]);
                kacc2[0][1] = ffma2(k0, v1, kacc2[0][1]);
                kacc2[0][2] = ffma2(k0, v2, kacc2[0][2]);
                kacc2[0][3] = ffma2(k0, v3, kacc2[0][3]);
                kacc2[1][0] = ffma2(k1, v0, kacc2[1][0]);
                kacc2[1][1] = ffma2(k1, v1, kacc2[1][1]);
                kacc2[1][2] = ffma2(k1, v2, kacc2[1][2]);
                kacc2[1][3] = ffma2(k1, v3, kacc2[1][3]);
            }
        }
    }
    // writeback
    float* kb = g_know + b * 4096;
    int cb = wy * 2;
#pragma unroll
    for (int i = 0; i < 2; i++)
#pragma unroll
        for (int j = 0; j < 4; j++) {
            float2 r = unpack2(kacc2[i][j]);
            atomicAdd(&kb[(cb + i) * 64 + tx + 16 * j], r.x + r.y);
        }
    if (wy >= 16 && wy < 24) {
#pragma unroll
        for (int j = 0; j < 8; j++)
            atomicAdd(&g_fsum[b * 64 + (wy - 16) * 8 + j], fpart[j]);
    }
}

// -------- new_mem + fold pass-3 into M2/d2; also zero stats for next layer
__global__ void __launch_bounds__(256) memfold_kernel(
    const float* __restrict__ hidden, const float* __restrict__ Wq,
    const float* __restrict__ bq, const float* __restrict__ Wp,
    const float* __restrict__ bp, float* __restrict__ hid_out)
{
    int b = blockIdx.x, tid = threadIdx.x;
    __shared__ float memS[4096], T[4096], rS[64], uS[64], fm[64];
    if (tid < 16) g_stats[b * 16 + tid] = 0.f;   // next-layer stats
    if (tid < 64) fm[tid] = g_fsum[b * 64 + tid] * (1.f / 65536.f);
    __syncthreads();
    const float* kb = g_know + b * 4096;
    const float* hb = hidden + (size_t)b * Lnum * 4096;
    float* ho = hid_out + (size_t)b * Lnum * 4096;
    for (int i = tid; i < 4096; i += 256) {
        int c = i >> 6;
        float m = fm[c] * hb[i] + kb[i] * (1.f / 65536.f);
        memS[i] = m; ho[i] = m;
    }
    if (tid < 64) {
        float u = bq[tid];
        for (int e = 0; e < 64; e++) u += Wq[tid * 64 + e] * g_bfold[b * 64 + e];
        uS[tid] = u;
    }
    __syncthreads();
    if (tid < 64) {
        float r = 0.f;
        for (int c = 0; c < 64; c++) r += memS[c * 64 + tid] * uS[c];
        rS[tid] = r;
    }
    for (int i = tid; i < 4096; i += 256) {   // T[d][e] = sum_c M[c][d]Wq[c][e]*a[e]
        int d = i >> 6, e = i & 63;
        float t = 0.f;
        for (int c = 0; c < 64; c++) t += memS[c * 64 + d] * Wq[c * 64 + e];
        T[i] = t * g_afold[b * 64 + e];
    }
    __syncthreads();
    for (int i = tid; i < 4096; i += 256)     // memS <- Wp^T (WpT[d][o])
        memS[i] = Wp[(i & 63) * 64 + (i >> 6)];
    __syncthreads();
    const float scale = 0.125f;
    for (int i = tid; i < 4096; i += 256) {   // g_M2[e*64+o]
        int e = i >> 6, o = i & 63;
        float m = 0.f;
        for (int d = 0; d < 64; d++) m += memS[d * 64 + o] * T[d * 64 + e];
        g_M2[b * 4096 + i] = m * scale;
    }
    if (tid < 64) {
        float s = 0.f;
        for (int d = 0; d < 64; d++) s += memS[d * 64 + tid] * rS[d];
        g_d2[b * 64 + tid] = s * scale + bp[tid];
    }
}

// -------- pass 3: feat <- feat + M2*feat + d2 (FFMA2) + next-layer GN stats
__global__ void __launch_bounds__(256) pass3_kernel() {
    __shared__ __align__(16) float M2s[4096];
    __shared__ __align__(16) float Xs[64 * XP];
    __shared__ float d2s[64];
    int b = blockIdx.y, n0 = blockIdx.x * 64, tid = threadIdx.x;
    for (int i = tid; i < 4096; i += 256) M2s[i] = g_M2[b * 4096 + i];
    if (tid < 64) d2s[tid] = g_d2[b * 64 + tid];
    float* fb = g_feat + (size_t)b * Cc * Np;
    for (int i = tid; i < 4096; i += 256) {
        int c = i >> 6, p = i & 63;
        Xs[c * XP + p] = fb[(size_t)c * Np + n0 + p];
    }
    __syncthreads();
    int ty = tid >> 4, tx = tid & 15, ob = ty * 4, pb = tx * 4;
    u64 acc[2][4];
#pragma unroll
    for (int m = 0; m < 2; m++) {
        u64 d = pack2(d2s[ob + 2 * m], d2s[ob + 2 * m + 1]);
#pragma unroll
        for (int q = 0; q < 4; q++) acc[m][q] = d;
    }
#pragma unroll 4
    for (int e = 0; e < 64; e++) {
        float4 x4 = *(const float4*)&Xs[e * XP + pb];
        u64 xp[4] = {pack2(x4.x, x4.x), pack2(x4.y, x4.y),
                     pack2(x4.z, x4.z), pack2(x4.w, x4.w)};
        ulonglong2 m2 = *(const ulonglong2*)&M2s[e * 64 + ob];
#pragma unroll
        for (int q = 0; q < 4; q++) {
            acc[0][q] = ffma2(m2.x, xp[q], acc[0][q]);
            acc[1][q] = ffma2(m2.y, xp[q], acc[1][q]);
        }
    }
    float s = 0.f, q2 = 0.f;
#pragma unroll
    for (int m = 0; m < 2; m++)
#pragma unroll
        for (int q = 0; q < 4; q++) {
            float2 r = unpack2(acc[m][q]);
            int r0 = ob + 2 * m, r1 = r0 + 1;
            float o0 = r.x + Xs[r0 * XP + pb + q];
            float o1 = r.y + Xs[r1 * XP + pb + q];
            fb[(size_t)r0 * Np + n0 + pb + q] = o0;
            fb[(size_t)r1 * Np + n0 + pb + q] = o1;
            s += o0 + o1; q2 += o0 * o0 + o1 * o1;
        }
    // warp w covers ty {2w,2w+1} -> channels 8w..8w+7 -> group w
    s = wred(s); q2 = wred(q2);
    if ((tid & 31) == 0) {
        int g = tid >> 5;
        atomicAdd(&g_stats[(b * 8 + g) * 2 + 0], s);
        atomicAdd(&g_stats[(b * 8 + g) * 2 + 1], q2);
    }
}

// -------- conv3x3 out + residual
__global__ void __launch_bounds__(256) conv_out_kernel(
    const float* __restrict__ x, const float* __restrict__ W,
    const float* __restrict__ bias, float* __restrict__ out)
{
    __shared__ float fs[8 * 3 * 258];
    __shared__ float ws[1152];
    int b = blockIdx.y, y = blockIdx.x, tid = threadIdx.x;
    for (int i = tid; i < 1152; i += 256) ws[i] = W[i];
    float acc0 = bias[0], acc1 = bias[1];
    const float* fb = g_feat + (size_t)b * Cc * Np;
    for (int cc = 0; cc < 64; cc += 8) {
        __syncthreads();
        for (int i = tid; i < 6192; i += 256) {
            int c = i / 774, rem = i % 774, r = rem / 258, col = rem % 258;
            int yy = y + r - 1, xx = col - 1;
            float v = 0.f;
            if (yy >= 0 && yy < 256 && xx >= 0 && xx < 256)
                v = fb[(size_t)(cc + c) * Np + yy * 256 + xx];
            fs[i] = v;
        }
        __syncthreads();
#pragma unroll
        for (int c = 0; c < 8; c++) {
            float in[9];
#pragma unroll
            for (int r = 0; r < 3; r++)
#pragma unroll
                for (int k = 0; k < 3; k++)
                    in[r * 3 + k] = fs[c * 774 + r * 258 + tid + k];
            const float* w0 = &ws[(cc + c) * 9];
            const float* w1 = &ws[(64 + cc + c) * 9];
#pragma unroll
            for (int t = 0; t < 9; t++) { acc0 += w0[t] * in[t]; acc1 += w1[t] * in[t]; }
        }
    }
    int o = y * 256 + tid;
    out[(size_t)(b * 2 + 0) * Np + o] = acc0 + x[(size_t)(b * 2 + 0) * Np + o];
    out[(size_t)(b * 2 + 1) * Np + o] = acc1 + x[(size_t)(b * 2 + 1) * Np + o];
}

extern "C" void kernel_launch(void* const* d_in, const int* in_sizes, int n_in,
                              void* d_out, int out_size)
{
    const float* x      = (const float*)d_in[0];
    const float* hidden = (const float*)d_in[1];
    const float* W_in   = (const float*)d_in[2];
    const float* b_in   = (const float*)d_in[3];
    const float* gamma  = (const float*)d_in[4];
    const float* beta   = (const float*)d_in[5];
    const float* Wq     = (const float*)d_in[6];
    const float* bq     = (const float*)d_in[7];
    const float* Wk     = (const float*)d_in[8];
    const float* bk     = (const float*)d_in[9];
    const float* Wv     = (const float*)d_in[10];
    const float* bv     = (const float*)d_in[11];
    const float* Wg     = (const float*)d_in[12];
    const float* bg     = (const float*)d_in[13];
    const float* Wp     = (const float*)d_in[14];
    const float* bp     = (const float*)d_in[15];
    const float* W_out  = (const float*)d_in[16];
    const float* b_out  = (const float*)d_in[17];
    float* out = (float*)d_out;
    float* hid_out = out + 262144;  // new_hidden [2,4,64,64]

    cudaFuncSetAttribute(pass2_kernel,
                         cudaFuncAttributeMaxDynamicSharedMemorySize, SMEM_P2);

    zero_init_kernel<<<1, 64>>>();
    conv_in_kernel<<<dim3(256, 2), 256>>>(x, W_in, b_in);
    for (int l = 0; l < Lnum; l++) {
        fold_kernel<<<2, 64>>>(gamma + l * 64, beta + l * 64);
        zero_kf_kernel<<<32, 256>>>();
        pass2_kernel<<<dim3(74, 2), 512, SMEM_P2>>>(
            Wk + l * 4096, bk + l * 64, Wv + l * 4096, bv + l * 64,
            Wg + l * 8192, bg + l * 128);
        memfold_kernel<<<2, 256>>>(hidden + l * 4096, Wq + l * 4096, bq + l * 64,
                                   Wp + l * 4096, bp + l * 64, hid_out + l * 4096);
        pass3_kernel<<<dim3(1024, 2), 256>>>();
    }
    conv_out_kernel<<<dim3(256, 2), 256>>>(x, W_out, b_out, out);
}

// round 5
// speedup vs baseline: 2.1715x; 1.3464x over previous
#include <cuda_runtime.h>
#include <cuda_bf16.h>
#include <cstdint>
#include <cstddef>

constexpr int Cc   = 64;
constexpr int Np   = 65536;
constexpr int Lnum = 4;
constexpr int Bn   = 2;
constexpr int XP   = 68;    // pass3 Xs pitch (floats)
constexpr int FP   = 72;    // bf16 fragment pitch (elements) — conflict-free

__device__ float g_feat[(size_t)Bn * Cc * Np];
__device__ float g_stats[Bn * 8 * 2];
__device__ float g_afold[Bn * Cc];
__device__ float g_bfold[Bn * Cc];
__device__ float g_know[Bn * Cc * Cc];
__device__ float g_fsum[Bn * Cc];
__device__ float g_M2[Bn * Cc * Cc];
__device__ float g_d2[Bn * Cc];

typedef unsigned long long u64;
typedef uint32_t u32;
__device__ __forceinline__ u64 ffma2(u64 a, u64 b, u64 c) {
    u64 d; asm("fma.rn.f32x2 %0,%1,%2,%3;" : "=l"(d) : "l"(a), "l"(b), "l"(c));
    return d;
}
__device__ __forceinline__ u64 pack2(float x, float y) {
    u64 d; asm("mov.b64 %0,{%1,%2};" : "=l"(d) : "f"(x), "f"(y));
    return d;
}
__device__ __forceinline__ float2 unpack2(u64 v) {
    float2 r; asm("mov.b64 {%0,%1},%2;" : "=f"(r.x), "=f"(r.y) : "l"(v));
    return r;
}
__device__ __forceinline__ float wred(float v) {
#pragma unroll
    for (int o = 16; o > 0; o >>= 1) v += __shfl_xor_sync(0xffffffffu, v, o);
    return v;
}
__device__ __forceinline__ u32 pkbf(float hi, float lo) {
    u32 r; asm("cvt.rn.bf16x2.f32 %0, %1, %2;" : "=r"(r) : "f"(hi), "f"(lo));
    return r;
}
__device__ __forceinline__ float sigm(float x) { return 1.f / (1.f + __expf(-x)); }

// warp-level bf16 MMA (sm_80+ baseline instruction; works on compute_103)
__device__ __forceinline__ void mma16816(float c[4], u32 a0, u32 a1, u32 a2,
                                         u32 a3, u32 b0, u32 b1) {
    asm volatile(
        "mma.sync.aligned.m16n8k16.row.col.f32.bf16.bf16.f32 "
        "{%0,%1,%2,%3}, {%4,%5,%6,%7}, {%8,%9}, {%0,%1,%2,%3};"
        : "+f"(c[0]), "+f"(c[1]), "+f"(c[2]), "+f"(c[3])
        : "r"(a0), "r"(a1), "r"(a2), "r"(a3), "r"(b0), "r"(b1));
}

// ===================== small kernels =====================
__global__ void zero_init_kernel() {
    int i = threadIdx.x;
    if (i < Bn * 16) g_stats[i] = 0.f;
}
__global__ void zero_kf_kernel() {
    int i = blockIdx.x * 256 + threadIdx.x;
    if (i < Bn * Cc * Cc) g_know[i] = 0.f;
    if (i < Bn * Cc)      g_fsum[i] = 0.f;
}

// ===================== conv in + layer0 GN stats =====================
__global__ void __launch_bounds__(256) conv_in_kernel(
    const float* __restrict__ x, const float* __restrict__ W,
    const float* __restrict__ bias)
{
    __shared__ float xs[2 * 3 * 258];
    __shared__ float ws[64 * 18];
    __shared__ float bsh[64];
    int b = blockIdx.y, y = blockIdx.x, tid = threadIdx.x;
    for (int i = tid; i < 64 * 18; i += 256) ws[i] = W[i];
    if (tid < 64) bsh[tid] = bias[tid];
    for (int i = tid; i < 2 * 3 * 258; i += 256) {
        int c = i / 774, rem = i % 774, r = rem / 258, col = rem % 258;
        int yy = y + r - 1, xx = col - 1;
        float v = 0.f;
        if (yy >= 0 && yy < 256 && xx >= 0 && xx < 256)
            v = x[((size_t)(b * 2 + c) * 256 + yy) * 256 + xx];
        xs[i] = v;
    }
    __syncthreads();
    float in[18];
#pragma unroll
    for (int c = 0; c < 2; c++)
#pragma unroll
        for (int r = 0; r < 3; r++)
#pragma unroll
            for (int k = 0; k < 3; k++)
                in[c * 9 + r * 3 + k] = xs[c * 774 + r * 258 + tid + k];
    size_t ob = (size_t)b * Cc * Np + y * 256 + tid;
#pragma unroll
    for (int g = 0; g < 8; g++) {
        float sg = 0.f, qg = 0.f;
#pragma unroll
        for (int j = 0; j < 8; j++) {
            int oc = g * 8 + j;
            float acc = bsh[oc];
#pragma unroll
            for (int t = 0; t < 18; t++) acc += ws[oc * 18 + t] * in[t];
            g_feat[ob + (size_t)oc * Np] = acc;
            sg += acc; qg += acc * acc;
        }
        float s = wred(sg), q = wred(qg);
        if ((tid & 31) == 0) {
            atomicAdd(&g_stats[(b * 8 + g) * 2 + 0], s);
            atomicAdd(&g_stats[(b * 8 + g) * 2 + 1], q);
        }
    }
}

__global__ void fold_kernel(const float* __restrict__ gamma,
                            const float* __restrict__ beta)
{
    int b = blockIdx.x, c = threadIdx.x, g = c >> 3;
    float inv = 1.f / (8.f * 65536.f);
    float mu  = g_stats[(b * 8 + g) * 2 + 0] * inv;
    float var = g_stats[(b * 8 + g) * 2 + 1] * inv - mu * mu;
    float a = gamma[c] * rsqrtf(var + 1e-5f);
    g_afold[b * 64 + c] = a;
    g_bfold[b * 64 + c] = beta[c] - mu * a;
}

// ===================== pass 2: warp-MMA (HMMA bf16) =====================
// smem map (bytes)
constexpr int SM_WHI = 0;                        // [256][FP] bf16 = 36864
constexpr int SM_WLO = 36864;                    // 36864
constexpr int SM_XS  = 73728;                    // [128 px][FP] bf16 = 18432
constexpr int SM_VT  = 92160;                    // [64 vch][FP] bf16 (per half)
constexpr int SM_GI  = 101376;                   // [64 ich][FP]
constexpr int SM_KG  = 110592;                   // [64 kch][FP]
constexpr int SM_BIA = 119808;                   // 256 f32
constexpr int SM_AFF = 120832;                   // av 64 + bs 64 f32
constexpr int SMEM_P2 = 121344;

__global__ void __launch_bounds__(256, 1) pass2_mma_kernel(
    const float* __restrict__ Wk, const float* __restrict__ bk,
    const float* __restrict__ Wv, const float* __restrict__ bv,
    const float* __restrict__ Wg, const float* __restrict__ bg)
{
    extern __shared__ char smc[];
    __nv_bfloat16* WHi = (__nv_bfloat16*)(smc + SM_WHI);
    __nv_bfloat16* WLo = (__nv_bfloat16*)(smc + SM_WLO);
    __nv_bfloat16* Xs  = (__nv_bfloat16*)(smc + SM_XS);
    __nv_bfloat16* Vt  = (__nv_bfloat16*)(smc + SM_VT);
    __nv_bfloat16* Gi  = (__nv_bfloat16*)(smc + SM_GI);
    __nv_bfloat16* Kg  = (__nv_bfloat16*)(smc + SM_KG);
    float* biasS = (float*)(smc + SM_BIA);
    float* avS   = (float*)(smc + SM_AFF);
    float* bsS   = avS + 64;

    int b = blockIdx.y, tid = threadIdx.x;
    int wid = tid >> 5, lane = tid & 31, g = lane >> 2, tg = lane & 3;

    // stage weights hi/lo: rows 0-63 k, 64-127 v, 128-191 f, 192-255 i
    for (int i = tid; i < 4096; i += 256) {
        int oc = i >> 6, c = i & 63;
        float w = Wk[i];
        __nv_bfloat16 h = __float2bfloat16(w);
        WHi[oc * FP + c] = h;
        WLo[oc * FP + c] = __float2bfloat16(w - __bfloat162float(h));
        w = Wv[i];
        h = __float2bfloat16(w);
        WHi[(64 + oc) * FP + c] = h;
        WLo[(64 + oc) * FP + c] = __float2bfloat16(w - __bfloat162float(h));
    }
    for (int i = tid; i < 8192; i += 256) {
        int oc = i >> 6, c = i & 63;
        float w = Wg[i];
        __nv_bfloat16 h = __float2bfloat16(w);
        WHi[(128 + oc) * FP + c] = h;
        WLo[(128 + oc) * FP + c] = __float2bfloat16(w - __bfloat162float(h));
    }
    if (tid < 64) {
        biasS[tid]       = bk[tid];
        biasS[64 + tid]  = bv[tid];
        biasS[128 + tid] = bg[tid];
        biasS[192 + tid] = bg[64 + tid];
        avS[tid] = g_afold[b * 64 + tid];
        bsS[tid] = g_bfold[b * 64 + tid];
    }

    float Ck[4][4];                 // persistent knowledge fragments
#pragma unroll
    for (int i = 0; i < 4; i++)
#pragma unroll
        for (int j = 0; j < 4; j++) Ck[i][j] = 0.f;
    float fpart[4] = {0.f, 0.f, 0.f, 0.f};

    const float* fb = g_feat + (size_t)b * Cc * Np;
    int mtk = wid >> 1, ntb = (wid & 1) * 4;   // knowledge tile assignment

    __syncthreads();

    for (int t = blockIdx.x; t < 512; t += 74) {
        int n0 = t << 7;
        // stage X^T: Xs[px][c] = feat*a + b (bf16), c-pairs packed
        for (int i = tid; i < 4096; i += 256) {
            int cp = i >> 7, px = i & 127;
            int c = cp * 2;
            float x0 = fb[(size_t)c * Np + n0 + px] * avS[c] + bsS[c];
            float x1 = fb[(size_t)(c + 1) * Np + n0 + px] * avS[c + 1] + bsS[c + 1];
            *(u32*)&Xs[px * FP + c] = pkbf(x1, x0);
        }
        __syncthreads();

#pragma unroll 1
        for (int h = 0; h < 2; h++) {
            const __nv_bfloat16* Xh = Xs + h * 64 * FP;
            // ---- GEMM1: this warp computes rows wid*32..+31 x 64 px
            float C[2][8][4];
#pragma unroll
            for (int mt = 0; mt < 2; mt++)
#pragma unroll
                for (int nt = 0; nt < 8; nt++)
#pragma unroll
                    for (int q = 0; q < 4; q++) C[mt][nt][q] = 0.f;
            int rbase = wid * 32;
#pragma unroll
            for (int ks = 0; ks < 4; ks++) {
                int kb2 = ks * 16 + 2 * tg;
                u32 bfr[8][2];
#pragma unroll
                for (int nt = 0; nt < 8; nt++) {
                    bfr[nt][0] = *(const u32*)&Xh[(nt * 8 + g) * FP + kb2];
                    bfr[nt][1] = *(const u32*)&Xh[(nt * 8 + g) * FP + kb2 + 8];
                }
                u32 afr[2][2][4];
#pragma unroll
                for (int mt = 0; mt < 2; mt++) {
                    int r = rbase + mt * 16;
                    afr[mt][0][0] = *(const u32*)&WHi[(r + g) * FP + kb2];
                    afr[mt][0][1] = *(const u32*)&WHi[(r + g + 8) * FP + kb2];
                    afr[mt][0][2] = *(const u32*)&WHi[(r + g) * FP + kb2 + 8];
                    afr[mt][0][3] = *(const u32*)&WHi[(r + g + 8) * FP + kb2 + 8];
                    afr[mt][1][0] = *(const u32*)&WLo[(r + g) * FP + kb2];
                    afr[mt][1][1] = *(const u32*)&WLo[(r + g + 8) * FP + kb2];
                    afr[mt][1][2] = *(const u32*)&WLo[(r + g) * FP + kb2 + 8];
                    afr[mt][1][3] = *(const u32*)&WLo[(r + g + 8) * FP + kb2 + 8];
                }
#pragma unroll
                for (int mt = 0; mt < 2; mt++)
#pragma unroll
                    for (int nt = 0; nt < 8; nt++) {
                        mma16816(C[mt][nt], afr[mt][0][0], afr[mt][0][1],
                                 afr[mt][0][2], afr[mt][0][3], bfr[nt][0], bfr[nt][1]);
                        mma16816(C[mt][nt], afr[mt][1][0], afr[mt][1][1],
                                 afr[mt][1][2], afr[mt][1][3], bfr[nt][0], bfr[nt][1]);
                    }
            }
            // ---- epilogue by role
            if (wid == 2 || wid == 3) {                  // v rows 64..127
                int base = (wid - 2) * 32;
#pragma unroll
                for (int mt = 0; mt < 2; mt++) {
                    int r0 = base + mt * 16 + g, r1 = r0 + 8;
                    float b0 = biasS[64 + r0], b1 = biasS[64 + r1];
#pragma unroll
                    for (int nt = 0; nt < 8; nt++) {
                        int col = nt * 8 + tg * 2;
                        *(u32*)&Vt[r0 * FP + col] =
                            pkbf(C[mt][nt][1] + b0, C[mt][nt][0] + b0);
                        *(u32*)&Vt[r1 * FP + col] =
                            pkbf(C[mt][nt][3] + b1, C[mt][nt][2] + b1);
                    }
                }
            } else if (wid == 6 || wid == 7) {           // i rows 192..255
                int base = (wid - 6) * 32;
#pragma unroll
                for (int mt = 0; mt < 2; mt++) {
                    int r0 = base + mt * 16 + g, r1 = r0 + 8;
                    float b0 = biasS[192 + r0], b1 = biasS[192 + r1];
#pragma unroll
                    for (int nt = 0; nt < 8; nt++) {
                        int col = nt * 8 + tg * 2;
                        *(u32*)&Gi[r0 * FP + col] =
                            pkbf(sigm(C[mt][nt][1] + b0), sigm(C[mt][nt][0] + b0));
                        *(u32*)&Gi[r1 * FP + col] =
                            pkbf(sigm(C[mt][nt][3] + b1), sigm(C[mt][nt][2] + b1));
                    }
                }
            } else if (wid == 4 || wid == 5) {           // f rows 128..191
                int base = (wid - 4) * 32;
#pragma unroll
                for (int mt = 0; mt < 2; mt++) {
                    int r0 = base + mt * 16 + g, r1 = r0 + 8;
                    float b0 = biasS[128 + r0], b1 = biasS[128 + r1];
#pragma unroll
                    for (int nt = 0; nt < 8; nt++) {
                        fpart[mt * 2]     += sigm(C[mt][nt][0] + b0) + sigm(C[mt][nt][1] + b0);
                        fpart[mt * 2 + 1] += sigm(C[mt][nt][2] + b1) + sigm(C[mt][nt][3] + b1);
                    }
                }
            }
            __syncthreads();
            if (wid < 2) {                               // k rows 0..63: gate
                int base = wid * 32;
#pragma unroll
                for (int mt = 0; mt < 2; mt++) {
                    int r0 = base + mt * 16 + g, r1 = r0 + 8;
                    float b0 = biasS[r0], b1 = biasS[r1];
#pragma unroll
                    for (int nt = 0; nt < 8; nt++) {
                        int col = nt * 8 + tg * 2;
                        u32 gi0 = *(const u32*)&Gi[r0 * FP + col];
                        u32 gi1 = *(const u32*)&Gi[r1 * FP + col];
                        float s0lo = __bfloat162float(((__nv_bfloat162*)&gi0)->x);
                        float s0hi = __bfloat162float(((__nv_bfloat162*)&gi0)->y);
                        float s1lo = __bfloat162float(((__nv_bfloat162*)&gi1)->x);
                        float s1hi = __bfloat162float(((__nv_bfloat162*)&gi1)->y);
                        *(u32*)&Kg[r0 * FP + col] =
                            pkbf((C[mt][nt][1] + b0) * s0hi, (C[mt][nt][0] + b0) * s0lo);
                        *(u32*)&Kg[r1 * FP + col] =
                            pkbf((C[mt][nt][3] + b1) * s1hi, (C[mt][nt][2] + b1) * s1lo);
                    }
                }
            }
            __syncthreads();
            // ---- knowledge MMA: know[c][d] += Kg[c][px] * Vt[d][px]
#pragma unroll
            for (int ks = 0; ks < 4; ks++) {
                int kb2 = ks * 16 + 2 * tg;
                u32 a0 = *(const u32*)&Kg[(mtk * 16 + g) * FP + kb2];
                u32 a1 = *(const u32*)&Kg[(mtk * 16 + g + 8) * FP + kb2];
                u32 a2 = *(const u32*)&Kg[(mtk * 16 + g) * FP + kb2 + 8];
                u32 a3 = *(const u32*)&Kg[(mtk * 16 + g + 8) * FP + kb2 + 8];
#pragma unroll
                for (int ntl = 0; ntl < 4; ntl++) {
                    u32 b0 = *(const u32*)&Vt[((ntb + ntl) * 8 + g) * FP + kb2];
                    u32 b1 = *(const u32*)&Vt[((ntb + ntl) * 8 + g) * FP + kb2 + 8];
                    mma16816(Ck[ntl], a0, a1, a2, a3, b0, b1);
                }
            }
            __syncthreads();
        }
    }
    // flush knowledge
    float* kbase = g_know + b * 4096;
#pragma unroll
    for (int ntl = 0; ntl < 4; ntl++) {
        int c0 = mtk * 16 + g, d0 = (ntb + ntl) * 8 + tg * 2;
        atomicAdd(&kbase[c0 * 64 + d0],           Ck[ntl][0]);
        atomicAdd(&kbase[c0 * 64 + d0 + 1],       Ck[ntl][1]);
        atomicAdd(&kbase[(c0 + 8) * 64 + d0],     Ck[ntl][2]);
        atomicAdd(&kbase[(c0 + 8) * 64 + d0 + 1], Ck[ntl][3]);
    }
    // flush f-sums (warps 4,5 own f channels)
    if (wid == 4 || wid == 5) {
#pragma unroll
        for (int s = 0; s < 4; s++) {
            float v = fpart[s];
            v += __shfl_xor_sync(0xffffffffu, v, 1);
            v += __shfl_xor_sync(0xffffffffu, v, 2);
            if (tg == 0) {
                int ch = (wid - 4) * 32 + (s >> 1) * 16 + g + (s & 1) * 8;
                atomicAdd(&g_fsum[b * 64 + ch], v);
            }
        }
    }
}

// ===================== memfold =====================
__global__ void __launch_bounds__(256) memfold_kernel(
    const float* __restrict__ hidden, const float* __restrict__ Wq,
    const float* __restrict__ bq, const float* __restrict__ Wp,
    const float* __restrict__ bp, float* __restrict__ hid_out)
{
    int b = blockIdx.x, tid = threadIdx.x;
    __shared__ float memS[4096], T[4096], rS[64], uS[64], fm[64];
    if (tid < 16) g_stats[b * 16 + tid] = 0.f;
    if (tid < 64) fm[tid] = g_fsum[b * 64 + tid] * (1.f / 65536.f);
    __syncthreads();
    const float* kb = g_know + b * 4096;
    const float* hb = hidden + (size_t)b * Lnum * 4096;
    float* ho = hid_out + (size_t)b * Lnum * 4096;
    for (int i = tid; i < 4096; i += 256) {
        int c = i >> 6;
        float m = fm[c] * hb[i] + kb[i] * (1.f / 65536.f);
        memS[i] = m; ho[i] = m;
    }
    if (tid < 64) {
        float u = bq[tid];
        for (int e = 0; e < 64; e++) u += Wq[tid * 64 + e] * g_bfold[b * 64 + e];
        uS[tid] = u;
    }
    __syncthreads();
    if (tid < 64) {
        float r = 0.f;
        for (int c = 0; c < 64; c++) r += memS[c * 64 + tid] * uS[c];
        rS[tid] = r;
    }
    for (int i = tid; i < 4096; i += 256) {
        int d = i >> 6, e = i & 63;
        float t = 0.f;
        for (int c = 0; c < 64; c++) t += memS[c * 64 + d] * Wq[c * 64 + e];
        T[i] = t * g_afold[b * 64 + e];
    }
    __syncthreads();
    for (int i = tid; i < 4096; i += 256)
        memS[i] = Wp[(i & 63) * 64 + (i >> 6)];
    __syncthreads();
    const float scale = 0.125f;
    for (int i = tid; i < 4096; i += 256) {
        int e = i >> 6, o = i & 63;
        float m = 0.f;
        for (int d = 0; d < 64; d++) m += memS[d * 64 + o] * T[d * 64 + e];
        g_M2[b * 4096 + i] = m * scale;
    }
    if (tid < 64) {
        float s = 0.f;
        for (int d = 0; d < 64; d++) s += memS[d * 64 + tid] * rS[d];
        g_d2[b * 64 + tid] = s * scale + bp[tid];
    }
}

// ===================== pass 3 (persistent, FFMA2) =====================
__global__ void __launch_bounds__(256) pass3_kernel() {
    __shared__ __align__(16) float M2s[4096];
    __shared__ __align__(16) float Xs[64 * XP];
    __shared__ float d2s[64];
    int b = blockIdx.y, tid = threadIdx.x;
    for (int i = tid; i < 4096; i += 256) M2s[i] = g_M2[b * 4096 + i];
    if (tid < 64) d2s[tid] = g_d2[b * 64 + tid];
    float* fb = g_feat + (size_t)b * Cc * Np;
    int ty = tid >> 4, tx = tid & 15, ob = ty * 4, pb = tx * 4;
    float ssum = 0.f, qsum = 0.f;
    for (int t = blockIdx.x; t < 1024; t += 74) {
        int n0 = t * 64;
        __syncthreads();
        for (int i = tid; i < 4096; i += 256) {
            int c = i >> 6, p = i & 63;
            Xs[c * XP + p] = fb[(size_t)c * Np + n0 + p];
        }
        __syncthreads();
        u64 acc[2][4];
#pragma unroll
        for (int m = 0; m < 2; m++) {
            u64 d = pack2(d2s[ob + 2 * m], d2s[ob + 2 * m + 1]);
#pragma unroll
            for (int q = 0; q < 4; q++) acc[m][q] = d;
        }
#pragma unroll 4
        for (int e = 0; e < 64; e++) {
            float4 x4 = *(const float4*)&Xs[e * XP + pb];
            u64 xp[4] = {pack2(x4.x, x4.x), pack2(x4.y, x4.y),
                         pack2(x4.z, x4.z), pack2(x4.w, x4.w)};
            ulonglong2 m2 = *(const ulonglong2*)&M2s[e * 64 + ob];
#pragma unroll
            for (int q = 0; q < 4; q++) {
                acc[0][q] = ffma2(m2.x, xp[q], acc[0][q]);
                acc[1][q] = ffma2(m2.y, xp[q], acc[1][q]);
            }
        }
#pragma unroll
        for (int m = 0; m < 2; m++)
#pragma unroll
            for (int q = 0; q < 4; q++) {
                float2 r = unpack2(acc[m][q]);
                int r0 = ob + 2 * m, r1 = r0 + 1;
                float o0 = r.x + Xs[r0 * XP + pb + q];
                float o1 = r.y + Xs[r1 * XP + pb + q];
                fb[(size_t)r0 * Np + n0 + pb + q] = o0;
                fb[(size_t)r1 * Np + n0 + pb + q] = o1;
                ssum += o0 + o1; qsum += o0 * o0 + o1 * o1;
            }
    }
    ssum = wred(ssum); qsum = wred(qsum);
    if ((tid & 31) == 0) {
        int g = tid >> 5;
        atomicAdd(&g_stats[(b * 8 + g) * 2 + 0], ssum);
        atomicAdd(&g_stats[(b * 8 + g) * 2 + 1], qsum);
    }
}

// ===================== conv out + residual =====================
__global__ void __launch_bounds__(256) conv_out_kernel(
    const float* __restrict__ x, const float* __restrict__ W,
    const float* __restrict__ bias, float* __restrict__ out)
{
    __shared__ float fs[8 * 3 * 258];
    __shared__ float ws[1152];
    int b = blockIdx.y, y = blockIdx.x, tid = threadIdx.x;
    for (int i = tid; i < 1152; i += 256) ws[i] = W[i];
    float acc0 = bias[0], acc1 = bias[1];
    const float* fb = g_feat + (size_t)b * Cc * Np;
    for (int cc = 0; cc < 64; cc += 8) {
        __syncthreads();
        for (int i = tid; i < 6192; i += 256) {
            int c = i / 774, rem = i % 774, r = rem / 258, col = rem % 258;
            int yy = y + r - 1, xx = col - 1;
            float v = 0.f;
            if (yy >= 0 && yy < 256 && xx >= 0 && xx < 256)
                v = fb[(size_t)(cc + c) * Np + yy * 256 + xx];
            fs[i] = v;
        }
        __syncthreads();
#pragma unroll
        for (int c = 0; c < 8; c++) {
            float in[9];
#pragma unroll
            for (int r = 0; r < 3; r++)
#pragma unroll
                for (int k = 0; k < 3; k++)
                    in[r * 3 + k] = fs[c * 774 + r * 258 + tid + k];
            const float* w0 = &ws[(cc + c) * 9];
            const float* w1 = &ws[(64 + cc + c) * 9];
#pragma unroll
            for (int t = 0; t < 9; t++) { acc0 += w0[t] * in[t]; acc1 += w1[t] * in[t]; }
        }
    }
    int o = y * 256 + tid;
    out[(size_t)(b * 2 + 0) * Np + o] = acc0 + x[(size_t)(b * 2 + 0) * Np + o];
    out[(size_t)(b * 2 + 1) * Np + o] = acc1 + x[(size_t)(b * 2 + 1) * Np + o];
}

extern "C" void kernel_launch(void* const* d_in, const int* in_sizes, int n_in,
                              void* d_out, int out_size)
{
    const float* x      = (const float*)d_in[0];
    const float* hidden = (const float*)d_in[1];
    const float* W_in   = (const float*)d_in[2];
    const float* b_in   = (const float*)d_in[3];
    const float* gamma  = (const float*)d_in[4];
    const float* beta   = (const float*)d_in[5];
    const float* Wq     = (const float*)d_in[6];
    const float* bq     = (const float*)d_in[7];
    const float* Wk     = (const float*)d_in[8];
    const float* bk     = (const float*)d_in[9];
    const float* Wv     = (const float*)d_in[10];
    const float* bv     = (const float*)d_in[11];
    const float* Wg     = (const float*)d_in[12];
    const float* bg     = (const float*)d_in[13];
    const float* Wp     = (const float*)d_in[14];
    const float* bp     = (const float*)d_in[15];
    const float* W_out  = (const float*)d_in[16];
    const float* b_out  = (const float*)d_in[17];
    float* out = (float*)d_out;
    float* hid_out = out + 262144;

    cudaFuncSetAttribute(pass2_mma_kernel,
                         cudaFuncAttributeMaxDynamicSharedMemorySize, SMEM_P2);

    zero_init_kernel<<<1, 64>>>();
    conv_in_kernel<<<dim3(256, 2), 256>>>(x, W_in, b_in);
    for (int l = 0; l < Lnum; l++) {
        fold_kernel<<<2, 64>>>(gamma + l * 64, beta + l * 64);
        zero_kf_kernel<<<32, 256>>>();
        pass2_mma_kernel<<<dim3(74, 2), 256, SMEM_P2>>>(
            Wk + l * 4096, bk + l * 64, Wv + l * 4096, bv + l * 64,
            Wg + l * 8192, bg + l * 128);
        memfold_kernel<<<2, 256>>>(hidden + l * 4096, Wq + l * 4096, bq + l * 64,
                                   Wp + l * 4096, bp + l * 64, hid_out + l * 4096);
        pass3_kernel<<<dim3(74, 2), 256>>>();
    }
    conv_out_kernel<<<dim3(256, 2), 256>>>(x, W_out, b_out, out);
}

// round 7
// speedup vs baseline: 2.2965x; 1.0575x over previous
#include <cuda_runtime.h>
#include <cuda_bf16.h>
#include <cstdint>
#include <cstddef>

constexpr int Cc   = 64;
constexpr int Np   = 65536;
constexpr int Lnum = 4;
constexpr int Bn   = 2;
constexpr int FP   = 72;    // bf16 fragment pitch — conflict-free
constexpr int CP   = 136;   // cov transpose pitch

__device__ float g_feat[(size_t)Bn * Cc * Np];          // fp32, for conv_out
__device__ uint32_t g_featbf[(size_t)Bn * Np * 32];     // bf16 pairs, [b][n][c]
__device__ float g_sum[Bn * 64];
__device__ float g_Cov[Bn * 4096];
__device__ float g_T[Bn * 4096];                        // logical = T*phys + t
__device__ float g_t[Bn * 64];
__device__ float g_afold[Bn * 64];
__device__ float g_bfold[Bn * 64];
__device__ float g_know[Bn * 4096];
__device__ float g_fsum[Bn * 64];
__device__ float g_M2[Bn * 4096];
__device__ float g_d2[Bn * 64];
__device__ float g_Weff[Bn * 16384];
__device__ float g_beff[Bn * 256];
__device__ float g_Wout[Bn * 1152];
__device__ float g_tb[Bn * 18];                         // per-tap t-bias
__device__ float g_bout[Bn * 2];

typedef uint32_t u32;
__device__ __forceinline__ u32 pkbf(float hi, float lo) {
    u32 r; asm("cvt.rn.bf16x2.f32 %0, %1, %2;" : "=r"(r) : "f"(hi), "f"(lo));
    return r;
}
__device__ __forceinline__ float sigm(float x) { return 1.f / (1.f + __expf(-x)); }
__device__ __forceinline__ void mma16816(float c[4], u32 a0, u32 a1, u32 a2,
                                         u32 a3, u32 b0, u32 b1) {
    asm volatile(
        "mma.sync.aligned.m16n8k16.row.col.f32.bf16.bf16.f32 "
        "{%0,%1,%2,%3}, {%4,%5,%6,%7}, {%8,%9}, {%0,%1,%2,%3};"
        : "+f"(c[0]), "+f"(c[1]), "+f"(c[2]), "+f"(c[3])
        : "r"(a0), "r"(a1), "r"(a2), "r"(a3), "r"(b0), "r"(b1));
}

// ===================== init: T=I, t=0, Cov=0, sum=0 =====================
__global__ void zero_init_kernel() {
    int tid = threadIdx.x;
    for (int i = tid; i < Bn * 4096; i += 256) {
        g_Cov[i] = 0.f;
        g_T[i] = (((i >> 6) & 63) == (i & 63)) ? 1.f : 0.f;
    }
    for (int i = tid; i < Bn * 64; i += 256) { g_sum[i] = 0.f; g_t[i] = 0.f; }
}

// ===================== conv3x3 in: fp32 + bf16 copies =====================
__global__ void __launch_bounds__(256) conv_in_kernel(
    const float* __restrict__ x, const float* __restrict__ W,
    const float* __restrict__ bias)
{
    __shared__ float xs[2 * 3 * 258];
    __shared__ float ws[64 * 18];
    __shared__ float bsh[64];
    int b = blockIdx.y, y = blockIdx.x, tid = threadIdx.x;
    for (int i = tid; i < 64 * 18; i += 256) ws[i] = W[i];
    if (tid < 64) bsh[tid] = bias[tid];
    for (int i = tid; i < 2 * 3 * 258; i += 256) {
        int c = i / 774, rem = i % 774, r = rem / 258, col = rem % 258;
        int yy = y + r - 1, xx = col - 1;
        float v = 0.f;
        if (yy >= 0 && yy < 256 && xx >= 0 && xx < 256)
            v = x[((size_t)(b * 2 + c) * 256 + yy) * 256 + xx];
        xs[i] = v;
    }
    __syncthreads();
    float in[18];
#pragma unroll
    for (int c = 0; c < 2; c++)
#pragma unroll
        for (int r = 0; r < 3; r++)
#pragma unroll
            for (int k = 0; k < 3; k++)
                in[c * 9 + r * 3 + k] = xs[c * 774 + r * 258 + tid + k];
    int n = y * 256 + tid;
    size_t ob = (size_t)b * Cc * Np + n;
    u32* gbf = g_featbf + (size_t)b * Np * 32 + (size_t)n * 32;
#pragma unroll
    for (int oc = 0; oc < 64; oc += 2) {
        float a0 = bsh[oc], a1 = bsh[oc + 1];
#pragma unroll
        for (int t = 0; t < 18; t++) {
            a0 += ws[oc * 18 + t] * in[t];
            a1 += ws[(oc + 1) * 18 + t] * in[t];
        }
        g_feat[ob + (size_t)oc * Np] = a0;
        g_feat[ob + (size_t)(oc + 1) * Np] = a1;
        gbf[oc >> 1] = pkbf(a1, a0);
    }
}

// ===================== Cov = sum feat feat^T (+ sums via ones row) ========
__global__ void __launch_bounds__(256) cov_kernel() {
    __shared__ __nv_bfloat16 Xt[80 * CP];
    int b = blockIdx.y, tid = threadIdx.x;
    int wid = tid >> 5, g = (tid & 31) >> 2, tg = tid & 3;
    for (int i = tid; i < 16 * CP; i += 256) {
        int r = 64 + i / CP;
        Xt[(size_t)(i / CP + 64) * CP + (i % CP)] =
            (r == 64) ? __float2bfloat16(1.f) : __float2bfloat16(0.f);
    }
    float C[8][4];
#pragma unroll
    for (int i = 0; i < 8; i++)
#pragma unroll
        for (int j = 0; j < 4; j++) C[i][j] = 0.f;
    const u32* gbf = g_featbf + (size_t)b * Np * 32;
    for (int t = blockIdx.x; t < 512; t += 74) {
        int n0 = t << 7;
        __syncthreads();
        for (int i = tid; i < 4096; i += 256) {
            int px = i >> 5, w = i & 31;
            u32 v = gbf[(size_t)(n0 + px) * 32 + w];
            __nv_bfloat162 h = *(__nv_bfloat162*)&v;
            Xt[(2 * w) * CP + px] = h.x;
            Xt[(2 * w + 1) * CP + px] = h.y;
        }
        __syncthreads();
        if (wid < 5) {
            int rb = wid * 16;
#pragma unroll
            for (int ks = 0; ks < 8; ks++) {
                int kb2 = ks * 16 + 2 * tg;
                u32 a0 = *(const u32*)&Xt[(rb + g) * CP + kb2];
                u32 a1 = *(const u32*)&Xt[(rb + g + 8) * CP + kb2];
                u32 a2 = *(const u32*)&Xt[(rb + g) * CP + kb2 + 8];
                u32 a3 = *(const u32*)&Xt[(rb + g + 8) * CP + kb2 + 8];
#pragma unroll
                for (int nt = 0; nt < 8; nt++) {
                    u32 b0 = *(const u32*)&Xt[(nt * 8 + g) * CP + kb2];
                    u32 b1 = *(const u32*)&Xt[(nt * 8 + g) * CP + kb2 + 8];
                    mma16816(C[nt], a0, a1, a2, a3, b0, b1);
                }
            }
        }
    }
    if (wid < 4) {
        int c0 = wid * 16 + g;
        float* cb = g_Cov + b * 4096;
#pragma unroll
        for (int nt = 0; nt < 8; nt++) {
            int d = nt * 8 + tg * 2;
            atomicAdd(&cb[c0 * 64 + d], C[nt][0]);
            atomicAdd(&cb[c0 * 64 + d + 1], C[nt][1]);
            atomicAdd(&cb[(c0 + 8) * 64 + d], C[nt][2]);
            atomicAdd(&cb[(c0 + 8) * 64 + d + 1], C[nt][3]);
        }
    } else if (wid == 4 && g == 0) {
#pragma unroll
        for (int nt = 0; nt < 8; nt++) {
            int d = nt * 8 + tg * 2;
            atomicAdd(&g_sum[b * 64 + d], C[nt][0]);
            atomicAdd(&g_sum[b * 64 + d + 1], C[nt][1]);
        }
    }
}

// ===================== per-layer: analytic GN stats =====================
__global__ void __launch_bounds__(256) prep_stats_kernel(
    const float* __restrict__ gamma, const float* __restrict__ beta)
{
    int b = blockIdx.x, tid = threadIdx.x;
    __shared__ float T[4096], Cov[4096], sumS[64], tS[64], S1[64], S2[64];
    for (int i = tid; i < 4096; i += 256) {
        T[i] = g_T[b * 4096 + i];
        Cov[i] = g_Cov[b * 4096 + i];
        g_know[b * 4096 + i] = 0.f;
    }
    if (tid < 64) {
        sumS[tid] = g_sum[b * 64 + tid];
        tS[tid] = g_t[b * 64 + tid];
        g_fsum[b * 64 + tid] = 0.f;
    }
    __syncthreads();
    int c = tid >> 2, qn = tid & 3;
    float rs = 0.f, qf = 0.f;
    for (int e = qn * 16; e < qn * 16 + 16; e++) {
        float Te = T[c * 64 + e];
        rs += Te * sumS[e];
        float inner = 0.f;
        for (int f = 0; f < 64; f++) inner += Cov[e * 64 + f] * T[c * 64 + f];
        qf += Te * inner;
    }
    rs += __shfl_xor_sync(0xffffffffu, rs, 1);
    rs += __shfl_xor_sync(0xffffffffu, rs, 2);
    qf += __shfl_xor_sync(0xffffffffu, qf, 1);
    qf += __shfl_xor_sync(0xffffffffu, qf, 2);
    if (qn == 0) {
        float tc = tS[c];
        S1[c] = rs + 65536.f * tc;
        S2[c] = qf + 2.f * tc * rs + 65536.f * tc * tc;
    }
    __syncthreads();
    if (tid < 64) {
        int g = tid >> 3;
        float m = 0.f, q2 = 0.f;
        for (int j = 0; j < 8; j++) { m += S1[g * 8 + j]; q2 += S2[g * 8 + j]; }
        float inv = 1.f / (8.f * 65536.f);
        m *= inv; q2 *= inv;
        float var = q2 - m * m;
        float a = gamma[tid] * rsqrtf(var + 1e-5f);
        g_afold[b * 64 + tid] = a;
        g_bfold[b * 64 + tid] = beta[tid] - m * a;
    }
}

// ===================== per-layer: effective weights ====================
__global__ void __launch_bounds__(256) prep_weff_kernel(
    const float* __restrict__ Wk, const float* __restrict__ bk,
    const float* __restrict__ Wv, const float* __restrict__ bv,
    const float* __restrict__ Wg, const float* __restrict__ bg)
{
    int s = blockIdx.x, b = blockIdx.y, tid = threadIdx.x;
    const float* Ws = (s == 0) ? Wk : (s == 1) ? Wv : (s == 2) ? Wg : Wg + 4096;
    const float* bs = (s == 0) ? bk : (s == 1) ? bv : (s == 2) ? bg : bg + 64;
    __shared__ float aT[4096], Wrow[4096], wvec[64];
    for (int i = tid; i < 4096; i += 256) {
        int c = i >> 6;
        aT[i] = g_afold[b * 64 + c] * g_T[b * 4096 + i];
        Wrow[i] = Ws[i];
    }
    if (tid < 64)
        wvec[tid] = g_afold[b * 64 + tid] * g_t[b * 64 + tid] + g_bfold[b * 64 + tid];
    __syncthreads();
    for (int j = tid; j < 4096; j += 256) {
        int oc = j >> 6, e = j & 63;
        float acc = 0.f;
#pragma unroll 4
        for (int c = 0; c < 64; c++) acc += Wrow[oc * 64 + c] * aT[c * 64 + e];
        g_Weff[b * 16384 + (s * 64 + oc) * 64 + e] = acc;
    }
    if (tid < 64) {
        float acc = bs[tid];
        for (int c = 0; c < 64; c++) acc += Wrow[tid * 64 + c] * wvec[c];
        g_beff[b * 256 + s * 64 + tid] = acc;
    }
}

// ===================== pass 2: warp-MMA =====================
constexpr int SM_WHI = 0;
constexpr int SM_WLO = 36864;
constexpr int SM_XS  = 73728;
constexpr int SM_VT  = 92160;
constexpr int SM_GI  = 101376;
constexpr int SM_KG  = 110592;
constexpr int SM_BIA = 119808;
constexpr int SMEM_P2 = 120832;

__global__ void __launch_bounds__(256, 1) pass2_mma_kernel() {
    extern __shared__ char smc[];
    __nv_bfloat16* WHi = (__nv_bfloat16*)(smc + SM_WHI);
    __nv_bfloat16* WLo = (__nv_bfloat16*)(smc + SM_WLO);
    __nv_bfloat16* Xs  = (__nv_bfloat16*)(smc + SM_XS);
    __nv_bfloat16* Vt  = (__nv_bfloat16*)(smc + SM_VT);
    __nv_bfloat16* Gi  = (__nv_bfloat16*)(smc + SM_GI);
    __nv_bfloat16* Kg  = (__nv_bfloat16*)(smc + SM_KG);
    float* biasS = (float*)(smc + SM_BIA);

    int b = blockIdx.y, tid = threadIdx.x;
    int wid = tid >> 5, g = (tid & 31) >> 2, tg = tid & 3;

    for (int i = tid; i < 16384; i += 256) {
        int oc = i >> 6, c = i & 63;
        float w = g_Weff[b * 16384 + i];
        __nv_bfloat16 h = __float2bfloat16(w);
        WHi[oc * FP + c] = h;
        WLo[oc * FP + c] = __float2bfloat16(w - __bfloat162float(h));
    }
    biasS[tid] = g_beff[b * 256 + tid];

    float Ck[4][4];
#pragma unroll
    for (int i = 0; i < 4; i++)
#pragma unroll
        for (int j = 0; j < 4; j++) Ck[i][j] = 0.f;
    float fpart[4] = {0.f, 0.f, 0.f, 0.f};

    const u32* gbf = g_featbf + (size_t)b * Np * 32;
    int mtk = wid >> 1, ntb = (wid & 1) * 4;
    __syncthreads();

    for (int t = blockIdx.x; t < 512; t += 74) {
        int n0 = t << 7;
        for (int i = tid; i < 4096; i += 256) {
            int px = i >> 5, w = i & 31;
            *(u32*)&Xs[px * FP + 2 * w] = gbf[(size_t)(n0 + px) * 32 + w];
        }
        __syncthreads();

#pragma unroll 1
        for (int h = 0; h < 2; h++) {
            const __nv_bfloat16* Xh = Xs + h * 64 * FP;
            float C[2][8][4];
#pragma unroll
            for (int mt = 0; mt < 2; mt++)
#pragma unroll
                for (int nt = 0; nt < 8; nt++)
#pragma unroll
                    for (int q = 0; q < 4; q++) C[mt][nt][q] = 0.f;
            int rbase = wid * 32;
#pragma unroll
            for (int ks = 0; ks < 4; ks++) {
                int kb2 = ks * 16 + 2 * tg;
                u32 bfr[8][2];
#pragma unroll
                for (int nt = 0; nt < 8; nt++) {
                    bfr[nt][0] = *(const u32*)&Xh[(nt * 8 + g) * FP + kb2];
                    bfr[nt][1] = *(const u32*)&Xh[(nt * 8 + g) * FP + kb2 + 8];
                }
#pragma unroll
                for (int mt = 0; mt < 2; mt++) {
                    int r = rbase + mt * 16;
                    u32 h0 = *(const u32*)&WHi[(r + g) * FP + kb2];
                    u32 h1 = *(const u32*)&WHi[(r + g + 8) * FP + kb2];
                    u32 h2 = *(const u32*)&WHi[(r + g) * FP + kb2 + 8];
                    u32 h3 = *(const u32*)&WHi[(r + g + 8) * FP + kb2 + 8];
                    u32 l0 = *(const u32*)&WLo[(r + g) * FP + kb2];
                    u32 l1 = *(const u32*)&WLo[(r + g + 8) * FP + kb2];
                    u32 l2 = *(const u32*)&WLo[(r + g) * FP + kb2 + 8];
                    u32 l3 = *(const u32*)&WLo[(r + g + 8) * FP + kb2 + 8];
#pragma unroll
                    for (int nt = 0; nt < 8; nt++) {
                        mma16816(C[mt][nt], h0, h1, h2, h3, bfr[nt][0], bfr[nt][1]);
                        mma16816(C[mt][nt], l0, l1, l2, l3, bfr[nt][0], bfr[nt][1]);
                    }
                }
            }
            if (wid == 2 || wid == 3) {
                int base = (wid - 2) * 32;
#pragma unroll
                for (int mt = 0; mt < 2; mt++) {
                    int r0 = base + mt * 16 + g, r1 = r0 + 8;
                    float b0 = biasS[64 + r0], b1 = biasS[64 + r1];
#pragma unroll
                    for (int nt = 0; nt < 8; nt++) {
                        int col = nt * 8 + tg * 2;
                        *(u32*)&Vt[r0 * FP + col] =
                            pkbf(C[mt][nt][1] + b0, C[mt][nt][0] + b0);
                        *(u32*)&Vt[r1 * FP + col] =
                            pkbf(C[mt][nt][3] + b1, C[mt][nt][2] + b1);
                    }
                }
            } else if (wid == 6 || wid == 7) {
                int base = (wid - 6) * 32;
#pragma unroll
                for (int mt = 0; mt < 2; mt++) {
                    int r0 = base + mt * 16 + g, r1 = r0 + 8;
                    float b0 = biasS[192 + r0], b1 = biasS[192 + r1];
#pragma unroll
                    for (int nt = 0; nt < 8; nt++) {
                        int col = nt * 8 + tg * 2;
                        *(u32*)&Gi[r0 * FP + col] =
                            pkbf(sigm(C[mt][nt][1] + b0), sigm(C[mt][nt][0] + b0));
                        *(u32*)&Gi[r1 * FP + col] =
                            pkbf(sigm(C[mt][nt][3] + b1), sigm(C[mt][nt][2] + b1));
                    }
                }
            } else if (wid == 4 || wid == 5) {
                int base = (wid - 4) * 32;
#pragma unroll
                for (int mt = 0; mt < 2; mt++) {
                    int r0 = base + mt * 16 + g, r1 = r0 + 8;
                    float b0 = biasS[128 + r0], b1 = biasS[128 + r1];
#pragma unroll
                    for (int nt = 0; nt < 8; nt++) {
                        fpart[mt * 2]     += sigm(C[mt][nt][0] + b0) + sigm(C[mt][nt][1] + b0);
                        fpart[mt * 2 + 1] += sigm(C[mt][nt][2] + b1) + sigm(C[mt][nt][3] + b1);
                    }
                }
            }
            __syncthreads();
            if (wid < 2) {
                int base = wid * 32;
#pragma unroll
                for (int mt = 0; mt < 2; mt++) {
                    int r0 = base + mt * 16 + g, r1 = r0 + 8;
                    float b0 = biasS[r0], b1 = biasS[r1];
#pragma unroll
                    for (int nt = 0; nt < 8; nt++) {
                        int col = nt * 8 + tg * 2;
                        u32 gi0 = *(const u32*)&Gi[r0 * FP + col];
                        u32 gi1 = *(const u32*)&Gi[r1 * FP + col];
                        float s0lo = __bfloat162float(((__nv_bfloat162*)&gi0)->x);
                        float s0hi = __bfloat162float(((__nv_bfloat162*)&gi0)->y);
                        float s1lo = __bfloat162float(((__nv_bfloat162*)&gi1)->x);
                        float s1hi = __bfloat162float(((__nv_bfloat162*)&gi1)->y);
                        *(u32*)&Kg[r0 * FP + col] =
                            pkbf((C[mt][nt][1] + b0) * s0hi, (C[mt][nt][0] + b0) * s0lo);
                        *(u32*)&Kg[r1 * FP + col] =
                            pkbf((C[mt][nt][3] + b1) * s1hi, (C[mt][nt][2] + b1) * s1lo);
                    }
                }
            }
            __syncthreads();
#pragma unroll
            for (int ks = 0; ks < 4; ks++) {
                int kb2 = ks * 16 + 2 * tg;
                u32 a0 = *(const u32*)&Kg[(mtk * 16 + g) * FP + kb2];
                u32 a1 = *(const u32*)&Kg[(mtk * 16 + g + 8) * FP + kb2];
                u32 a2 = *(const u32*)&Kg[(mtk * 16 + g) * FP + kb2 + 8];
                u32 a3 = *(const u32*)&Kg[(mtk * 16 + g + 8) * FP + kb2 + 8];
#pragma unroll
                for (int ntl = 0; ntl < 4; ntl++) {
                    u32 b0 = *(const u32*)&Vt[((ntb + ntl) * 8 + g) * FP + kb2];
                    u32 b1 = *(const u32*)&Vt[((ntb + ntl) * 8 + g) * FP + kb2 + 8];
                    mma16816(Ck[ntl], a0, a1, a2, a3, b0, b1);
                }
            }
            __syncthreads();
        }
    }
    float* kbase = g_know + b * 4096;
#pragma unroll
    for (int ntl = 0; ntl < 4; ntl++) {
        int c0 = mtk * 16 + g, d0 = (ntb + ntl) * 8 + tg * 2;
        atomicAdd(&kbase[c0 * 64 + d0],           Ck[ntl][0]);
        atomicAdd(&kbase[c0 * 64 + d0 + 1],       Ck[ntl][1]);
        atomicAdd(&kbase[(c0 + 8) * 64 + d0],     Ck[ntl][2]);
        atomicAdd(&kbase[(c0 + 8) * 64 + d0 + 1], Ck[ntl][3]);
    }
    if (wid == 4 || wid == 5) {
#pragma unroll
        for (int s = 0; s < 4; s++) {
            float v = fpart[s];
            v += __shfl_xor_sync(0xffffffffu, v, 1);
            v += __shfl_xor_sync(0xffffffffu, v, 2);
            if (tg == 0) {
                int ch = (wid - 4) * 32 + (s >> 1) * 16 + g + (s & 1) * 8;
                atomicAdd(&g_fsum[b * 64 + ch], v);
            }
        }
    }
}

// ===================== memfold: new_mem + M2/d2 =====================
__global__ void __launch_bounds__(256) memfold_kernel(
    const float* __restrict__ hidden, const float* __restrict__ Wq,
    const float* __restrict__ bq, const float* __restrict__ Wp,
    const float* __restrict__ bp, float* __restrict__ hid_out)
{
    int b = blockIdx.x, tid = threadIdx.x;
    __shared__ float memS[4096], T[4096], rS[64], uS[64], fm[64];
    if (tid < 64) fm[tid] = g_fsum[b * 64 + tid] * (1.f / 65536.f);
    __syncthreads();
    const float* kb = g_know + b * 4096;
    const float* hb = hidden + (size_t)b * Lnum * 4096;
    float* ho = hid_out + (size_t)b * Lnum * 4096;
    for (int i = tid; i < 4096; i += 256) {
        int c = i >> 6;
        float m = fm[c] * hb[i] + kb[i] * (1.f / 65536.f);
        memS[i] = m; ho[i] = m;
    }
    if (tid < 64) {
        float u = bq[tid];
        for (int e = 0; e < 64; e++) u += Wq[tid * 64 + e] * g_bfold[b * 64 + e];
        uS[tid] = u;
    }
    __syncthreads();
    if (tid < 64) {
        float r = 0.f;
        for (int c = 0; c < 64; c++) r += memS[c * 64 + tid] * uS[c];
        rS[tid] = r;
    }
    for (int i = tid; i < 4096; i += 256) {
        int d = i >> 6, e = i & 63;
        float t = 0.f;
        for (int c = 0; c < 64; c++) t += memS[c * 64 + d] * Wq[c * 64 + e];
        T[i] = t * g_afold[b * 64 + e];
    }
    __syncthreads();
    for (int i = tid; i < 4096; i += 256)
        memS[i] = Wp[(i & 63) * 64 + (i >> 6)];
    __syncthreads();
    const float scale = 0.125f;
    for (int i = tid; i < 4096; i += 256) {
        int e = i >> 6, o = i & 63;
        float m = 0.f;
        for (int d = 0; d < 64; d++) m += memS[d * 64 + o] * T[d * 64 + e];
        g_M2[b * 4096 + i] = m * scale;
    }
    if (tid < 64) {
        float s = 0.f;
        for (int d = 0; d < 64; d++) s += memS[d * 64 + tid] * rS[d];
        g_d2[b * 64 + tid] = s * scale + bp[tid];
    }
}

// ===================== compose: T <- (I+M)T, t <- (I+M)t + d2 ==========
__global__ void __launch_bounds__(256) compose_kernel() {
    int b = blockIdx.x, tid = threadIdx.x;
    __shared__ float M2[4096], Told[4096], tS[64], d2S[64];
    for (int i = tid; i < 4096; i += 256) {
        M2[i] = g_M2[b * 4096 + i];       // M[o][e] = M2[e*64+o]
        Told[i] = g_T[b * 4096 + i];
    }
    if (tid < 64) { tS[tid] = g_t[b * 64 + tid]; d2S[tid] = g_d2[b * 64 + tid]; }
    __syncthreads();
    for (int j = tid; j < 4096; j += 256) {
        int o = j >> 6, e = j & 63;
        float acc = Told[o * 64 + e];
#pragma unroll 4
        for (int m = 0; m < 64; m++) acc += M2[m * 64 + o] * Told[m * 64 + e];
        g_T[b * 4096 + j] = acc;
    }
    if (tid < 64) {
        float acc = tS[tid] + d2S[tid];
        for (int e = 0; e < 64; e++) acc += M2[e * 64 + tid] * tS[e];
        g_t[b * 64 + tid] = acc;
    }
}

// ===================== conv_out prep: fold T4 into W_out =====================
__global__ void __launch_bounds__(256) convout_prep_kernel(
    const float* __restrict__ W, const float* __restrict__ bias)
{
    int b = blockIdx.x, tid = threadIdx.x;
    __shared__ float T[4096];
    for (int i = tid; i < 4096; i += 256) T[i] = g_T[b * 4096 + i];
    __syncthreads();
    for (int j = tid; j < 1152; j += 256) {
        int o = j / 576, r = j % 576, e = r / 9, tap = r % 9;
        float acc = 0.f;
        for (int c = 0; c < 64; c++)
            acc += W[o * 576 + c * 9 + tap] * T[c * 64 + e];
        g_Wout[b * 1152 + j] = acc;
    }
    if (tid < 18) {   // per-tap t bias
        int o = tid / 9, tap = tid % 9;
        float acc = 0.f;
        for (int c = 0; c < 64; c++)
            acc += W[o * 576 + c * 9 + tap] * g_t[b * 64 + c];
        g_tb[b * 18 + tid] = acc;
    }
    if (tid < 2) g_bout[b * 2 + tid] = bias[tid];
}

// ===================== conv3x3 out + residual (on feat_phys) ============
__global__ void __launch_bounds__(256) conv_out_kernel(
    const float* __restrict__ x, float* __restrict__ out)
{
    __shared__ float fs[8 * 3 * 258];
    __shared__ float ws[1152];
    __shared__ float tb[18];
    int b = blockIdx.y, y = blockIdx.x, tid = threadIdx.x;
    for (int i = tid; i < 1152; i += 256) ws[i] = g_Wout[b * 1152 + i];
    if (tid < 18) tb[tid] = g_tb[b * 18 + tid];
    __syncthreads();
    float acc0 = g_bout[b * 2 + 0], acc1 = g_bout[b * 2 + 1];
#pragma unroll
    for (int r = 0; r < 3; r++) {
        int yy = y + r - 1;
        if (yy < 0 || yy >= 256) continue;
#pragma unroll
        for (int k = 0; k < 3; k++) {
            int xx = tid + k - 1;
            if (xx < 0 || xx >= 256) continue;
            acc0 += tb[r * 3 + k];
            acc1 += tb[9 + r * 3 + k];
        }
    }
    const float* fb = g_feat + (size_t)b * Cc * Np;
    for (int cc = 0; cc < 64; cc += 8) {
        __syncthreads();
        for (int i = tid; i < 6192; i += 256) {
            int c = i / 774, rem = i % 774, r = rem / 258, col = rem % 258;
            int yy = y + r - 1, xx = col - 1;
            float v = 0.f;
            if (yy >= 0 && yy < 256 && xx >= 0 && xx < 256)
                v = fb[(size_t)(cc + c) * Np + yy * 256 + xx];
            fs[i] = v;
        }
        __syncthreads();
#pragma unroll
        for (int c = 0; c < 8; c++) {
            float in[9];
#pragma unroll
            for (int r = 0; r < 3; r++)
#pragma unroll
                for (int k = 0; k < 3; k++)
                    in[r * 3 + k] = fs[c * 774 + r * 258 + tid + k];
            const float* w0 = &ws[(cc + c) * 9];
            const float* w1 = &ws[(64 + cc + c) * 9];
#pragma unroll
            for (int t = 0; t < 9; t++) { acc0 += w0[t] * in[t]; acc1 += w1[t] * in[t]; }
        }
    }
    int o = y * 256 + tid;
    out[(size_t)(b * 2 + 0) * Np + o] = acc0 + x[(size_t)(b * 2 + 0) * Np + o];
    out[(size_t)(b * 2 + 1) * Np + o] = acc1 + x[(size_t)(b * 2 + 1) * Np + o];
}

extern "C" void kernel_launch(void* const* d_in, const int* in_sizes, int n_in,
                              void* d_out, int out_size)
{
    const float* x      = (const float*)d_in[0];
    const float* hidden = (const float*)d_in[1];
    const float* W_in   = (const float*)d_in[2];
    const float* b_in   = (const float*)d_in[3];
    const float* gamma  = (const float*)d_in[4];
    const float* beta   = (const float*)d_in[5];
    const float* Wq     = (const float*)d_in[6];
    const float* bq     = (const float*)d_in[7];
    const float* Wk     = (const float*)d_in[8];
    const float* bk     = (const float*)d_in[9];
    const float* Wv     = (const float*)d_in[10];
    const float* bv     = (const float*)d_in[11];
    const float* Wg     = (const float*)d_in[12];
    const float* bg     = (const float*)d_in[13];
    const float* Wp     = (const float*)d_in[14];
    const float* bp     = (const float*)d_in[15];
    const float* W_out  = (const float*)d_in[16];
    const float* b_out  = (const float*)d_in[17];
    float* out = (float*)d_out;
    float* hid_out = out + 262144;

    cudaFuncSetAttribute(pass2_mma_kernel,
                         cudaFuncAttributeMaxDynamicSharedMemorySize, SMEM_P2);

    zero_init_kernel<<<1, 256>>>();
    conv_in_kernel<<<dim3(256, 2), 256>>>(x, W_in, b_in);
    cov_kernel<<<dim3(74, 2), 256>>>();
    for (int l = 0; l < Lnum; l++) {
        prep_stats_kernel<<<2, 256>>>(gamma + l * 64, beta + l * 64);
        prep_weff_kernel<<<dim3(4, 2), 256>>>(
            Wk + l * 4096, bk + l * 64, Wv + l * 4096, bv + l * 64,
            Wg + l * 8192, bg + l * 128);
        pass2_mma_kernel<<<dim3(74, 2), 256, SMEM_P2>>>();
        memfold_kernel<<<2, 256>>>(hidden + l * 4096, Wq + l * 4096, bq + l * 64,
                                   Wp + l * 4096, bp + l * 64, hid_out + l * 4096);
        compose_kernel<<<2, 256>>>();
    }
    convout_prep_kernel<<<2, 256>>>(W_out, b_out);
    conv_out_kernel<<<dim3(256, 2), 256>>>(x, out);
}

// round 8
// speedup vs baseline: 2.3313x; 1.0151x over previous
#include <cuda_runtime.h>
#include <cuda_bf16.h>
#include <cstdint>
#include <cstddef>

constexpr int Cc   = 64;
constexpr int Np   = 65536;
constexpr int Lnum = 4;
constexpr int Bn   = 2;
constexpr int FP   = 72;    // bf16 fragment pitch — conflict-free
constexpr int CP   = 136;   // cov transpose pitch

__device__ float g_feat[(size_t)Bn * Cc * Np];          // fp32, for conv_out
__device__ uint32_t g_featbf[(size_t)Bn * Np * 32];     // bf16 pairs, [b][n][c]
__device__ float g_sum[Bn * 64];
__device__ float g_Cov[Bn * 4096];
__device__ float g_T[Bn * 4096];                        // logical = T*phys + t
__device__ float g_t[Bn * 64];
__device__ float g_afold[Bn * 64];
__device__ float g_bfold[Bn * 64];
__device__ float g_know[Bn * 4096];
__device__ float g_fsum[Bn * 64];
__device__ float g_Weff[Bn * 16384];
__device__ float g_beff[Bn * 256];
__device__ float g_Wout[Bn * 1152];
__device__ float g_tb[Bn * 18];                         // per-tap t-bias
__device__ float g_bout[Bn * 2];

typedef uint32_t u32;
__device__ __forceinline__ u32 pkbf(float hi, float lo) {
    u32 r; asm("cvt.rn.bf16x2.f32 %0, %1, %2;" : "=r"(r) : "f"(hi), "f"(lo));
    return r;
}
__device__ __forceinline__ float sigm(float x) { return 1.f / (1.f + __expf(-x)); }
__device__ __forceinline__ void mma16816(float c[4], u32 a0, u32 a1, u32 a2,
                                         u32 a3, u32 b0, u32 b1) {
    asm volatile(
        "mma.sync.aligned.m16n8k16.row.col.f32.bf16.bf16.f32 "
        "{%0,%1,%2,%3}, {%4,%5,%6,%7}, {%8,%9}, {%0,%1,%2,%3};"
        : "+f"(c[0]), "+f"(c[1]), "+f"(c[2]), "+f"(c[3])
        : "r"(a0), "r"(a1), "r"(a2), "r"(a3), "r"(b0), "r"(b1));
}

// ===================== init: T=I, t=0, Cov=0, sum=0 =====================
__global__ void zero_init_kernel() {
    int tid = threadIdx.x;
    for (int i = tid; i < Bn * 4096; i += 256) {
        g_Cov[i] = 0.f;
        g_T[i] = (((i >> 6) & 63) == (i & 63)) ? 1.f : 0.f;
    }
    for (int i = tid; i < Bn * 64; i += 256) { g_sum[i] = 0.f; g_t[i] = 0.f; }
}

// ===================== conv3x3 in: fp32 + bf16 copies =====================
__global__ void __launch_bounds__(256) conv_in_kernel(
    const float* __restrict__ x, const float* __restrict__ W,
    const float* __restrict__ bias)
{
    __shared__ float xs[2 * 3 * 258];
    __shared__ float ws[64 * 18];
    __shared__ float bsh[64];
    int b = blockIdx.y, y = blockIdx.x, tid = threadIdx.x;
    for (int i = tid; i < 64 * 18; i += 256) ws[i] = W[i];
    if (tid < 64) bsh[tid] = bias[tid];
    for (int i = tid; i < 2 * 3 * 258; i += 256) {
        int c = i / 774, rem = i % 774, r = rem / 258, col = rem % 258;
        int yy = y + r - 1, xx = col - 1;
        float v = 0.f;
        if (yy >= 0 && yy < 256 && xx >= 0 && xx < 256)
            v = x[((size_t)(b * 2 + c) * 256 + yy) * 256 + xx];
        xs[i] = v;
    }
    __syncthreads();
    float in[18];
#pragma unroll
    for (int c = 0; c < 2; c++)
#pragma unroll
        for (int r = 0; r < 3; r++)
#pragma unroll
            for (int k = 0; k < 3; k++)
                in[c * 9 + r * 3 + k] = xs[c * 774 + r * 258 + tid + k];
    int n = y * 256 + tid;
    size_t ob = (size_t)b * Cc * Np + n;
    u32* gbf = g_featbf + (size_t)b * Np * 32 + (size_t)n * 32;
#pragma unroll
    for (int oc = 0; oc < 64; oc += 2) {
        float a0 = bsh[oc], a1 = bsh[oc + 1];
#pragma unroll
        for (int t = 0; t < 18; t++) {
            a0 += ws[oc * 18 + t] * in[t];
            a1 += ws[(oc + 1) * 18 + t] * in[t];
        }
        g_feat[ob + (size_t)oc * Np] = a0;
        g_feat[ob + (size_t)(oc + 1) * Np] = a1;
        gbf[oc >> 1] = pkbf(a1, a0);
    }
}

// ===================== Cov = sum feat feat^T (+ sums via ones row) ========
__global__ void __launch_bounds__(256) cov_kernel() {
    __shared__ __nv_bfloat16 Xt[80 * CP];
    int b = blockIdx.y, tid = threadIdx.x;
    int wid = tid >> 5, g = (tid & 31) >> 2, tg = tid & 3;
    for (int i = tid; i < 16 * CP; i += 256) {
        int r = 64 + i / CP;
        Xt[(size_t)(i / CP + 64) * CP + (i % CP)] =
            (r == 64) ? __float2bfloat16(1.f) : __float2bfloat16(0.f);
    }
    float C[8][4];
#pragma unroll
    for (int i = 0; i < 8; i++)
#pragma unroll
        for (int j = 0; j < 4; j++) C[i][j] = 0.f;
    const u32* gbf = g_featbf + (size_t)b * Np * 32;
    for (int t = blockIdx.x; t < 512; t += 74) {
        int n0 = t << 7;
        __syncthreads();
        for (int i = tid; i < 4096; i += 256) {
            int px = i >> 5, w = i & 31;
            u32 v = gbf[(size_t)(n0 + px) * 32 + w];
            __nv_bfloat162 h = *(__nv_bfloat162*)&v;
            Xt[(2 * w) * CP + px] = h.x;
            Xt[(2 * w + 1) * CP + px] = h.y;
        }
        __syncthreads();
        if (wid < 5) {
            int rb = wid * 16;
#pragma unroll
            for (int ks = 0; ks < 8; ks++) {
                int kb2 = ks * 16 + 2 * tg;
                u32 a0 = *(const u32*)&Xt[(rb + g) * CP + kb2];
                u32 a1 = *(const u32*)&Xt[(rb + g + 8) * CP + kb2];
                u32 a2 = *(const u32*)&Xt[(rb + g) * CP + kb2 + 8];
                u32 a3 = *(const u32*)&Xt[(rb + g + 8) * CP + kb2 + 8];
#pragma unroll
                for (int nt = 0; nt < 8; nt++) {
                    u32 b0 = *(const u32*)&Xt[(nt * 8 + g) * CP + kb2];
                    u32 b1 = *(const u32*)&Xt[(nt * 8 + g) * CP + kb2 + 8];
                    mma16816(C[nt], a0, a1, a2, a3, b0, b1);
                }
            }
        }
    }
    if (wid < 4) {
        int c0 = wid * 16 + g;
        float* cb = g_Cov + b * 4096;
#pragma unroll
        for (int nt = 0; nt < 8; nt++) {
            int d = nt * 8 + tg * 2;
            atomicAdd(&cb[c0 * 64 + d], C[nt][0]);
            atomicAdd(&cb[c0 * 64 + d + 1], C[nt][1]);
            atomicAdd(&cb[(c0 + 8) * 64 + d], C[nt][2]);
            atomicAdd(&cb[(c0 + 8) * 64 + d + 1], C[nt][3]);
        }
    } else if (wid == 4 && g == 0) {
#pragma unroll
        for (int nt = 0; nt < 8; nt++) {
            int d = nt * 8 + tg * 2;
            atomicAdd(&g_sum[b * 64 + d], C[nt][0]);
            atomicAdd(&g_sum[b * 64 + d + 1], C[nt][1]);
        }
    }
}

// ===================== prep: stats + Weff + beff + zero (fused) ==========
constexpr int SMEM_PREP = (16384 + 512) * 4;
__global__ void __launch_bounds__(512) prep_kernel(
    const float* __restrict__ gamma, const float* __restrict__ beta,
    const float* __restrict__ Wk, const float* __restrict__ bk,
    const float* __restrict__ Wv, const float* __restrict__ bv,
    const float* __restrict__ Wg, const float* __restrict__ bg)
{
    extern __shared__ float sm[];
    float* T    = sm;             // 4096
    float* Cov  = sm + 4096;      // 4096
    float* aT   = sm + 8192;      // 4096
    float* Wsm  = sm + 12288;     // 4096
    float* sumS = sm + 16384;     // 64 each below
    float* tS   = sumS + 64;
    float* S1   = tS + 64;
    float* S2   = S1 + 64;
    float* af   = S2 + 64;
    float* bf   = af + 64;
    float* wvec = bf + 64;
    int b = blockIdx.x, tid = threadIdx.x;
    for (int i = tid; i < 4096; i += 512) {
        T[i] = g_T[b * 4096 + i];
        Cov[i] = g_Cov[b * 4096 + i];
        g_know[b * 4096 + i] = 0.f;
    }
    if (tid < 64) {
        sumS[tid] = g_sum[b * 64 + tid];
        tS[tid] = g_t[b * 64 + tid];
        g_fsum[b * 64 + tid] = 0.f;
    }
    __syncthreads();
    {   // stats: 8 threads per channel, ILP4 inner
        int c = tid >> 3, qn = tid & 7;
        const float* Tc = T + c * 64;
        float rs = 0.f, qf = 0.f;
#pragma unroll
        for (int eo = 0; eo < 8; eo++) {
            int e = qn * 8 + eo;
            float Te = Tc[e];
            rs += Te * sumS[e];
            const float* Ce = Cov + e * 64;
            float i0 = 0, i1 = 0, i2 = 0, i3 = 0;
#pragma unroll
            for (int f = 0; f < 64; f += 4) {
                i0 += Ce[f] * Tc[f];       i1 += Ce[f + 1] * Tc[f + 1];
                i2 += Ce[f + 2] * Tc[f + 2]; i3 += Ce[f + 3] * Tc[f + 3];
            }
            qf += Te * ((i0 + i1) + (i2 + i3));
        }
        rs += __shfl_xor_sync(~0u, rs, 1); rs += __shfl_xor_sync(~0u, rs, 2);
        rs += __shfl_xor_sync(~0u, rs, 4);
        qf += __shfl_xor_sync(~0u, qf, 1); qf += __shfl_xor_sync(~0u, qf, 2);
        qf += __shfl_xor_sync(~0u, qf, 4);
        if (qn == 0) {
            float tc = tS[c];
            S1[c] = rs + 65536.f * tc;
            S2[c] = qf + 2.f * tc * rs + 65536.f * tc * tc;
        }
    }
    __syncthreads();
    if (tid < 64) {
        int g = tid >> 3;
        float m = 0.f, q2 = 0.f;
#pragma unroll
        for (int j = 0; j < 8; j++) { m += S1[g * 8 + j]; q2 += S2[g * 8 + j]; }
        float inv = 1.f / (8.f * 65536.f);
        m *= inv; q2 *= inv;
        float a = gamma[tid] * rsqrtf(q2 - m * m + 1e-5f);
        float bb = beta[tid] - m * a;
        af[tid] = a; bf[tid] = bb;
        g_afold[b * 64 + tid] = a;
        g_bfold[b * 64 + tid] = bb;
        wvec[tid] = a * tS[tid] + bb;
    }
    __syncthreads();
    for (int i = tid; i < 4096; i += 512) aT[i] = af[i >> 6] * T[i];
    const float* Wsrc[4] = {Wk, Wv, Wg, Wg + 4096};
    const float* bsrc[4] = {bk, bv, bg, bg + 64};
#pragma unroll 1
    for (int s = 0; s < 4; s++) {
        __syncthreads();
        for (int i = tid; i < 4096; i += 512) Wsm[i] = Wsrc[s][i];
        __syncthreads();
        for (int j = tid; j < 4096; j += 512) {
            int oc = j >> 6, e = j & 63;
            const float* wr = Wsm + oc * 64;
            float a0 = 0, a1 = 0, a2 = 0, a3 = 0;
#pragma unroll
            for (int c = 0; c < 64; c += 4) {
                a0 += wr[c]     * aT[c * 64 + e];
                a1 += wr[c + 1] * aT[(c + 1) * 64 + e];
                a2 += wr[c + 2] * aT[(c + 2) * 64 + e];
                a3 += wr[c + 3] * aT[(c + 3) * 64 + e];
            }
            g_Weff[b * 16384 + (s * 64 + oc) * 64 + e] = (a0 + a1) + (a2 + a3);
        }
        if (tid < 64) {
            const float* wr = Wsm + tid * 64;
            float a0 = bsrc[s][tid], a1 = 0, a2 = 0, a3 = 0;
#pragma unroll
            for (int c = 0; c < 64; c += 4) {
                a0 += wr[c] * wvec[c];         a1 += wr[c + 1] * wvec[c + 1];
                a2 += wr[c + 2] * wvec[c + 2]; a3 += wr[c + 3] * wvec[c + 3];
            }
            g_beff[b * 256 + s * 64 + tid] = (a0 + a1) + (a2 + a3);
        }
    }
}

// ===================== pass 2: warp-MMA =====================
constexpr int SM_WHI = 0;
constexpr int SM_WLO = 36864;
constexpr int SM_XS  = 73728;
constexpr int SM_VT  = 92160;
constexpr int SM_GI  = 101376;
constexpr int SM_KG  = 110592;
constexpr int SM_BIA = 119808;
constexpr int SMEM_P2 = 120832;

__global__ void __launch_bounds__(256, 1) pass2_mma_kernel() {
    extern __shared__ char smc[];
    __nv_bfloat16* WHi = (__nv_bfloat16*)(smc + SM_WHI);
    __nv_bfloat16* WLo = (__nv_bfloat16*)(smc + SM_WLO);
    __nv_bfloat16* Xs  = (__nv_bfloat16*)(smc + SM_XS);
    __nv_bfloat16* Vt  = (__nv_bfloat16*)(smc + SM_VT);
    __nv_bfloat16* Gi  = (__nv_bfloat16*)(smc + SM_GI);
    __nv_bfloat16* Kg  = (__nv_bfloat16*)(smc + SM_KG);
    float* biasS = (float*)(smc + SM_BIA);

    int b = blockIdx.y, tid = threadIdx.x;
    int wid = tid >> 5, g = (tid & 31) >> 2, tg = tid & 3;

    for (int i = tid; i < 16384; i += 256) {
        int oc = i >> 6, c = i & 63;
        float w = g_Weff[b * 16384 + i];
        __nv_bfloat16 h = __float2bfloat16(w);
        WHi[oc * FP + c] = h;
        WLo[oc * FP + c] = __float2bfloat16(w - __bfloat162float(h));
    }
    biasS[tid] = g_beff[b * 256 + tid];

    float Ck[4][4];
#pragma unroll
    for (int i = 0; i < 4; i++)
#pragma unroll
        for (int j = 0; j < 4; j++) Ck[i][j] = 0.f;
    float fpart[4] = {0.f, 0.f, 0.f, 0.f};

    const u32* gbf = g_featbf + (size_t)b * Np * 32;
    int mtk = wid >> 1, ntb = (wid & 1) * 4;
    __syncthreads();

    for (int t = blockIdx.x; t < 512; t += 74) {
        int n0 = t << 7;
        for (int i = tid; i < 4096; i += 256) {
            int px = i >> 5, w = i & 31;
            *(u32*)&Xs[px * FP + 2 * w] = gbf[(size_t)(n0 + px) * 32 + w];
        }
        __syncthreads();

#pragma unroll 1
        for (int h = 0; h < 2; h++) {
            const __nv_bfloat16* Xh = Xs + h * 64 * FP;
            float C[2][8][4];
#pragma unroll
            for (int mt = 0; mt < 2; mt++)
#pragma unroll
                for (int nt = 0; nt < 8; nt++)
#pragma unroll
                    for (int q = 0; q < 4; q++) C[mt][nt][q] = 0.f;
            int rbase = wid * 32;
#pragma unroll
            for (int ks = 0; ks < 4; ks++) {
                int kb2 = ks * 16 + 2 * tg;
                u32 bfr[8][2];
#pragma unroll
                for (int nt = 0; nt < 8; nt++) {
                    bfr[nt][0] = *(const u32*)&Xh[(nt * 8 + g) * FP + kb2];
                    bfr[nt][1] = *(const u32*)&Xh[(nt * 8 + g) * FP + kb2 + 8];
                }
#pragma unroll
                for (int mt = 0; mt < 2; mt++) {
                    int r = rbase + mt * 16;
                    u32 h0 = *(const u32*)&WHi[(r + g) * FP + kb2];
                    u32 h1 = *(const u32*)&WHi[(r + g + 8) * FP + kb2];
                    u32 h2 = *(const u32*)&WHi[(r + g) * FP + kb2 + 8];
                    u32 h3 = *(const u32*)&WHi[(r + g + 8) * FP + kb2 + 8];
                    u32 l0 = *(const u32*)&WLo[(r + g) * FP + kb2];
                    u32 l1 = *(const u32*)&WLo[(r + g + 8) * FP + kb2];
                    u32 l2 = *(const u32*)&WLo[(r + g) * FP + kb2 + 8];
                    u32 l3 = *(const u32*)&WLo[(r + g + 8) * FP + kb2 + 8];
#pragma unroll
                    for (int nt = 0; nt < 8; nt++) {
                        mma16816(C[mt][nt], h0, h1, h2, h3, bfr[nt][0], bfr[nt][1]);
                        mma16816(C[mt][nt], l0, l1, l2, l3, bfr[nt][0], bfr[nt][1]);
                    }
                }
            }
            if (wid == 2 || wid == 3) {
                int base = (wid - 2) * 32;
#pragma unroll
                for (int mt = 0; mt < 2; mt++) {
                    int r0 = base + mt * 16 + g, r1 = r0 + 8;
                    float b0 = biasS[64 + r0], b1 = biasS[64 + r1];
#pragma unroll
                    for (int nt = 0; nt < 8; nt++) {
                        int col = nt * 8 + tg * 2;
                        *(u32*)&Vt[r0 * FP + col] =
                            pkbf(C[mt][nt][1] + b0, C[mt][nt][0] + b0);
                        *(u32*)&Vt[r1 * FP + col] =
                            pkbf(C[mt][nt][3] + b1, C[mt][nt][2] + b1);
                    }
                }
            } else if (wid == 6 || wid == 7) {
                int base = (wid - 6) * 32;
#pragma unroll
                for (int mt = 0; mt < 2; mt++) {
                    int r0 = base + mt * 16 + g, r1 = r0 + 8;
                    float b0 = biasS[192 + r0], b1 = biasS[192 + r1];
#pragma unroll
                    for (int nt = 0; nt < 8; nt++) {
                        int col = nt * 8 + tg * 2;
                        *(u32*)&Gi[r0 * FP + col] =
                            pkbf(sigm(C[mt][nt][1] + b0), sigm(C[mt][nt][0] + b0));
                        *(u32*)&Gi[r1 * FP + col] =
                            pkbf(sigm(C[mt][nt][3] + b1), sigm(C[mt][nt][2] + b1));
                    }
                }
            } else if (wid == 4 || wid == 5) {
                int base = (wid - 4) * 32;
#pragma unroll
                for (int mt = 0; mt < 2; mt++) {
                    int r0 = base + mt * 16 + g, r1 = r0 + 8;
                    float b0 = biasS[128 + r0], b1 = biasS[128 + r1];
#pragma unroll
                    for (int nt = 0; nt < 8; nt++) {
                        fpart[mt * 2]     += sigm(C[mt][nt][0] + b0) + sigm(C[mt][nt][1] + b0);
                        fpart[mt * 2 + 1] += sigm(C[mt][nt][2] + b1) + sigm(C[mt][nt][3] + b1);
                    }
                }
            }
            __syncthreads();
            if (wid < 2) {
                int base = wid * 32;
#pragma unroll
                for (int mt = 0; mt < 2; mt++) {
                    int r0 = base + mt * 16 + g, r1 = r0 + 8;
                    float b0 = biasS[r0], b1 = biasS[r1];
#pragma unroll
                    for (int nt = 0; nt < 8; nt++) {
                        int col = nt * 8 + tg * 2;
                        u32 gi0 = *(const u32*)&Gi[r0 * FP + col];
                        u32 gi1 = *(const u32*)&Gi[r1 * FP + col];
                        float s0lo = __bfloat162float(((__nv_bfloat162*)&gi0)->x);
                        float s0hi = __bfloat162float(((__nv_bfloat162*)&gi0)->y);
                        float s1lo = __bfloat162float(((__nv_bfloat162*)&gi1)->x);
                        float s1hi = __bfloat162float(((__nv_bfloat162*)&gi1)->y);
                        *(u32*)&Kg[r0 * FP + col] =
                            pkbf((C[mt][nt][1] + b0) * s0hi, (C[mt][nt][0] + b0) * s0lo);
                        *(u32*)&Kg[r1 * FP + col] =
                            pkbf((C[mt][nt][3] + b1) * s1hi, (C[mt][nt][2] + b1) * s1lo);
                    }
                }
            }
            __syncthreads();
#pragma unroll
            for (int ks = 0; ks < 4; ks++) {
                int kb2 = ks * 16 + 2 * tg;
                u32 a0 = *(const u32*)&Kg[(mtk * 16 + g) * FP + kb2];
                u32 a1 = *(const u32*)&Kg[(mtk * 16 + g + 8) * FP + kb2];
                u32 a2 = *(const u32*)&Kg[(mtk * 16 + g) * FP + kb2 + 8];
                u32 a3 = *(const u32*)&Kg[(mtk * 16 + g + 8) * FP + kb2 + 8];
#pragma unroll
                for (int ntl = 0; ntl < 4; ntl++) {
                    u32 b0 = *(const u32*)&Vt[((ntb + ntl) * 8 + g) * FP + kb2];
                    u32 b1 = *(const u32*)&Vt[((ntb + ntl) * 8 + g) * FP + kb2 + 8];
                    mma16816(Ck[ntl], a0, a1, a2, a3, b0, b1);
                }
            }
            __syncthreads();
        }
    }
    float* kbase = g_know + b * 4096;
#pragma unroll
    for (int ntl = 0; ntl < 4; ntl++) {
        int c0 = mtk * 16 + g, d0 = (ntb + ntl) * 8 + tg * 2;
        atomicAdd(&kbase[c0 * 64 + d0],           Ck[ntl][0]);
        atomicAdd(&kbase[c0 * 64 + d0 + 1],       Ck[ntl][1]);
        atomicAdd(&kbase[(c0 + 8) * 64 + d0],     Ck[ntl][2]);
        atomicAdd(&kbase[(c0 + 8) * 64 + d0 + 1], Ck[ntl][3]);
    }
    if (wid == 4 || wid == 5) {
#pragma unroll
        for (int s = 0; s < 4; s++) {
            float v = fpart[s];
            v += __shfl_xor_sync(0xffffffffu, v, 1);
            v += __shfl_xor_sync(0xffffffffu, v, 2);
            if (tg == 0) {
                int ch = (wid - 4) * 32 + (s >> 1) * 16 + g + (s & 1) * 8;
                atomicAdd(&g_fsum[b * 64 + ch], v);
            }
        }
    }
}

// ===================== update: memfold + compose (fused) =====================
constexpr int SMEM_UPD = (16384 + 512) * 4;
__global__ void __launch_bounds__(512) update_kernel(
    const float* __restrict__ hidden, const float* __restrict__ Wq,
    const float* __restrict__ bq, const float* __restrict__ Wp,
    const float* __restrict__ bp, float* __restrict__ hid_out)
{
    extern __shared__ float sm[];
    float* memS = sm;             // 4096 (later reused for Told)
    float* T1   = sm + 4096;      // 4096
    float* W2   = sm + 8192;      // 4096 (Wq then WpT)
    float* M2   = sm + 12288;     // 4096
    float* fm   = sm + 16384;     // 64 each below
    float* uS   = fm + 64;
    float* rS   = uS + 64;
    float* d2   = rS + 64;
    float* tS   = d2 + 64;
    float* af   = tS + 64;
    float* bfS  = af + 64;
    int b = blockIdx.x, tid = threadIdx.x;
    if (tid < 64) {
        fm[tid]  = g_fsum[b * 64 + tid] * (1.f / 65536.f);
        tS[tid]  = g_t[b * 64 + tid];
        af[tid]  = g_afold[b * 64 + tid];
        bfS[tid] = g_bfold[b * 64 + tid];
    }
    __syncthreads();
    const float* kb = g_know + b * 4096;
    const float* hb = hidden + (size_t)b * Lnum * 4096;
    float* ho = hid_out + (size_t)b * Lnum * 4096;
    for (int i = tid; i < 4096; i += 512) {
        int c = i >> 6;
        float m = fm[c] * hb[i] + kb[i] * (1.f / 65536.f);
        memS[i] = m; ho[i] = m;
        W2[i] = Wq[i];
    }
    __syncthreads();
    if (tid < 64) {               // uS[c] = bq[c] + sum_e Wq[c][e]*bfold[e]
        const float* wr = W2 + tid * 64;
        float a0 = bq[tid], a1 = 0, a2 = 0, a3 = 0;
#pragma unroll
        for (int e = 0; e < 64; e += 4) {
            a0 += wr[e] * bfS[e];         a1 += wr[e + 1] * bfS[e + 1];
            a2 += wr[e + 2] * bfS[e + 2]; a3 += wr[e + 3] * bfS[e + 3];
        }
        uS[tid] = (a0 + a1) + (a2 + a3);
    }
    __syncthreads();
    if (tid < 64) {               // rS[d] = sum_c memS[c][d]*uS[c]
        float a0 = 0, a1 = 0, a2 = 0, a3 = 0;
#pragma unroll
        for (int c = 0; c < 64; c += 4) {
            a0 += memS[c * 64 + tid] * uS[c];
            a1 += memS[(c + 1) * 64 + tid] * uS[c + 1];
            a2 += memS[(c + 2) * 64 + tid] * uS[c + 2];
            a3 += memS[(c + 3) * 64 + tid] * uS[c + 3];
        }
        rS[tid] = (a0 + a1) + (a2 + a3);
    }
    for (int j = tid; j < 4096; j += 512) {   // T1[d][e] = (mem^T Wq)[d][e]*af[e]
        int d = j >> 6, e = j & 63;
        float a0 = 0, a1 = 0, a2 = 0, a3 = 0;
#pragma unroll
        for (int c = 0; c < 64; c += 4) {
            a0 += memS[c * 64 + d] * W2[c * 64 + e];
            a1 += memS[(c + 1) * 64 + d] * W2[(c + 1) * 64 + e];
            a2 += memS[(c + 2) * 64 + d] * W2[(c + 2) * 64 + e];
            a3 += memS[(c + 3) * 64 + d] * W2[(c + 3) * 64 + e];
        }
        T1[j] = ((a0 + a1) + (a2 + a3)) * af[e];
    }
    __syncthreads();
    for (int i = tid; i < 4096; i += 512)     // W2 <- Wp^T : W2[d][o]=Wp[o][d]
        W2[(i & 63) * 64 + (i >> 6)] = Wp[i];
    __syncthreads();
    const float scale = 0.125f;
    for (int j = tid; j < 4096; j += 512) {   // M2[e*64+o]
        int e = j >> 6, o = j & 63;
        float a0 = 0, a1 = 0, a2 = 0, a3 = 0;
#pragma unroll
        for (int d = 0; d < 64; d += 4) {
            a0 += W2[d * 64 + o] * T1[d * 64 + e];
            a1 += W2[(d + 1) * 64 + o] * T1[(d + 1) * 64 + e];
            a2 += W2[(d + 2) * 64 + o] * T1[(d + 2) * 64 + e];
            a3 += W2[(d + 3) * 64 + o] * T1[(d + 3) * 64 + e];
        }
        M2[j] = ((a0 + a1) + (a2 + a3)) * scale;
    }
    if (tid < 64) {
        float a0 = 0, a1 = 0, a2 = 0, a3 = 0;
#pragma unroll
        for (int d = 0; d < 64; d += 4) {
            a0 += W2[d * 64 + tid] * rS[d];
            a1 += W2[(d + 1) * 64 + tid] * rS[d + 1];
            a2 += W2[(d + 2) * 64 + tid] * rS[d + 2];
            a3 += W2[(d + 3) * 64 + tid] * rS[d + 3];
        }
        d2[tid] = ((a0 + a1) + (a2 + a3)) * scale + bp[tid];
    }
    __syncthreads();
    for (int i = tid; i < 4096; i += 512) memS[i] = g_T[b * 4096 + i];  // Told
    __syncthreads();
    for (int j = tid; j < 4096; j += 512) {   // Tnew = (I+M)Told
        int o = j >> 6, e = j & 63;
        float a0 = memS[o * 64 + e], a1 = 0, a2 = 0, a3 = 0;
#pragma unroll
        for (int m = 0; m < 64; m += 4) {
            a0 += M2[m * 64 + o] * memS[m * 64 + e];
            a1 += M2[(m + 1) * 64 + o] * memS[(m + 1) * 64 + e];
            a2 += M2[(m + 2) * 64 + o] * memS[(m + 2) * 64 + e];
            a3 += M2[(m + 3) * 64 + o] * memS[(m + 3) * 64 + e];
        }
        g_T[b * 4096 + j] = (a0 + a1) + (a2 + a3);
    }
    if (tid < 64) {                           // tnew = t + d2 + M t
        float a0 = tS[tid] + d2[tid], a1 = 0, a2 = 0, a3 = 0;
#pragma unroll
        for (int e = 0; e < 64; e += 4) {
            a0 += M2[e * 64 + tid] * tS[e];
            a1 += M2[(e + 1) * 64 + tid] * tS[e + 1];
            a2 += M2[(e + 2) * 64 + tid] * tS[e + 2];
            a3 += M2[(e + 3) * 64 + tid] * tS[e + 3];
        }
        g_t[b * 64 + tid] = (a0 + a1) + (a2 + a3);
    }
}

// ===================== conv_out prep: fold T4 into W_out =====================
__global__ void __launch_bounds__(256) convout_prep_kernel(
    const float* __restrict__ W, const float* __restrict__ bias)
{
    int b = blockIdx.x, tid = threadIdx.x;
    __shared__ float T[4096];
    for (int i = tid; i < 4096; i += 256) T[i] = g_T[b * 4096 + i];
    __syncthreads();
    for (int j = tid; j < 1152; j += 256) {
        int o = j / 576, r = j % 576, e = r / 9, tap = r % 9;
        float a0 = 0, a1 = 0, a2 = 0, a3 = 0;
#pragma unroll
        for (int c = 0; c < 64; c += 4) {
            a0 += W[o * 576 + c * 9 + tap] * T[c * 64 + e];
            a1 += W[o * 576 + (c + 1) * 9 + tap] * T[(c + 1) * 64 + e];
            a2 += W[o * 576 + (c + 2) * 9 + tap] * T[(c + 2) * 64 + e];
            a3 += W[o * 576 + (c + 3) * 9 + tap] * T[(c + 3) * 64 + e];
        }
        g_Wout[b * 1152 + j] = (a0 + a1) + (a2 + a3);
    }
    if (tid < 18) {   // per-tap t bias
        int o = tid / 9, tap = tid % 9;
        float acc = 0.f;
        for (int c = 0; c < 64; c++)
            acc += W[o * 576 + c * 9 + tap] * g_t[b * 64 + c];
        g_tb[b * 18 + tid] = acc;
    }
    if (tid < 2) g_bout[b * 2 + tid] = bias[tid];
}

// ===================== conv3x3 out + residual (on feat_phys) ============
__global__ void __launch_bounds__(256) conv_out_kernel(
    const float* __restrict__ x, float* __restrict__ out)
{
    __shared__ float fs[8 * 3 * 258];
    __shared__ float ws[1152];
    __shared__ float tb[18];
    int b = blockIdx.y, y = blockIdx.x, tid = threadIdx.x;
    for (int i = tid; i < 1152; i += 256) ws[i] = g_Wout[b * 1152 + i];
    if (tid < 18) tb[tid] = g_tb[b * 18 + tid];
    __syncthreads();
    float acc0 = g_bout[b * 2 + 0], acc1 = g_bout[b * 2 + 1];
#pragma unroll
    for (int r = 0; r < 3; r++) {
        int yy = y + r - 1;
        if (yy < 0 || yy >= 256) continue;
#pragma unroll
        for (int k = 0; k < 3; k++) {
            int xx = tid + k - 1;
            if (xx < 0 || xx >= 256) continue;
            acc0 += tb[r * 3 + k];
            acc1 += tb[9 + r * 3 + k];
        }
    }
    const float* fb = g_feat + (size_t)b * Cc * Np;
    for (int cc = 0; cc < 64; cc += 8) {
        __syncthreads();
        for (int i = tid; i < 6192; i += 256) {
            int c = i / 774, rem = i % 774, r = rem / 258, col = rem % 258;
            int yy = y + r - 1, xx = col - 1;
            float v = 0.f;
            if (yy >= 0 && yy < 256 && xx >= 0 && xx < 256)
                v = fb[(size_t)(cc + c) * Np + yy * 256 + xx];
            fs[i] = v;
        }
        __syncthreads();
#pragma unroll
        for (int c = 0; c < 8; c++) {
            float in[9];
#pragma unroll
            for (int r = 0; r < 3; r++)
#pragma unroll
                for (int k = 0; k < 3; k++)
                    in[r * 3 + k] = fs[c * 774 + r * 258 + tid + k];
            const float* w0 = &ws[(cc + c) * 9];
            const float* w1 = &ws[(64 + cc + c) * 9];
#pragma unroll
            for (int t = 0; t < 9; t++) { acc0 += w0[t] * in[t]; acc1 += w1[t] * in[t]; }
        }
    }
    int o = y * 256 + tid;
    out[(size_t)(b * 2 + 0) * Np + o] = acc0 + x[(size_t)(b * 2 + 0) * Np + o];
    out[(size_t)(b * 2 + 1) * Np + o] = acc1 + x[(size_t)(b * 2 + 1) * Np + o];
}

extern "C" void kernel_launch(void* const* d_in, const int* in_sizes, int n_in,
                              void* d_out, int out_size)
{
    const float* x      = (const float*)d_in[0];
    const float* hidden = (const float*)d_in[1];
    const float* W_in   = (const float*)d_in[2];
    const float* b_in   = (const float*)d_in[3];
    const float* gamma  = (const float*)d_in[4];
    const float* beta   = (const float*)d_in[5];
    const float* Wq     = (const float*)d_in[6];
    const float* bq     = (const float*)d_in[7];
    const float* Wk     = (const float*)d_in[8];
    const float* bk     = (const float*)d_in[9];
    const float* Wv     = (const float*)d_in[10];
    const float* bv     = (const float*)d_in[11];
    const float* Wg     = (const float*)d_in[12];
    const float* bg     = (const float*)d_in[13];
    const float* Wp     = (const float*)d_in[14];
    const float* bp     = (const float*)d_in[15];
    const float* W_out  = (const float*)d_in[16];
    const float* b_out  = (const float*)d_in[17];
    float* out = (float*)d_out;
    float* hid_out = out + 262144;

    cudaFuncSetAttribute(pass2_mma_kernel,
                         cudaFuncAttributeMaxDynamicSharedMemorySize, SMEM_P2);
    cudaFuncSetAttribute(prep_kernel,
                         cudaFuncAttributeMaxDynamicSharedMemorySize, SMEM_PREP);
    cudaFuncSetAttribute(update_kernel,
                         cudaFuncAttributeMaxDynamicSharedMemorySize, SMEM_UPD);

    zero_init_kernel<<<1, 256>>>();
    conv_in_kernel<<<dim3(256, 2), 256>>>(x, W_in, b_in);
    cov_kernel<<<dim3(74, 2), 256>>>();
    for (int l = 0; l < Lnum; l++) {
        prep_kernel<<<2, 512, SMEM_PREP>>>(
            gamma + l * 64, beta + l * 64,
            Wk + l * 4096, bk + l * 64, Wv + l * 4096, bv + l * 64,
            Wg + l * 8192, bg + l * 128);
        pass2_mma_kernel<<<dim3(74, 2), 256, SMEM_P2>>>();
        update_kernel<<<2, 512, SMEM_UPD>>>(
            hidden + l * 4096, Wq + l * 4096, bq + l * 64,
            Wp + l * 4096, bp + l * 64, hid_out + l * 4096);
    }
    convout_prep_kernel<<<2, 256>>>(W_out, b_out);
    conv_out_kernel<<<dim3(256, 2), 256>>>(x, out);
}

// round 9
// speedup vs baseline: 3.2994x; 1.4153x over previous
#include <cuda_runtime.h>
#include <cuda_bf16.h>
#include <cstdint>
#include <cstddef>

constexpr int Cc   = 64;
constexpr int Np   = 65536;
constexpr int Lnum = 4;
constexpr int Bn   = 2;
constexpr int FP   = 72;    // bf16 fragment pitch — conflict-free
constexpr int CP   = 136;   // cov transpose pitch

__device__ float g_feat[(size_t)Bn * Cc * Np];          // fp32, for conv_out
__device__ uint32_t g_featbf[(size_t)Bn * Np * 32];     // bf16 pairs, [b][n][c]
__device__ float g_sum[Bn * 64];
__device__ float g_Cov[Bn * 4096];
__device__ float g_T[Bn * 4096];                        // ping buffer
__device__ float g_T2[Bn * 4096];                       // pong buffer
__device__ float g_t[Bn * 64];
__device__ float g_t2[Bn * 64];
__device__ float g_S1[Bn * 64];
__device__ float g_S2[Bn * 64];
__device__ float g_afold[Bn * 64];
__device__ float g_bfold[Bn * 64];
__device__ float g_know[Bn * 4096];
__device__ float g_fsum[Bn * 64];
__device__ float g_mem[Bn * 4096];
__device__ float g_T1g[Bn * 4096];
__device__ float g_rS[Bn * 64];
__device__ float g_M2[Bn * 4096];
__device__ float g_d2[Bn * 64];
__device__ float g_Weff[Bn * 16384];
__device__ float g_beff[Bn * 256];
__device__ float g_Wout[Bn * 1152];
__device__ float g_tb[Bn * 18];
__device__ float g_bout[Bn * 2];

typedef uint32_t u32;
__device__ __forceinline__ u32 pkbf(float hi, float lo) {
    u32 r; asm("cvt.rn.bf16x2.f32 %0, %1, %2;" : "=r"(r) : "f"(hi), "f"(lo));
    return r;
}
__device__ __forceinline__ float sigm(float x) { return 1.f / (1.f + __expf(-x)); }
__device__ __forceinline__ void mma16816(float c[4], u32 a0, u32 a1, u32 a2,
                                         u32 a3, u32 b0, u32 b1) {
    asm volatile(
        "mma.sync.aligned.m16n8k16.row.col.f32.bf16.bf16.f32 "
        "{%0,%1,%2,%3}, {%4,%5,%6,%7}, {%8,%9}, {%0,%1,%2,%3};"
        : "+f"(c[0]), "+f"(c[1]), "+f"(c[2]), "+f"(c[3])
        : "r"(a0), "r"(a1), "r"(a2), "r"(a3), "r"(b0), "r"(b1));
}

// ===================== init =====================
__global__ void zero_init_kernel() {
    int tid = threadIdx.x;
    for (int i = tid; i < Bn * 4096; i += 256) {
        g_Cov[i] = 0.f;
        g_T[i] = (((i >> 6) & 63) == (i & 63)) ? 1.f : 0.f;
    }
    for (int i = tid; i < Bn * 64; i += 256) { g_sum[i] = 0.f; g_t[i] = 0.f; }
}

// ===================== conv3x3 in: fp32 + bf16 copies ====================
__global__ void __launch_bounds__(256) conv_in_kernel(
    const float* __restrict__ x, const float* __restrict__ W,
    const float* __restrict__ bias)
{
    __shared__ float xs[2 * 3 * 258];
    __shared__ float ws[64 * 18];
    __shared__ float bsh[64];
    int b = blockIdx.y, y = blockIdx.x, tid = threadIdx.x;
    for (int i = tid; i < 64 * 18; i += 256) ws[i] = W[i];
    if (tid < 64) bsh[tid] = bias[tid];
    for (int i = tid; i < 2 * 3 * 258; i += 256) {
        int c = i / 774, rem = i % 774, r = rem / 258, col = rem % 258;
        int yy = y + r - 1, xx = col - 1;
        float v = 0.f;
        if (yy >= 0 && yy < 256 && xx >= 0 && xx < 256)
            v = x[((size_t)(b * 2 + c) * 256 + yy) * 256 + xx];
        xs[i] = v;
    }
    __syncthreads();
    float in[18];
#pragma unroll
    for (int c = 0; c < 2; c++)
#pragma unroll
        for (int r = 0; r < 3; r++)
#pragma unroll
            for (int k = 0; k < 3; k++)
                in[c * 9 + r * 3 + k] = xs[c * 774 + r * 258 + tid + k];
    int n = y * 256 + tid;
    size_t ob = (size_t)b * Cc * Np + n;
    u32* gbf = g_featbf + (size_t)b * Np * 32 + (size_t)n * 32;
#pragma unroll
    for (int oc = 0; oc < 64; oc += 2) {
        float a0 = bsh[oc], a1 = bsh[oc + 1];
#pragma unroll
        for (int t = 0; t < 18; t++) {
            a0 += ws[oc * 18 + t] * in[t];
            a1 += ws[(oc + 1) * 18 + t] * in[t];
        }
        g_feat[ob + (size_t)oc * Np] = a0;
        g_feat[ob + (size_t)(oc + 1) * Np] = a1;
        gbf[oc >> 1] = pkbf(a1, a0);
    }
}

// ===================== Cov = sum feat feat^T ============================
__global__ void __launch_bounds__(256) cov_kernel() {
    __shared__ __nv_bfloat16 Xt[80 * CP];
    int b = blockIdx.y, tid = threadIdx.x;
    int wid = tid >> 5, g = (tid & 31) >> 2, tg = tid & 3;
    for (int i = tid; i < 16 * CP; i += 256) {
        int r = 64 + i / CP;
        Xt[(size_t)(i / CP + 64) * CP + (i % CP)] =
            (r == 64) ? __float2bfloat16(1.f) : __float2bfloat16(0.f);
    }
    float C[8][4];
#pragma unroll
    for (int i = 0; i < 8; i++)
#pragma unroll
        for (int j = 0; j < 4; j++) C[i][j] = 0.f;
    const u32* gbf = g_featbf + (size_t)b * Np * 32;
    for (int t = blockIdx.x; t < 512; t += 74) {
        int n0 = t << 7;
        __syncthreads();
        for (int i = tid; i < 4096; i += 256) {
            int px = i >> 5, w = i & 31;
            u32 v = gbf[(size_t)(n0 + px) * 32 + w];
            __nv_bfloat162 h = *(__nv_bfloat162*)&v;
            Xt[(2 * w) * CP + px] = h.x;
            Xt[(2 * w + 1) * CP + px] = h.y;
        }
        __syncthreads();
        if (wid < 5) {
            int rb = wid * 16;
#pragma unroll
            for (int ks = 0; ks < 8; ks++) {
                int kb2 = ks * 16 + 2 * tg;
                u32 a0 = *(const u32*)&Xt[(rb + g) * CP + kb2];
                u32 a1 = *(const u32*)&Xt[(rb + g + 8) * CP + kb2];
                u32 a2 = *(const u32*)&Xt[(rb + g) * CP + kb2 + 8];
                u32 a3 = *(const u32*)&Xt[(rb + g + 8) * CP + kb2 + 8];
#pragma unroll
                for (int nt = 0; nt < 8; nt++) {
                    u32 b0 = *(const u32*)&Xt[(nt * 8 + g) * CP + kb2];
                    u32 b1 = *(const u32*)&Xt[(nt * 8 + g) * CP + kb2 + 8];
                    mma16816(C[nt], a0, a1, a2, a3, b0, b1);
                }
            }
        }
    }
    if (wid < 4) {
        int c0 = wid * 16 + g;
        float* cb = g_Cov + b * 4096;
#pragma unroll
        for (int nt = 0; nt < 8; nt++) {
            int d = nt * 8 + tg * 2;
            atomicAdd(&cb[c0 * 64 + d], C[nt][0]);
            atomicAdd(&cb[c0 * 64 + d + 1], C[nt][1]);
            atomicAdd(&cb[(c0 + 8) * 64 + d], C[nt][2]);
            atomicAdd(&cb[(c0 + 8) * 64 + d + 1], C[nt][3]);
        }
    } else if (wid == 4 && g == 0) {
#pragma unroll
        for (int nt = 0; nt < 8; nt++) {
            int d = nt * 8 + tg * 2;
            atomicAdd(&g_sum[b * 64 + d], C[nt][0]);
            atomicAdd(&g_sum[b * 64 + d + 1], C[nt][1]);
        }
    }
}

// ===================== prep stage A: quadratic-form stats ================
// grid (8, Bn); block bx computes channels bx*8..+8 (one warp each)
__global__ void __launch_bounds__(256) prep_stats_kernel(int par) {
    const float* Tsrc = par ? g_T2 : g_T;
    const float* tsrc = par ? g_t2 : g_t;
    __shared__ float CovS[4096], Tr[512], sumS[64];
    int b = blockIdx.y, bx = blockIdx.x, tid = threadIdx.x;
    int c0 = bx * 8;
    for (int i = tid; i < 4096; i += 256) CovS[i] = g_Cov[b * 4096 + i];
    for (int i = tid; i < 512; i += 256) Tr[i] = Tsrc[b * 4096 + c0 * 64 + i];
    if (tid < 64) sumS[tid] = g_sum[b * 64 + tid];
    // zero next-layer accumulators (spread over blocks)
    for (int i = tid; i < 512; i += 256) g_know[b * 4096 + bx * 512 + i] = 0.f;
    if (bx == 0 && tid < 64) g_fsum[b * 64 + tid] = 0.f;
    __syncthreads();
    int cl = tid >> 5, lane = tid & 31;
    const float* Tc = Tr + cl * 64;
    float rs = 0.f, qf = 0.f;
#pragma unroll
    for (int eo = 0; eo < 2; eo++) {
        int e = lane + eo * 32;
        float Te = Tc[e];
        rs += Te * sumS[e];
        const float* Ce = CovS + e * 64;
        float i0 = 0, i1 = 0, i2 = 0, i3 = 0;
#pragma unroll
        for (int f = 0; f < 64; f += 4) {
            i0 += Ce[f] * Tc[f];         i1 += Ce[f + 1] * Tc[f + 1];
            i2 += Ce[f + 2] * Tc[f + 2]; i3 += Ce[f + 3] * Tc[f + 3];
        }
        qf += Te * ((i0 + i1) + (i2 + i3));
    }
#pragma unroll
    for (int o = 16; o > 0; o >>= 1) {
        rs += __shfl_xor_sync(~0u, rs, o);
        qf += __shfl_xor_sync(~0u, qf, o);
    }
    if (lane == 0) {
        int c = c0 + cl;
        float tc = tsrc[b * 64 + c];
        g_S1[b * 64 + c] = rs + 65536.f * tc;
        g_S2[b * 64 + c] = qf + 2.f * tc * rs + 65536.f * tc * tc;
    }
}

// ===================== prep stage B: effective weights ===================
// grid (16, Bn): bx -> slice s = bx>>2, quarter q = bx&3 (16 rows)
__global__ void __launch_bounds__(256) prep_weff_kernel(
    int par, const float* __restrict__ gamma, const float* __restrict__ beta,
    const float* __restrict__ Wk, const float* __restrict__ bk,
    const float* __restrict__ Wv, const float* __restrict__ bv,
    const float* __restrict__ Wg, const float* __restrict__ bg)
{
    const float* Tsrc = par ? g_T2 : g_T;
    const float* tsrc = par ? g_t2 : g_t;
    __shared__ float aT[4096], af[64], wvec[64], S1s[64], S2s[64];
    int b = blockIdx.y, bx = blockIdx.x, tid = threadIdx.x;
    int s = bx >> 2, oc0 = (bx & 3) * 16;
    if (tid < 64) { S1s[tid] = g_S1[b * 64 + tid]; S2s[tid] = g_S2[b * 64 + tid]; }
    __syncthreads();
    if (tid < 64) {
        int g = tid >> 3;
        float m = 0.f, q2 = 0.f;
#pragma unroll
        for (int j = 0; j < 8; j++) { m += S1s[g * 8 + j]; q2 += S2s[g * 8 + j]; }
        float inv = 1.f / (8.f * 65536.f);
        m *= inv; q2 *= inv;
        float a = gamma[tid] * rsqrtf(q2 - m * m + 1e-5f);
        float bb = beta[tid] - m * a;
        af[tid] = a;
        wvec[tid] = a * tsrc[b * 64 + tid] + bb;
        if (bx == 0) { g_afold[b * 64 + tid] = a; g_bfold[b * 64 + tid] = bb; }
    }
    __syncthreads();
    for (int i = tid; i < 4096; i += 256) aT[i] = af[i >> 6] * Tsrc[b * 4096 + i];
    __syncthreads();
    const float* Ws = (s == 0) ? Wk : (s == 1) ? Wv : (s == 2) ? Wg : Wg + 4096;
    const float* bs = (s == 0) ? bk : (s == 1) ? bv : (s == 2) ? bg : bg + 64;
#pragma unroll
    for (int r = 0; r < 4; r++) {
        int o = tid + 256 * r;
        int oc = oc0 + (o >> 6), e = o & 63;
        const float* wr = Ws + oc * 64;
        float a0 = 0, a1 = 0, a2 = 0, a3 = 0;
#pragma unroll
        for (int c = 0; c < 64; c += 4) {
            a0 += wr[c]     * aT[c * 64 + e];
            a1 += wr[c + 1] * aT[(c + 1) * 64 + e];
            a2 += wr[c + 2] * aT[(c + 2) * 64 + e];
            a3 += wr[c + 3] * aT[(c + 3) * 64 + e];
        }
        g_Weff[b * 16384 + (s * 64 + oc) * 64 + e] = (a0 + a1) + (a2 + a3);
    }
    if (tid < 16) {
        int oc = oc0 + tid;
        const float* wr = Ws + oc * 64;
        float a0 = bs[oc], a1 = 0, a2 = 0, a3 = 0;
#pragma unroll
        for (int c = 0; c < 64; c += 4) {
            a0 += wr[c] * wvec[c];         a1 += wr[c + 1] * wvec[c + 1];
            a2 += wr[c + 2] * wvec[c + 2]; a3 += wr[c + 3] * wvec[c + 3];
        }
        g_beff[b * 256 + s * 64 + oc] = (a0 + a1) + (a2 + a3);
    }
}

// ===================== pass 2: warp-MMA (in-register gating) =============
constexpr int SM_WHI = 0;
constexpr int SM_WLO = 36864;
constexpr int SM_XS  = 73728;
constexpr int SM_VT  = 92160;
constexpr int SM_KG  = 101376;
constexpr int SM_BIA = 110592;
constexpr int SMEM_P2 = 111616;

__global__ void __launch_bounds__(256, 1) pass2_mma_kernel() {
    extern __shared__ char smc[];
    __nv_bfloat16* WHi = (__nv_bfloat16*)(smc + SM_WHI);
    __nv_bfloat16* WLo = (__nv_bfloat16*)(smc + SM_WLO);
    __nv_bfloat16* Xs  = (__nv_bfloat16*)(smc + SM_XS);
    __nv_bfloat16* Vt  = (__nv_bfloat16*)(smc + SM_VT);
    __nv_bfloat16* Kg  = (__nv_bfloat16*)(smc + SM_KG);
    float* biasS = (float*)(smc + SM_BIA);

    int b = blockIdx.y, tid = threadIdx.x;
    int wid = tid >> 5, g = (tid & 31) >> 2, tg = tid & 3;

    for (int i = tid; i < 16384; i += 256) {
        int oc = i >> 6, c = i & 63;
        float w = g_Weff[b * 16384 + i];
        __nv_bfloat16 h = __float2bfloat16(w);
        WHi[oc * FP + c] = h;
        WLo[oc * FP + c] = __float2bfloat16(w - __bfloat162float(h));
    }
    biasS[tid] = g_beff[b * 256 + tid];

    float Ck[4][4];
#pragma unroll
    for (int i = 0; i < 4; i++)
#pragma unroll
        for (int j = 0; j < 4; j++) Ck[i][j] = 0.f;
    float fpart[2] = {0.f, 0.f};

    const u32* gbf = g_featbf + (size_t)b * Np * 32;
    int mtk = wid >> 1, ntb = (wid & 1) * 4;
    // paired row tiles: warps 0-3: (k, i); warps 4-7: (v, f)
    int rA = (wid < 4) ? wid * 16 : 64 + (wid - 4) * 16;
    int rB = (wid < 4) ? 192 + wid * 16 : 128 + (wid - 4) * 16;
    __syncthreads();

    for (int t = blockIdx.x; t < 512; t += 74) {
        int n0 = t << 7;
        for (int i = tid; i < 4096; i += 256) {
            int px = i >> 5, w = i & 31;
            *(u32*)&Xs[px * FP + 2 * w] = gbf[(size_t)(n0 + px) * 32 + w];
        }
        __syncthreads();

#pragma unroll 1
        for (int h = 0; h < 2; h++) {
            const __nv_bfloat16* Xh = Xs + h * 64 * FP;
            float C[2][8][4];
#pragma unroll
            for (int mt = 0; mt < 2; mt++)
#pragma unroll
                for (int nt = 0; nt < 8; nt++)
#pragma unroll
                    for (int q = 0; q < 4; q++) C[mt][nt][q] = 0.f;
#pragma unroll
            for (int ks = 0; ks < 4; ks++) {
                int kb2 = ks * 16 + 2 * tg;
                u32 bfr[8][2];
#pragma unroll
                for (int nt = 0; nt < 8; nt++) {
                    bfr[nt][0] = *(const u32*)&Xh[(nt * 8 + g) * FP + kb2];
                    bfr[nt][1] = *(const u32*)&Xh[(nt * 8 + g) * FP + kb2 + 8];
                }
#pragma unroll
                for (int mt = 0; mt < 2; mt++) {
                    int r = mt ? rB : rA;
                    u32 h0 = *(const u32*)&WHi[(r + g) * FP + kb2];
                    u32 h1 = *(const u32*)&WHi[(r + g + 8) * FP + kb2];
                    u32 h2 = *(const u32*)&WHi[(r + g) * FP + kb2 + 8];
                    u32 h3 = *(const u32*)&WHi[(r + g + 8) * FP + kb2 + 8];
                    u32 l0 = *(const u32*)&WLo[(r + g) * FP + kb2];
                    u32 l1 = *(const u32*)&WLo[(r + g + 8) * FP + kb2];
                    u32 l2 = *(const u32*)&WLo[(r + g) * FP + kb2 + 8];
                    u32 l3 = *(const u32*)&WLo[(r + g + 8) * FP + kb2 + 8];
#pragma unroll
                    for (int nt = 0; nt < 8; nt++) {
                        mma16816(C[mt][nt], h0, h1, h2, h3, bfr[nt][0], bfr[nt][1]);
                        mma16816(C[mt][nt], l0, l1, l2, l3, bfr[nt][0], bfr[nt][1]);
                    }
                }
            }
            // epilogue: in-register gating
            if (wid < 4) {
                int r0 = rA + g, r1 = r0 + 8;
                float bk0 = biasS[r0], bk1 = biasS[r1];
                float bi0 = biasS[rB + g], bi1 = biasS[rB + g + 8];
#pragma unroll
                for (int nt = 0; nt < 8; nt++) {
                    int col = nt * 8 + tg * 2;
                    *(u32*)&Kg[r0 * FP + col] =
                        pkbf((C[0][nt][1] + bk0) * sigm(C[1][nt][1] + bi0),
                             (C[0][nt][0] + bk0) * sigm(C[1][nt][0] + bi0));
                    *(u32*)&Kg[r1 * FP + col] =
                        pkbf((C[0][nt][3] + bk1) * sigm(C[1][nt][3] + bi1),
                             (C[0][nt][2] + bk1) * sigm(C[1][nt][2] + bi1));
                }
            } else {
                int v0 = rA - 64 + g, v1 = v0 + 8;
                float bv0 = biasS[rA + g], bv1 = biasS[rA + g + 8];
                float bf0 = biasS[rB + g], bf1 = biasS[rB + g + 8];
#pragma unroll
                for (int nt = 0; nt < 8; nt++) {
                    int col = nt * 8 + tg * 2;
                    *(u32*)&Vt[v0 * FP + col] = pkbf(C[0][nt][1] + bv0, C[0][nt][0] + bv0);
                    *(u32*)&Vt[v1 * FP + col] = pkbf(C[0][nt][3] + bv1, C[0][nt][2] + bv1);
                    fpart[0] += sigm(C[1][nt][0] + bf0) + sigm(C[1][nt][1] + bf0);
                    fpart[1] += sigm(C[1][nt][2] + bf1) + sigm(C[1][nt][3] + bf1);
                }
            }
            __syncthreads();
            // knowledge MMA: know[c][d] += Kg[c][px] * Vt[d][px]
#pragma unroll
            for (int ks = 0; ks < 4; ks++) {
                int kb2 = ks * 16 + 2 * tg;
                u32 a0 = *(const u32*)&Kg[(mtk * 16 + g) * FP + kb2];
                u32 a1 = *(const u32*)&Kg[(mtk * 16 + g + 8) * FP + kb2];
                u32 a2 = *(const u32*)&Kg[(mtk * 16 + g) * FP + kb2 + 8];
                u32 a3 = *(const u32*)&Kg[(mtk * 16 + g + 8) * FP + kb2 + 8];
#pragma unroll
                for (int ntl = 0; ntl < 4; ntl++) {
                    u32 b0 = *(const u32*)&Vt[((ntb + ntl) * 8 + g) * FP + kb2];
                    u32 b1 = *(const u32*)&Vt[((ntb + ntl) * 8 + g) * FP + kb2 + 8];
                    mma16816(Ck[ntl], a0, a1, a2, a3, b0, b1);
                }
            }
            __syncthreads();
        }
    }
    float* kbase = g_know + b * 4096;
#pragma unroll
    for (int ntl = 0; ntl < 4; ntl++) {
        int c0 = mtk * 16 + g, d0 = (ntb + ntl) * 8 + tg * 2;
        atomicAdd(&kbase[c0 * 64 + d0],           Ck[ntl][0]);
        atomicAdd(&kbase[c0 * 64 + d0 + 1],       Ck[ntl][1]);
        atomicAdd(&kbase[(c0 + 8) * 64 + d0],     Ck[ntl][2]);
        atomicAdd(&kbase[(c0 + 8) * 64 + d0 + 1], Ck[ntl][3]);
    }
    if (wid >= 4) {
#pragma unroll
        for (int s = 0; s < 2; s++) {
            float v = fpart[s];
            v += __shfl_xor_sync(0xffffffffu, v, 1);
            v += __shfl_xor_sync(0xffffffffu, v, 2);
            if (tg == 0)
                atomicAdd(&g_fsum[b * 64 + (wid - 4) * 16 + g + s * 8], v);
        }
    }
}

// ===================== update chain (wide grids) ========================
// upd1: mem = fm*hidden + know/N ; uS, rS.  grid (Bn), 512 thr.
__global__ void __launch_bounds__(512) upd1_kernel(
    const float* __restrict__ hidden, const float* __restrict__ Wq,
    const float* __restrict__ bq, float* __restrict__ hid_out)
{
    __shared__ float memS[4096], fm[64], bf[64], uS[64];
    int b = blockIdx.x, tid = threadIdx.x;
    if (tid < 64) {
        fm[tid] = g_fsum[b * 64 + tid] * (1.f / 65536.f);
        bf[tid] = g_bfold[b * 64 + tid];
    }
    __syncthreads();
    const float* kb = g_know + b * 4096;
    const float* hb = hidden + (size_t)b * Lnum * 4096;
    float* ho = hid_out + (size_t)b * Lnum * 4096;
    for (int i = tid; i < 4096; i += 512) {
        int c = i >> 6;
        float m = fm[c] * hb[i] + kb[i] * (1.f / 65536.f);
        memS[i] = m; g_mem[b * 4096 + i] = m; ho[i] = m;
    }
    if (tid < 64) {
        const float* wr = Wq + tid * 64;
        float a0 = bq[tid], a1 = 0, a2 = 0, a3 = 0;
#pragma unroll
        for (int e = 0; e < 64; e += 4) {
            a0 += wr[e] * bf[e];         a1 += wr[e + 1] * bf[e + 1];
            a2 += wr[e + 2] * bf[e + 2]; a3 += wr[e + 3] * bf[e + 3];
        }
        uS[tid] = (a0 + a1) + (a2 + a3);
    }
    __syncthreads();
    if (tid < 64) {
        float a0 = 0, a1 = 0, a2 = 0, a3 = 0;
#pragma unroll
        for (int c = 0; c < 64; c += 4) {
            a0 += memS[c * 64 + tid] * uS[c];
            a1 += memS[(c + 1) * 64 + tid] * uS[c + 1];
            a2 += memS[(c + 2) * 64 + tid] * uS[c + 2];
            a3 += memS[(c + 3) * 64 + tid] * uS[c + 3];
        }
        g_rS[b * 64 + tid] = (a0 + a1) + (a2 + a3);
    }
}

// upd2: T1[d][e] = (mem^T Wq)[d][e]*af[e].  grid (8, Bn), 256 thr.
__global__ void __launch_bounds__(256) upd2_kernel(const float* __restrict__ Wq) {
    __shared__ float memS[4096], WqS[4096], af[64];
    int b = blockIdx.y, d0 = blockIdx.x * 8, tid = threadIdx.x;
    for (int i = tid; i < 4096; i += 256) {
        memS[i] = g_mem[b * 4096 + i];
        WqS[i] = Wq[i];
    }
    if (tid < 64) af[tid] = g_afold[b * 64 + tid];
    __syncthreads();
#pragma unroll
    for (int r = 0; r < 2; r++) {
        int o = tid + 256 * r;
        int d = d0 + (o >> 6), e = o & 63;
        float a0 = 0, a1 = 0, a2 = 0, a3 = 0;
#pragma unroll
        for (int c = 0; c < 64; c += 4) {
            a0 += memS[c * 64 + d] * WqS[c * 64 + e];
            a1 += memS[(c + 1) * 64 + d] * WqS[(c + 1) * 64 + e];
            a2 += memS[(c + 2) * 64 + d] * WqS[(c + 2) * 64 + e];
            a3 += memS[(c + 3) * 64 + d] * WqS[(c + 3) * 64 + e];
        }
        g_T1g[b * 4096 + d * 64 + e] = ((a0 + a1) + (a2 + a3)) * af[e];
    }
}

// upd3: M2[e*64+o] = scale * sum_d Wp[o][d]*T1[d][e]; d2.  grid (8, Bn).
__global__ void __launch_bounds__(256) upd3_kernel(
    const float* __restrict__ Wp, const float* __restrict__ bp)
{
    __shared__ float T1S[4096];
    int b = blockIdx.y, e0 = blockIdx.x * 8, tid = threadIdx.x;
    for (int i = tid; i < 4096; i += 256) T1S[i] = g_T1g[b * 4096 + i];
    __syncthreads();
    const float scale = 0.125f;
#pragma unroll
    for (int r = 0; r < 2; r++) {
        int idx = tid + 256 * r;
        int e = e0 + (idx >> 6), o = idx & 63;
        const float* wr = Wp + o * 64;
        float a0 = 0, a1 = 0, a2 = 0, a3 = 0;
#pragma unroll
        for (int d = 0; d < 64; d += 4) {
            a0 += wr[d] * T1S[d * 64 + e];
            a1 += wr[d + 1] * T1S[(d + 1) * 64 + e];
            a2 += wr[d + 2] * T1S[(d + 2) * 64 + e];
            a3 += wr[d + 3] * T1S[(d + 3) * 64 + e];
        }
        g_M2[b * 4096 + e * 64 + o] = ((a0 + a1) + (a2 + a3)) * scale;
    }
    if (blockIdx.x == 0 && tid < 64) {
        const float* wr = Wp + tid * 64;
        float a0 = 0, a1 = 0, a2 = 0, a3 = 0;
#pragma unroll
        for (int d = 0; d < 64; d += 4) {
            a0 += wr[d] * g_rS[b * 64 + d];
            a1 += wr[d + 1] * g_rS[b * 64 + d + 1];
            a2 += wr[d + 2] * g_rS[b * 64 + d + 2];
            a3 += wr[d + 3] * g_rS[b * 64 + d + 3];
        }
        g_d2[b * 64 + tid] = ((a0 + a1) + (a2 + a3)) * scale + bp[tid];
    }
}

// upd4: Tnew = (I+M)Told, tnew = t + d2 + M t.  grid (8, Bn). ping-pong.
__global__ void __launch_bounds__(256) upd4_kernel(int par) {
    const float* Tsrc = par ? g_T2 : g_T;
    float* Tdst       = par ? g_T  : g_T2;
    const float* tsrc = par ? g_t2 : g_t;
    float* tdst       = par ? g_t  : g_t2;
    __shared__ float ToldS[4096], M2S[4096];
    int b = blockIdx.y, o0 = blockIdx.x * 8, tid = threadIdx.x;
    for (int i = tid; i < 4096; i += 256) {
        ToldS[i] = Tsrc[b * 4096 + i];
        M2S[i] = g_M2[b * 4096 + i];
    }
    __syncthreads();
#pragma unroll
    for (int r = 0; r < 2; r++) {
        int idx = tid + 256 * r;
        int o = o0 + (idx >> 6), e = idx & 63;
        float a0 = ToldS[o * 64 + e], a1 = 0, a2 = 0, a3 = 0;
#pragma unroll
        for (int m = 0; m < 64; m += 4) {
            a0 += M2S[m * 64 + o] * ToldS[m * 64 + e];
            a1 += M2S[(m + 1) * 64 + o] * ToldS[(m + 1) * 64 + e];
            a2 += M2S[(m + 2) * 64 + o] * ToldS[(m + 2) * 64 + e];
            a3 += M2S[(m + 3) * 64 + o] * ToldS[(m + 3) * 64 + e];
        }
        Tdst[b * 4096 + o * 64 + e] = (a0 + a1) + (a2 + a3);
    }
    if (blockIdx.x == 0 && tid < 64) {
        float a0 = tsrc[b * 64 + tid] + g_d2[b * 64 + tid], a1 = 0, a2 = 0, a3 = 0;
#pragma unroll
        for (int e = 0; e < 64; e += 4) {
            a0 += M2S[e * 64 + tid] * tsrc[b * 64 + e];
            a1 += M2S[(e + 1) * 64 + tid] * tsrc[b * 64 + e + 1];
            a2 += M2S[(e + 2) * 64 + tid] * tsrc[b * 64 + e + 2];
            a3 += M2S[(e + 3) * 64 + tid] * tsrc[b * 64 + e + 3];
        }
        tdst[b * 64 + tid] = (a0 + a1) + (a2 + a3);
    }
}

// ===================== conv_out prep + conv_out =========================
__global__ void __launch_bounds__(256) convout_prep_kernel(
    const float* __restrict__ W, const float* __restrict__ bias)
{
    int b = blockIdx.x, tid = threadIdx.x;
    __shared__ float T[4096];
    for (int i = tid; i < 4096; i += 256) T[i] = g_T[b * 4096 + i];
    __syncthreads();
    for (int j = tid; j < 1152; j += 256) {
        int o = j / 576, r = j % 576, e = r / 9, tap = r % 9;
        float a0 = 0, a1 = 0, a2 = 0, a3 = 0;
#pragma unroll
        for (int c = 0; c < 64; c += 4) {
            a0 += W[o * 576 + c * 9 + tap] * T[c * 64 + e];
            a1 += W[o * 576 + (c + 1) * 9 + tap] * T[(c + 1) * 64 + e];
            a2 += W[o * 576 + (c + 2) * 9 + tap] * T[(c + 2) * 64 + e];
            a3 += W[o * 576 + (c + 3) * 9 + tap] * T[(c + 3) * 64 + e];
        }
        g_Wout[b * 1152 + j] = (a0 + a1) + (a2 + a3);
    }
    if (tid < 18) {
        int o = tid / 9, tap = tid % 9;
        float acc = 0.f;
        for (int c = 0; c < 64; c++)
            acc += W[o * 576 + c * 9 + tap] * g_t[b * 64 + c];
        g_tb[b * 18 + tid] = acc;
    }
    if (tid < 2) g_bout[b * 2 + tid] = bias[tid];
}

__global__ void __launch_bounds__(256) conv_out_kernel(
    const float* __restrict__ x, float* __restrict__ out)
{
    __shared__ float fs[8 * 3 * 258];
    __shared__ float ws[1152];
    __shared__ float tb[18];
    int b = blockIdx.y, y = blockIdx.x, tid = threadIdx.x;
    for (int i = tid; i < 1152; i += 256) ws[i] = g_Wout[b * 1152 + i];
    if (tid < 18) tb[tid] = g_tb[b * 18 + tid];
    __syncthreads();
    float acc0 = g_bout[b * 2 + 0], acc1 = g_bout[b * 2 + 1];
#pragma unroll
    for (int r = 0; r < 3; r++) {
        int yy = y + r - 1;
        if (yy < 0 || yy >= 256) continue;
#pragma unroll
        for (int k = 0; k < 3; k++) {
            int xx = tid + k - 1;
            if (xx < 0 || xx >= 256) continue;
            acc0 += tb[r * 3 + k];
            acc1 += tb[9 + r * 3 + k];
        }
    }
    const float* fb = g_feat + (size_t)b * Cc * Np;
    for (int cc = 0; cc < 64; cc += 8) {
        __syncthreads();
        for (int i = tid; i < 6192; i += 256) {
            int c = i / 774, rem = i % 774, r = rem / 258, col = rem % 258;
            int yy = y + r - 1, xx = col - 1;
            float v = 0.f;
            if (yy >= 0 && yy < 256 && xx >= 0 && xx < 256)
                v = fb[(size_t)(cc + c) * Np + yy * 256 + xx];
            fs[i] = v;
        }
        __syncthreads();
#pragma unroll
        for (int c = 0; c < 8; c++) {
            float in[9];
#pragma unroll
            for (int r = 0; r < 3; r++)
#pragma unroll
                for (int k = 0; k < 3; k++)
                    in[r * 3 + k] = fs[c * 774 + r * 258 + tid + k];
            const float* w0 = &ws[(cc + c) * 9];
            const float* w1 = &ws[(64 + cc + c) * 9];
#pragma unroll
            for (int t = 0; t < 9; t++) { acc0 += w0[t] * in[t]; acc1 += w1[t] * in[t]; }
        }
    }
    int o = y * 256 + tid;
    out[(size_t)(b * 2 + 0) * Np + o] = acc0 + x[(size_t)(b * 2 + 0) * Np + o];
    out[(size_t)(b * 2 + 1) * Np + o] = acc1 + x[(size_t)(b * 2 + 1) * Np + o];
}

extern "C" void kernel_launch(void* const* d_in, const int* in_sizes, int n_in,
                              void* d_out, int out_size)
{
    const float* x      = (const float*)d_in[0];
    const float* hidden = (const float*)d_in[1];
    const float* W_in   = (const float*)d_in[2];
    const float* b_in   = (const float*)d_in[3];
    const float* gamma  = (const float*)d_in[4];
    const float* beta   = (const float*)d_in[5];
    const float* Wq     = (const float*)d_in[6];
    const float* bq     = (const float*)d_in[7];
    const float* Wk     = (const float*)d_in[8];
    const float* bk     = (const float*)d_in[9];
    const float* Wv     = (const float*)d_in[10];
    const float* bv     = (const float*)d_in[11];
    const float* Wg     = (const float*)d_in[12];
    const float* bg     = (const float*)d_in[13];
    const float* Wp     = (const float*)d_in[14];
    const float* bp     = (const float*)d_in[15];
    const float* W_out  = (const float*)d_in[16];
    const float* b_out  = (const float*)d_in[17];
    float* out = (float*)d_out;
    float* hid_out = out + 262144;

    cudaFuncSetAttribute(pass2_mma_kernel,
                         cudaFuncAttributeMaxDynamicSharedMemorySize, SMEM_P2);

    zero_init_kernel<<<1, 256>>>();
    conv_in_kernel<<<dim3(256, 2), 256>>>(x, W_in, b_in);
    cov_kernel<<<dim3(74, 2), 256>>>();
    for (int l = 0; l < Lnum; l++) {
        int par = l & 1;
        prep_stats_kernel<<<dim3(8, 2), 256>>>(par);
        prep_weff_kernel<<<dim3(16, 2), 256>>>(
            par, gamma + l * 64, beta + l * 64,
            Wk + l * 4096, bk + l * 64, Wv + l * 4096, bv + l * 64,
            Wg + l * 8192, bg + l * 128);
        pass2_mma_kernel<<<dim3(74, 2), 256, SMEM_P2>>>();
        upd1_kernel<<<2, 512>>>(hidden + l * 4096, Wq + l * 4096, bq + l * 64,
                                hid_out + l * 4096);
        upd2_kernel<<<dim3(8, 2), 256>>>(Wq + l * 4096);
        upd3_kernel<<<dim3(8, 2), 256>>>(Wp + l * 4096, bp + l * 64);
        upd4_kernel<<<dim3(8, 2), 256>>>(par);
    }
    convout_prep_kernel<<<2, 256>>>(W_out, b_out);
    conv_out_kernel<<<dim3(256, 2), 256>>>(x, out);
}

// round 13
// speedup vs baseline: 3.6719x; 1.1129x over previous
#include <cuda_runtime.h>
#include <cuda_bf16.h>
#include <cstdint>
#include <cstddef>

constexpr int Cc   = 64;
constexpr int Np   = 65536;
constexpr int Lnum = 4;
constexpr int Bn   = 2;
constexpr int FP   = 72;    // bf16 fragment pitch — conflict-free
constexpr int CP   = 136;   // cov transpose pitch

__device__ float g_feat[(size_t)Bn * Cc * Np];          // fp32, for conv_out
__device__ uint32_t g_featbf[(size_t)Bn * Np * 32];     // bf16 pairs, [b][n][c]
__device__ float g_sum[Bn * 64];
__device__ float g_Cov[Bn * 4096];
__device__ float g_T[Bn * 4096];                        // ping buffer
__device__ float g_T2[Bn * 4096];                       // pong buffer
__device__ float g_t[Bn * 64];
__device__ float g_t2[Bn * 64];
__device__ float g_S1[Bn * 64];
__device__ float g_S2[Bn * 64];
__device__ float g_afold[Bn * 64];
__device__ float g_bfold[Bn * 64];
__device__ float g_know[Bn * 4096];
__device__ float g_fsum[Bn * 64];
__device__ float g_M2[Bn * 4096];
__device__ float g_d2[Bn * 64];
__device__ float g_Weff[Bn * 16384];
__device__ float g_beff[Bn * 256];
__device__ float g_Wout[Bn * 1152];
__device__ float g_tb[Bn * 18];
__device__ float g_bout[Bn * 2];

typedef uint32_t u32;
__device__ __forceinline__ u32 pkbf(float hi, float lo) {
    u32 r; asm("cvt.rn.bf16x2.f32 %0, %1, %2;" : "=r"(r) : "f"(hi), "f"(lo));
    return r;
}
__device__ __forceinline__ float sigm(float x) { return 1.f / (1.f + __expf(-x)); }
__device__ __forceinline__ void mma16816(float c[4], u32 a0, u32 a1, u32 a2,
                                         u32 a3, u32 b0, u32 b1) {
    asm volatile(
        "mma.sync.aligned.m16n8k16.row.col.f32.bf16.bf16.f32 "
        "{%0,%1,%2,%3}, {%4,%5,%6,%7}, {%8,%9}, {%0,%1,%2,%3};"
        : "+f"(c[0]), "+f"(c[1]), "+f"(c[2]), "+f"(c[3])
        : "r"(a0), "r"(a1), "r"(a2), "r"(a3), "r"(b0), "r"(b1));
}

// ===================== init =====================
__global__ void zero_init_kernel() {
    int tid = threadIdx.x;
    for (int i = tid; i < Bn * 4096; i += 256) {
        g_Cov[i] = 0.f;
        g_T[i] = (((i >> 6) & 63) == (i & 63)) ? 1.f : 0.f;
    }
    for (int i = tid; i < Bn * 64; i += 256) { g_sum[i] = 0.f; g_t[i] = 0.f; }
}

// ===================== conv3x3 in: fp32 + bf16 copies ====================
__global__ void __launch_bounds__(256) conv_in_kernel(
    const float* __restrict__ x, const float* __restrict__ W,
    const float* __restrict__ bias)
{
    __shared__ float xs[2 * 3 * 258];
    __shared__ float ws[64 * 18];
    __shared__ float bsh[64];
    int b = blockIdx.y, y = blockIdx.x, tid = threadIdx.x;
    for (int i = tid; i < 64 * 18; i += 256) ws[i] = W[i];
    if (tid < 64) bsh[tid] = bias[tid];
    for (int i = tid; i < 2 * 3 * 258; i += 256) {
        int c = i / 774, rem = i % 774, r = rem / 258, col = rem % 258;
        int yy = y + r - 1, xx = col - 1;
        float v = 0.f;
        if (yy >= 0 && yy < 256 && xx >= 0 && xx < 256)
            v = x[((size_t)(b * 2 + c) * 256 + yy) * 256 + xx];
        xs[i] = v;
    }
    __syncthreads();
    float in[18];
#pragma unroll
    for (int c = 0; c < 2; c++)
#pragma unroll
        for (int r = 0; r < 3; r++)
#pragma unroll
            for (int k = 0; k < 3; k++)
                in[c * 9 + r * 3 + k] = xs[c * 774 + r * 258 + tid + k];
    int n = y * 256 + tid;
    size_t ob = (size_t)b * Cc * Np + n;
    u32* gbf = g_featbf + (size_t)b * Np * 32 + (size_t)n * 32;
#pragma unroll
    for (int oc = 0; oc < 64; oc += 2) {
        float a0 = bsh[oc], a1 = bsh[oc + 1];
#pragma unroll
        for (int t = 0; t < 18; t++) {
            a0 += ws[oc * 18 + t] * in[t];
            a1 += ws[(oc + 1) * 18 + t] * in[t];
        }
        g_feat[ob + (size_t)oc * Np] = a0;
        g_feat[ob + (size_t)(oc + 1) * Np] = a1;
        gbf[oc >> 1] = pkbf(a1, a0);
    }
}

// ===================== Cov = sum feat feat^T ============================
__global__ void __launch_bounds__(256) cov_kernel() {
    __shared__ __nv_bfloat16 Xt[80 * CP];
    int b = blockIdx.y, tid = threadIdx.x;
    int wid = tid >> 5, g = (tid & 31) >> 2, tg = tid & 3;
    for (int i = tid; i < 16 * CP; i += 256) {
        int r = 64 + i / CP;
        Xt[(size_t)(i / CP + 64) * CP + (i % CP)] =
            (r == 64) ? __float2bfloat16(1.f) : __float2bfloat16(0.f);
    }
    float C[8][4];
#pragma unroll
    for (int i = 0; i < 8; i++)
#pragma unroll
        for (int j = 0; j < 4; j++) C[i][j] = 0.f;
    const u32* gbf = g_featbf + (size_t)b * Np * 32;
    for (int t = blockIdx.x; t < 512; t += 74) {
        int n0 = t << 7;
        __syncthreads();
        for (int i = tid; i < 4096; i += 256) {
            int px = i >> 5, w = i & 31;
            u32 v = gbf[(size_t)(n0 + px) * 32 + w];
            __nv_bfloat162 h = *(__nv_bfloat162*)&v;
            Xt[(2 * w) * CP + px] = h.x;
            Xt[(2 * w + 1) * CP + px] = h.y;
        }
        __syncthreads();
        if (wid < 5) {
            int rb = wid * 16;
#pragma unroll
            for (int ks = 0; ks < 8; ks++) {
                int kb2 = ks * 16 + 2 * tg;
                u32 a0 = *(const u32*)&Xt[(rb + g) * CP + kb2];
                u32 a1 = *(const u32*)&Xt[(rb + g + 8) * CP + kb2];
                u32 a2 = *(const u32*)&Xt[(rb + g) * CP + kb2 + 8];
                u32 a3 = *(const u32*)&Xt[(rb + g + 8) * CP + kb2 + 8];
#pragma unroll
                for (int nt = 0; nt < 8; nt++) {
                    u32 b0 = *(const u32*)&Xt[(nt * 8 + g) * CP + kb2];
                    u32 b1 = *(const u32*)&Xt[(nt * 8 + g) * CP + kb2 + 8];
                    mma16816(C[nt], a0, a1, a2, a3, b0, b1);
                }
            }
        }
    }
    if (wid < 4) {
        int c0 = wid * 16 + g;
        float* cb = g_Cov + b * 4096;
#pragma unroll
        for (int nt = 0; nt < 8; nt++) {
            int d = nt * 8 + tg * 2;
            atomicAdd(&cb[c0 * 64 + d], C[nt][0]);
            atomicAdd(&cb[c0 * 64 + d + 1], C[nt][1]);
            atomicAdd(&cb[(c0 + 8) * 64 + d], C[nt][2]);
            atomicAdd(&cb[(c0 + 8) * 64 + d + 1], C[nt][3]);
        }
    } else if (wid == 4 && g == 0) {
#pragma unroll
        for (int nt = 0; nt < 8; nt++) {
            int d = nt * 8 + tg * 2;
            atomicAdd(&g_sum[b * 64 + d], C[nt][0]);
            atomicAdd(&g_sum[b * 64 + d + 1], C[nt][1]);
        }
    }
}

// ===================== layer-0 stats (standalone) ========================
__global__ void __launch_bounds__(256) prep_stats_kernel() {
    __shared__ float CovS[4096], Tr[512], sumS[64];
    int b = blockIdx.y, bx = blockIdx.x, tid = threadIdx.x;
    int c0 = bx * 8;
    for (int i = tid; i < 4096; i += 256) CovS[i] = g_Cov[b * 4096 + i];
    for (int i = tid; i < 512; i += 256) Tr[i] = g_T[b * 4096 + c0 * 64 + i];
    if (tid < 64) sumS[tid] = g_sum[b * 64 + tid];
    for (int i = tid; i < 512; i += 256) g_know[b * 4096 + bx * 512 + i] = 0.f;
    if (bx == 0 && tid < 64) g_fsum[b * 64 + tid] = 0.f;
    __syncthreads();
    int cl = tid >> 5, lane = tid & 31;
    const float* Tc = Tr + cl * 64;
    float rs = 0.f, qf = 0.f;
#pragma unroll
    for (int eo = 0; eo < 2; eo++) {
        int e = lane + eo * 32;
        float Te = Tc[e];
        rs += Te * sumS[e];
        const float* Ce = CovS + e * 64;
        float i0 = 0, i1 = 0, i2 = 0, i3 = 0;
#pragma unroll
        for (int f = 0; f < 64; f += 4) {
            i0 += Ce[f] * Tc[f];         i1 += Ce[f + 1] * Tc[f + 1];
            i2 += Ce[f + 2] * Tc[f + 2]; i3 += Ce[f + 3] * Tc[f + 3];
        }
        qf += Te * ((i0 + i1) + (i2 + i3));
    }
#pragma unroll
    for (int o = 16; o > 0; o >>= 1) {
        rs += __shfl_xor_sync(~0u, rs, o);
        qf += __shfl_xor_sync(~0u, qf, o);
    }
    if (lane == 0) {
        int c = c0 + cl;
        float tc = g_t[b * 64 + c];
        g_S1[b * 64 + c] = rs + 65536.f * tc;
        g_S2[b * 64 + c] = qf + 2.f * tc * rs + 65536.f * tc * tc;
    }
}

// ===================== effective weights =================================
__global__ void __launch_bounds__(256) prep_weff_kernel(
    int par, const float* __restrict__ gamma, const float* __restrict__ beta,
    const float* __restrict__ Wk, const float* __restrict__ bk,
    const float* __restrict__ Wv, const float* __restrict__ bv,
    const float* __restrict__ Wg, const float* __restrict__ bg)
{
    const float* Tsrc = par ? g_T2 : g_T;
    const float* tsrc = par ? g_t2 : g_t;
    __shared__ float aT[4096], af[64], wvec[64], S1s[64], S2s[64];
    int b = blockIdx.y, bx = blockIdx.x, tid = threadIdx.x;
    int s = bx >> 2, oc0 = (bx & 3) * 16;
    if (tid < 64) { S1s[tid] = g_S1[b * 64 + tid]; S2s[tid] = g_S2[b * 64 + tid]; }
    __syncthreads();
    if (tid < 64) {
        int g = tid >> 3;
        float m = 0.f, q2 = 0.f;
#pragma unroll
        for (int j = 0; j < 8; j++) { m += S1s[g * 8 + j]; q2 += S2s[g * 8 + j]; }
        float inv = 1.f / (8.f * 65536.f);
        m *= inv; q2 *= inv;
        float a = gamma[tid] * rsqrtf(q2 - m * m + 1e-5f);
        float bb = beta[tid] - m * a;
        af[tid] = a;
        wvec[tid] = a * tsrc[b * 64 + tid] + bb;
        if (bx == 0) { g_afold[b * 64 + tid] = a; g_bfold[b * 64 + tid] = bb; }
    }
    __syncthreads();
    for (int i = tid; i < 4096; i += 256) aT[i] = af[i >> 6] * Tsrc[b * 4096 + i];
    __syncthreads();
    const float* Ws = (s == 0) ? Wk : (s == 1) ? Wv : (s == 2) ? Wg : Wg + 4096;
    const float* bs = (s == 0) ? bk : (s == 1) ? bv : (s == 2) ? bg : bg + 64;
#pragma unroll
    for (int r = 0; r < 4; r++) {
        int o = tid + 256 * r;
        int oc = oc0 + (o >> 6), e = o & 63;
        const float* wr = Ws + oc * 64;
        float a0 = 0, a1 = 0, a2 = 0, a3 = 0;
#pragma unroll
        for (int c = 0; c < 64; c += 4) {
            a0 += wr[c]     * aT[c * 64 + e];
            a1 += wr[c + 1] * aT[(c + 1) * 64 + e];
            a2 += wr[c + 2] * aT[(c + 2) * 64 + e];
            a3 += wr[c + 3] * aT[(c + 3) * 64 + e];
        }
        g_Weff[b * 16384 + (s * 64 + oc) * 64 + e] = (a0 + a1) + (a2 + a3);
    }
    if (tid < 16) {
        int oc = oc0 + tid;
        const float* wr = Ws + oc * 64;
        float a0 = bs[oc], a1 = 0, a2 = 0, a3 = 0;
#pragma unroll
        for (int c = 0; c < 64; c += 4) {
            a0 += wr[c] * wvec[c];         a1 += wr[c + 1] * wvec[c + 1];
            a2 += wr[c + 2] * wvec[c + 2]; a3 += wr[c + 3] * wvec[c + 3];
        }
        g_beff[b * 256 + s * 64 + oc] = (a0 + a1) + (a2 + a3);
    }
}

// ===================== pass 2: warp-MMA (in-register gating) =============
constexpr int SM_WHI = 0;
constexpr int SM_WLO = 36864;
constexpr int SM_XS  = 73728;
constexpr int SM_VT  = 92160;
constexpr int SM_KG  = 101376;
constexpr int SM_BIA = 110592;
constexpr int SMEM_P2 = 111616;

__global__ void __launch_bounds__(256, 1) pass2_mma_kernel() {
    extern __shared__ char smc[];
    __nv_bfloat16* WHi = (__nv_bfloat16*)(smc + SM_WHI);
    __nv_bfloat16* WLo = (__nv_bfloat16*)(smc + SM_WLO);
    __nv_bfloat16* Xs  = (__nv_bfloat16*)(smc + SM_XS);
    __nv_bfloat16* Vt  = (__nv_bfloat16*)(smc + SM_VT);
    __nv_bfloat16* Kg  = (__nv_bfloat16*)(smc + SM_KG);
    float* biasS = (float*)(smc + SM_BIA);

    int b = blockIdx.y, tid = threadIdx.x;
    int wid = tid >> 5, g = (tid & 31) >> 2, tg = tid & 3;

    for (int i = tid; i < 16384; i += 256) {
        int oc = i >> 6, c = i & 63;
        float w = g_Weff[b * 16384 + i];
        __nv_bfloat16 h = __float2bfloat16(w);
        WHi[oc * FP + c] = h;
        WLo[oc * FP + c] = __float2bfloat16(w - __bfloat162float(h));
    }
    biasS[tid] = g_beff[b * 256 + tid];

    float Ck[4][4];
#pragma unroll
    for (int i = 0; i < 4; i++)
#pragma unroll
        for (int j = 0; j < 4; j++) Ck[i][j] = 0.f;
    float fpart[2] = {0.f, 0.f};

    const u32* gbf = g_featbf + (size_t)b * Np * 32;
    int mtk = wid >> 1, ntb = (wid & 1) * 4;
    int rA = (wid < 4) ? wid * 16 : 64 + (wid - 4) * 16;
    int rB = (wid < 4) ? 192 + wid * 16 : 128 + (wid - 4) * 16;
    __syncthreads();

    for (int t = blockIdx.x; t < 512; t += 74) {
        int n0 = t << 7;
        for (int i = tid; i < 4096; i += 256) {
            int px = i >> 5, w = i & 31;
            *(u32*)&Xs[px * FP + 2 * w] = gbf[(size_t)(n0 + px) * 32 + w];
        }
        __syncthreads();

#pragma unroll 1
        for (int h = 0; h < 2; h++) {
            const __nv_bfloat16* Xh = Xs + h * 64 * FP;
            float C[2][8][4];
#pragma unroll
            for (int mt = 0; mt < 2; mt++)
#pragma unroll
                for (int nt = 0; nt < 8; nt++)
#pragma unroll
                    for (int q = 0; q < 4; q++) C[mt][nt][q] = 0.f;
#pragma unroll
            for (int ks = 0; ks < 4; ks++) {
                int kb2 = ks * 16 + 2 * tg;
                u32 bfr[8][2];
#pragma unroll
                for (int nt = 0; nt < 8; nt++) {
                    bfr[nt][0] = *(const u32*)&Xh[(nt * 8 + g) * FP + kb2];
                    bfr[nt][1] = *(const u32*)&Xh[(nt * 8 + g) * FP + kb2 + 8];
                }
#pragma unroll
                for (int mt = 0; mt < 2; mt++) {
                    int r = mt ? rB : rA;
                    u32 h0 = *(const u32*)&WHi[(r + g) * FP + kb2];
                    u32 h1 = *(const u32*)&WHi[(r + g + 8) * FP + kb2];
                    u32 h2 = *(const u32*)&WHi[(r + g) * FP + kb2 + 8];
                    u32 h3 = *(const u32*)&WHi[(r + g + 8) * FP + kb2 + 8];
                    u32 l0 = *(const u32*)&WLo[(r + g) * FP + kb2];
                    u32 l1 = *(const u32*)&WLo[(r + g + 8) * FP + kb2];
                    u32 l2 = *(const u32*)&WLo[(r + g) * FP + kb2 + 8];
                    u32 l3 = *(const u32*)&WLo[(r + g + 8) * FP + kb2 + 8];
#pragma unroll
                    for (int nt = 0; nt < 8; nt++) {
                        mma16816(C[mt][nt], h0, h1, h2, h3, bfr[nt][0], bfr[nt][1]);
                        mma16816(C[mt][nt], l0, l1, l2, l3, bfr[nt][0], bfr[nt][1]);
                    }
                }
            }
            if (wid < 4) {
                int r0 = rA + g, r1 = r0 + 8;
                float bk0 = biasS[r0], bk1 = biasS[r1];
                float bi0 = biasS[rB + g], bi1 = biasS[rB + g + 8];
#pragma unroll
                for (int nt = 0; nt < 8; nt++) {
                    int col = nt * 8 + tg * 2;
                    *(u32*)&Kg[r0 * FP + col] =
                        pkbf((C[0][nt][1] + bk0) * sigm(C[1][nt][1] + bi0),
                             (C[0][nt][0] + bk0) * sigm(C[1][nt][0] + bi0));
                    *(u32*)&Kg[r1 * FP + col] =
                        pkbf((C[0][nt][3] + bk1) * sigm(C[1][nt][3] + bi1),
                             (C[0][nt][2] + bk1) * sigm(C[1][nt][2] + bi1));
                }
            } else {
                int v0 = rA - 64 + g, v1 = v0 + 8;
                float bv0 = biasS[rA + g], bv1 = biasS[rA + g + 8];
                float bf0 = biasS[rB + g], bf1 = biasS[rB + g + 8];
#pragma unroll
                for (int nt = 0; nt < 8; nt++) {
                    int col = nt * 8 + tg * 2;
                    *(u32*)&Vt[v0 * FP + col] = pkbf(C[0][nt][1] + bv0, C[0][nt][0] + bv0);
                    *(u32*)&Vt[v1 * FP + col] = pkbf(C[0][nt][3] + bv1, C[0][nt][2] + bv1);
                    fpart[0] += sigm(C[1][nt][0] + bf0) + sigm(C[1][nt][1] + bf0);
                    fpart[1] += sigm(C[1][nt][2] + bf1) + sigm(C[1][nt][3] + bf1);
                }
            }
            __syncthreads();
#pragma unroll
            for (int ks = 0; ks < 4; ks++) {
                int kb2 = ks * 16 + 2 * tg;
                u32 a0 = *(const u32*)&Kg[(mtk * 16 + g) * FP + kb2];
                u32 a1 = *(const u32*)&Kg[(mtk * 16 + g + 8) * FP + kb2];
                u32 a2 = *(const u32*)&Kg[(mtk * 16 + g) * FP + kb2 + 8];
                u32 a3 = *(const u32*)&Kg[(mtk * 16 + g + 8) * FP + kb2 + 8];
#pragma unroll
                for (int ntl = 0; ntl < 4; ntl++) {
                    u32 b0 = *(const u32*)&Vt[((ntb + ntl) * 8 + g) * FP + kb2];
                    u32 b1 = *(const u32*)&Vt[((ntb + ntl) * 8 + g) * FP + kb2 + 8];
                    mma16816(Ck[ntl], a0, a1, a2, a3, b0, b1);
                }
            }
            __syncthreads();
        }
    }
    float* kbase = g_know + b * 4096;
#pragma unroll
    for (int ntl = 0; ntl < 4; ntl++) {
        int c0 = mtk * 16 + g, d0 = (ntb + ntl) * 8 + tg * 2;
        atomicAdd(&kbase[c0 * 64 + d0],           Ck[ntl][0]);
        atomicAdd(&kbase[c0 * 64 + d0 + 1],       Ck[ntl][1]);
        atomicAdd(&kbase[(c0 + 8) * 64 + d0],     Ck[ntl][2]);
        atomicAdd(&kbase[(c0 + 8) * 64 + d0 + 1], Ck[ntl][3]);
    }
    if (wid >= 4) {
#pragma unroll
        for (int s = 0; s < 2; s++) {
            float v = fpart[s];
            v += __shfl_xor_sync(0xffffffffu, v, 1);
            v += __shfl_xor_sync(0xffffffffu, v, 2);
            if (tg == 0)
                atomicAdd(&g_fsum[b * 64 + (wid - 4) * 16 + g + s * 8], v);
        }
    }
}

// ===================== updA: mem + T1/M2 e-slice + d2 ====================
// grid (8, Bn), 256 thr. Block bx owns e-slice e0 = bx*8.
__global__ void __launch_bounds__(256) updA_kernel(
    const float* __restrict__ hidden, const float* __restrict__ Wq,
    const float* __restrict__ bq, const float* __restrict__ Wp,
    const float* __restrict__ bp, float* __restrict__ hid_out)
{
    __shared__ float memS[4096], WS[4096], T1L[512];
    __shared__ float fm[64], bf[64], uS[64], rSs[64], afS[8];
    int b = blockIdx.y, bx = blockIdx.x, tid = threadIdx.x;
    int e0 = bx * 8;
    if (tid < 64) {
        fm[tid] = g_fsum[b * 64 + tid] * (1.f / 65536.f);
        bf[tid] = g_bfold[b * 64 + tid];
    }
    if (tid < 8) afS[tid] = g_afold[b * 64 + e0 + tid];
    __syncthreads();
    const float* kb = g_know + b * 4096;
    const float* hb = hidden + (size_t)b * Lnum * 4096;
    float* ho = hid_out + (size_t)b * Lnum * 4096;
    for (int i = tid; i < 4096; i += 256) {
        int c = i >> 6;
        float m = fm[c] * hb[i] + kb[i] * (1.f / 65536.f);
        memS[i] = m;
        WS[i] = Wq[i];
        if (bx == 0) ho[i] = m;
    }
    __syncthreads();
    if (bx == 0 && tid < 64) {       // uS[c] = bq[c] + Wq[c,:]·bf
        const float* wr = WS + tid * 64;
        float a0 = bq[tid], a1 = 0, a2 = 0, a3 = 0;
#pragma unroll
        for (int e = 0; e < 64; e += 4) {
            a0 += wr[e] * bf[e];         a1 += wr[e + 1] * bf[e + 1];
            a2 += wr[e + 2] * bf[e + 2]; a3 += wr[e + 3] * bf[e + 3];
        }
        uS[tid] = (a0 + a1) + (a2 + a3);
    }
    __syncthreads();
    if (bx == 0 && tid < 64) {       // rS[d] = sum_c mem[c][d]·uS[c]
        float a0 = 0, a1 = 0, a2 = 0, a3 = 0;
#pragma unroll
        for (int c = 0; c < 64; c += 4) {
            a0 += memS[c * 64 + tid] * uS[c];
            a1 += memS[(c + 1) * 64 + tid] * uS[c + 1];
            a2 += memS[(c + 2) * 64 + tid] * uS[c + 2];
            a3 += memS[(c + 3) * 64 + tid] * uS[c + 3];
        }
        rSs[tid] = (a0 + a1) + (a2 + a3);
    }
    // T1L[d*8+el] = (sum_c mem[c][d]·Wq[c][e0+el]) * af[e0+el]
    for (int i = tid; i < 512; i += 256) {
        int d = i >> 3, el = i & 7, e = e0 + el;
        float a0 = 0, a1 = 0, a2 = 0, a3 = 0;
#pragma unroll
        for (int c = 0; c < 64; c += 4) {
            a0 += memS[c * 64 + d] * WS[c * 64 + e];
            a1 += memS[(c + 1) * 64 + d] * WS[(c + 1) * 64 + e];
            a2 += memS[(c + 2) * 64 + d] * WS[(c + 2) * 64 + e];
            a3 += memS[(c + 3) * 64 + d] * WS[(c + 3) * 64 + e];
        }
        T1L[i] = ((a0 + a1) + (a2 + a3)) * afS[el];
    }
    __syncthreads();
    for (int i = tid; i < 4096; i += 256) WS[i] = Wp[i];   // reuse for Wp
    __syncthreads();
    const float scale = 0.125f;
    // M2[(e0+el)*64+o] = scale * sum_d Wp[o][d]·T1L[d*8+el]
    for (int i = tid; i < 512; i += 256) {
        int el = i >> 6, o = i & 63;
        const float* wr = WS + o * 64;
        float a0 = 0, a1 = 0, a2 = 0, a3 = 0;
#pragma unroll
        for (int d = 0; d < 64; d += 4) {
            a0 += wr[d] * T1L[d * 8 + el];
            a1 += wr[d + 1] * T1L[(d + 1) * 8 + el];
            a2 += wr[d + 2] * T1L[(d + 2) * 8 + el];
            a3 += wr[d + 3] * T1L[(d + 3) * 8 + el];
        }
        g_M2[b * 4096 + (e0 + el) * 64 + o] = ((a0 + a1) + (a2 + a3)) * scale;
    }
    if (bx == 0 && tid < 64) {       // d2[o] = scale·Wp[o,:]·rS + bp[o]
        const float* wr = WS + tid * 64;
        float a0 = 0, a1 = 0, a2 = 0, a3 = 0;
#pragma unroll
        for (int d = 0; d < 64; d += 4) {
            a0 += wr[d] * rSs[d];         a1 += wr[d + 1] * rSs[d + 1];
            a2 += wr[d + 2] * rSs[d + 2]; a3 += wr[d + 3] * rSs[d + 3];
        }
        g_d2[b * 64 + tid] = ((a0 + a1) + (a2 + a3)) * scale + bp[tid];
    }
}

// ===================== updB: compose + next-layer stats + zero ===========
// grid (8, Bn). Block bx owns channel rows c0 = bx*8 of Tnew.
__global__ void __launch_bounds__(256) updB_kernel(int par) {
    const float* Tsrc = par ? g_T2 : g_T;
    float* Tdst       = par ? g_T  : g_T2;
    const float* tsrc = par ? g_t2 : g_t;
    float* tdst       = par ? g_t  : g_t2;
    __shared__ float A[4096], M2S[4096], Tr[512], tnewS[8], sumS[64];
    int b = blockIdx.y, bx = blockIdx.x, tid = threadIdx.x;
    int c0 = bx * 8;
    for (int i = tid; i < 4096; i += 256) {
        A[i] = Tsrc[b * 4096 + i];
        M2S[i] = g_M2[b * 4096 + i];
    }
    for (int i = tid; i < 512; i += 256) g_know[b * 4096 + bx * 512 + i] = 0.f;
    if (bx == 0 && tid < 64) g_fsum[b * 64 + tid] = 0.f;
    if (tid < 64) sumS[tid] = g_sum[b * 64 + tid];
    __syncthreads();
    // Tnew rows c0..c0+8
    for (int i = tid; i < 512; i += 256) {
        int cl = i >> 6, e = i & 63, c = c0 + cl;
        float a0 = A[c * 64 + e], a1 = 0, a2 = 0, a3 = 0;
#pragma unroll
        for (int m = 0; m < 64; m += 4) {
            a0 += M2S[m * 64 + c] * A[m * 64 + e];
            a1 += M2S[(m + 1) * 64 + c] * A[(m + 1) * 64 + e];
            a2 += M2S[(m + 2) * 64 + c] * A[(m + 2) * 64 + e];
            a3 += M2S[(m + 3) * 64 + c] * A[(m + 3) * 64 + e];
        }
        float v = (a0 + a1) + (a2 + a3);
        Tr[i] = v;
        Tdst[b * 4096 + c * 64 + e] = v;
    }
    // tnew for own channels
    if (tid < 8) {
        int c = c0 + tid;
        float a0 = tsrc[b * 64 + c] + g_d2[b * 64 + c], a1 = 0, a2 = 0, a3 = 0;
#pragma unroll
        for (int e = 0; e < 64; e += 4) {
            a0 += M2S[e * 64 + c] * tsrc[b * 64 + e];
            a1 += M2S[(e + 1) * 64 + c] * tsrc[b * 64 + e + 1];
            a2 += M2S[(e + 2) * 64 + c] * tsrc[b * 64 + e + 2];
            a3 += M2S[(e + 3) * 64 + c] * tsrc[b * 64 + e + 3];
        }
        float v = (a0 + a1) + (a2 + a3);
        tnewS[tid] = v;
        tdst[b * 64 + c] = v;
    }
    __syncthreads();
    for (int i = tid; i < 4096; i += 256) A[i] = g_Cov[b * 4096 + i];  // reuse
    __syncthreads();
    // stats for next layer on own channels (warp cl -> channel c0+cl)
    int cl = tid >> 5, lane = tid & 31;
    const float* Tc = Tr + cl * 64;
    float rs = 0.f, qf = 0.f;
#pragma unroll
    for (int eo = 0; eo < 2; eo++) {
        int e = lane + eo * 32;
        float Te = Tc[e];
        rs += Te * sumS[e];
        const float* Ce = A + e * 64;
        float i0 = 0, i1 = 0, i2 = 0, i3 = 0;
#pragma unroll
        for (int f = 0; f < 64; f += 4) {
            i0 += Ce[f] * Tc[f];         i1 += Ce[f + 1] * Tc[f + 1];
            i2 += Ce[f + 2] * Tc[f + 2]; i3 += Ce[f + 3] * Tc[f + 3];
        }
        qf += Te * ((i0 + i1) + (i2 + i3));
    }
#pragma unroll
    for (int o = 16; o > 0; o >>= 1) {
        rs += __shfl_xor_sync(~0u, rs, o);
        qf += __shfl_xor_sync(~0u, qf, o);
    }
    if (lane == 0) {
        int c = c0 + cl;
        float tc = tnewS[cl];
        g_S1[b * 64 + c] = rs + 65536.f * tc;
        g_S2[b * 64 + c] = qf + 2.f * tc * rs + 65536.f * tc * tc;
    }
}

// ===================== conv_out prep + conv_out =========================
__global__ void __launch_bounds__(256) convout_prep_kernel(
    const float* __restrict__ W, const float* __restrict__ bias)
{
    int b = blockIdx.x, tid = threadIdx.x;
    __shared__ float T[4096];
    for (int i = tid; i < 4096; i += 256) T[i] = g_T[b * 4096 + i];
    __syncthreads();
    for (int j = tid; j < 1152; j += 256) {
        int o = j / 576, r = j % 576, e = r / 9, tap = r % 9;
        float a0 = 0, a1 = 0, a2 = 0, a3 = 0;
#pragma unroll
        for (int c = 0; c < 64; c += 4) {
            a0 += W[o * 576 + c * 9 + tap] * T[c * 64 + e];
            a1 += W[o * 576 + (c + 1) * 9 + tap] * T[(c + 1) * 64 + e];
            a2 += W[o * 576 + (c + 2) * 9 + tap] * T[(c + 2) * 64 + e];
            a3 += W[o * 576 + (c + 3) * 9 + tap] * T[(c + 3) * 64 + e];
        }
        g_Wout[b * 1152 + j] = (a0 + a1) + (a2 + a3);
    }
    if (tid < 18) {
        int o = tid / 9, tap = tid % 9;
        float acc = 0.f;
        for (int c = 0; c < 64; c++)
            acc += W[o * 576 + c * 9 + tap] * g_t[b * 64 + c];
        g_tb[b * 18 + tid] = acc;
    }
    if (tid < 2) g_bout[b * 2 + tid] = bias[tid];
}

__global__ void __launch_bounds__(256) conv_out_kernel(
    const float* __restrict__ x, float* __restrict__ out)
{
    __shared__ float fs[8 * 3 * 258];
    __shared__ float ws[1152];
    __shared__ float tb[18];
    int b = blockIdx.y, y = blockIdx.x, tid = threadIdx.x;
    for (int i = tid; i < 1152; i += 256) ws[i] = g_Wout[b * 1152 + i];
    if (tid < 18) tb[tid] = g_tb[b * 18 + tid];
    __syncthreads();
    float acc0 = g_bout[b * 2 + 0], acc1 = g_bout[b * 2 + 1];
#pragma unroll
    for (int r = 0; r < 3; r++) {
        int yy = y + r - 1;
        if (yy < 0 || yy >= 256) continue;
#pragma unroll
        for (int k = 0; k < 3; k++) {
            int xx = tid + k - 1;
            if (xx < 0 || xx >= 256) continue;
            acc0 += tb[r * 3 + k];
            acc1 += tb[9 + r * 3 + k];
        }
    }
    const float* fb = g_feat + (size_t)b * Cc * Np;
    for (int cc = 0; cc < 64; cc += 8) {
        __syncthreads();
        for (int i = tid; i < 6192; i += 256) {
            int c = i / 774, rem = i % 774, r = rem / 258, col = rem % 258;
            int yy = y + r - 1, xx = col - 1;
            float v = 0.f;
            if (yy >= 0 && yy < 256 && xx >= 0 && xx < 256)
                v = fb[(size_t)(cc + c) * Np + yy * 256 + xx];
            fs[i] = v;
        }
        __syncthreads();
#pragma unroll
        for (int c = 0; c < 8; c++) {
            float in[9];
#pragma unroll
            for (int r = 0; r < 3; r++)
#pragma unroll
                for (int k = 0; k < 3; k++)
                    in[r * 3 + k] = fs[c * 774 + r * 258 + tid + k];
            const float* w0 = &ws[(cc + c) * 9];
            const float* w1 = &ws[(64 + cc + c) * 9];
#pragma unroll
            for (int t = 0; t < 9; t++) { acc0 += w0[t] * in[t]; acc1 += w1[t] * in[t]; }
        }
    }
    int o = y * 256 + tid;
    out[(size_t)(b * 2 + 0) * Np + o] = acc0 + x[(size_t)(b * 2 + 0) * Np + o];
    out[(size_t)(b * 2 + 1) * Np + o] = acc1 + x[(size_t)(b * 2 + 1) * Np + o];
}

extern "C" void kernel_launch(void* const* d_in, const int* in_sizes, int n_in,
                              void* d_out, int out_size)
{
    const float* x      = (const float*)d_in[0];
    const float* hidden = (const float*)d_in[1];
    const float* W_in   = (const float*)d_in[2];
    const float* b_in   = (const float*)d_in[3];
    const float* gamma  = (const float*)d_in[4];
    const float* beta   = (const float*)d_in[5];
    const float* Wq     = (const float*)d_in[6];
    const float* bq     = (const float*)d_in[7];
    const float* Wk     = (const float*)d_in[8];
    const float* bk     = (const float*)d_in[9];
    const float* Wv     = (const float*)d_in[10];
    const float* bv     = (const float*)d_in[11];
    const float* Wg     = (const float*)d_in[12];
    const float* bg     = (const float*)d_in[13];
    const float* Wp     = (const float*)d_in[14];
    const float* bp     = (const float*)d_in[15];
    const float* W_out  = (const float*)d_in[16];
    const float* b_out  = (const float*)d_in[17];
    float* out = (float*)d_out;
    float* hid_out = out + 262144;

    cudaFuncSetAttribute(pass2_mma_kernel,
                         cudaFuncAttributeMaxDynamicSharedMemorySize, SMEM_P2);

    zero_init_kernel<<<1, 256>>>();
    conv_in_kernel<<<dim3(256, 2), 256>>>(x, W_in, b_in);
    cov_kernel<<<dim3(74, 2), 256>>>();
    prep_stats_kernel<<<dim3(8, 2), 256>>>();
    for (int l = 0; l < Lnum; l++) {
        int par = l & 1;
        prep_weff_kernel<<<dim3(16, 2), 256>>>(
            par, gamma + l * 64, beta + l * 64,
            Wk + l * 4096, bk + l * 64, Wv + l * 4096, bv + l * 64,
            Wg + l * 8192, bg + l * 128);
        pass2_mma_kernel<<<dim3(74, 2), 256, SMEM_P2>>>();
        updA_kernel<<<dim3(8, 2), 256>>>(hidden + l * 4096, Wq + l * 4096,
                                         bq + l * 64, Wp + l * 4096,
                                         bp + l * 64, hid_out + l * 4096);
        updB_kernel<<<dim3(8, 2), 256>>>(par);
    }
    convout_prep_kernel<<<2, 256>>>(W_out, b_out);
    conv_out_kernel<<<dim3(256, 2), 256>>>(x, out);
}

// round 15
// speedup vs baseline: 3.7567x; 1.0231x over previous
#include <cuda_runtime.h>
#include <cuda_bf16.h>
#include <cstdint>
#include <cstddef>

constexpr int Cc   = 64;
constexpr int Np   = 65536;
constexpr int Lnum = 4;
constexpr int Bn   = 2;
constexpr int FP   = 72;    // bf16 fragment pitch — conflict-free
constexpr int CP   = 136;   // cov transpose pitch

__device__ float g_feat[(size_t)Bn * Cc * Np];          // fp32, for conv_out
__device__ uint32_t g_featbf[(size_t)Bn * Np * 32];     // bf16 pairs, [b][n][c]
__device__ float g_sum[Bn * 64];
__device__ float g_Cov[Bn * 4096];
__device__ float g_T[Bn * 4096];                        // ping buffer
__device__ float g_T2[Bn * 4096];                       // pong buffer
__device__ float g_t[Bn * 64];
__device__ float g_t2[Bn * 64];
__device__ float g_S1[Bn * 64];
__device__ float g_S2[Bn * 64];
__device__ float g_afold[Bn * 64];
__device__ float g_bfold[Bn * 64];
__device__ float g_know[Bn * 4096];
__device__ float g_fsum[Bn * 64];
__device__ float g_M2[Bn * 4096];
__device__ float g_d2[Bn * 64];
__device__ float g_Weff[Bn * 16384];
__device__ float g_beff[Bn * 256];
__device__ float g_Wout[Bn * 1152];
__device__ float g_tb[Bn * 18];
__device__ float g_bout[Bn * 2];

typedef uint32_t u32;
__device__ __forceinline__ u32 pkbf(float hi, float lo) {
    u32 r; asm("cvt.rn.bf16x2.f32 %0, %1, %2;" : "=r"(r) : "f"(hi), "f"(lo));
    return r;
}
__device__ __forceinline__ float sigm(float x) { return 1.f / (1.f + __expf(-x)); }
__device__ __forceinline__ float wred(float v) {
#pragma unroll
    for (int o = 16; o > 0; o >>= 1) v += __shfl_xor_sync(0xffffffffu, v, o);
    return v;
}
__device__ __forceinline__ u32 smem_u32(const void* p) {
    u32 a;
    asm("{ .reg .u64 t; cvta.to.shared.u64 t, %1; cvt.u32.u64 %0, t; }"
        : "=r"(a) : "l"(p));
    return a;
}
__device__ __forceinline__ void mma16816(float c[4], u32 a0, u32 a1, u32 a2,
                                         u32 a3, u32 b0, u32 b1) {
    asm volatile(
        "mma.sync.aligned.m16n8k16.row.col.f32.bf16.bf16.f32 "
        "{%0,%1,%2,%3}, {%4,%5,%6,%7}, {%8,%9}, {%0,%1,%2,%3};"
        : "+f"(c[0]), "+f"(c[1]), "+f"(c[2]), "+f"(c[3])
        : "r"(a0), "r"(a1), "r"(a2), "r"(a3), "r"(b0), "r"(b1));
}

// ===================== init =====================
__global__ void zero_init_kernel() {
    int tid = threadIdx.x;
    for (int i = tid; i < Bn * 4096; i += 256) {
        g_Cov[i] = 0.f;
        g_T[i] = (((i >> 6) & 63) == (i & 63)) ? 1.f : 0.f;
    }
    for (int i = tid; i < Bn * 64; i += 256) { g_sum[i] = 0.f; g_t[i] = 0.f; }
}

// ===================== conv3x3 in + fused covariance =====================
__global__ void __launch_bounds__(256) conv_in_kernel(
    const float* __restrict__ x, const float* __restrict__ W,
    const float* __restrict__ bias)
{
    __shared__ float xs[2 * 3 * 258];
    __shared__ float ws[64 * 18];
    __shared__ float bsh[64];
    __shared__ float sumloc[64];
    __shared__ __nv_bfloat16 Xt[2][64 * CP];
    int b = blockIdx.y, y = blockIdx.x, tid = threadIdx.x;
    for (int i = tid; i < 64 * 18; i += 256) ws[i] = W[i];
    if (tid < 64) { bsh[tid] = bias[tid]; sumloc[tid] = 0.f; }
    for (int i = tid; i < 2 * 3 * 258; i += 256) {
        int c = i / 774, rem = i % 774, r = rem / 258, col = rem % 258;
        int yy = y + r - 1, xx = col - 1;
        float v = 0.f;
        if (yy >= 0 && yy < 256 && xx >= 0 && xx < 256)
            v = x[((size_t)(b * 2 + c) * 256 + yy) * 256 + xx];
        xs[i] = v;
    }
    __syncthreads();
    float in[18];
#pragma unroll
    for (int c = 0; c < 2; c++)
#pragma unroll
        for (int r = 0; r < 3; r++)
#pragma unroll
            for (int k = 0; k < 3; k++)
                in[c * 9 + r * 3 + k] = xs[c * 774 + r * 258 + tid + k];
    int n = y * 256 + tid;
    size_t ob = (size_t)b * Cc * Np + n;
    u32* gbf = g_featbf + (size_t)b * Np * 32 + (size_t)n * 32;
    int half = tid >> 7, pxl = tid & 127;
    __nv_bfloat16* Xh = Xt[half];
#pragma unroll
    for (int oc = 0; oc < 64; oc += 2) {
        float a0 = bsh[oc], a1 = bsh[oc + 1];
#pragma unroll
        for (int t = 0; t < 18; t++) {
            a0 += ws[oc * 18 + t] * in[t];
            a1 += ws[(oc + 1) * 18 + t] * in[t];
        }
        g_feat[ob + (size_t)oc * Np] = a0;
        g_feat[ob + (size_t)(oc + 1) * Np] = a1;
        u32 pr = pkbf(a1, a0);
        gbf[oc >> 1] = pr;
        __nv_bfloat162 h2 = *(__nv_bfloat162*)&pr;
        Xh[oc * CP + pxl] = h2.x;
        Xh[(oc + 1) * CP + pxl] = h2.y;
        float s0 = wred(a0), s1 = wred(a1);
        if ((tid & 31) == 0) {
            atomicAdd(&sumloc[oc], s0);
            atomicAdd(&sumloc[oc + 1], s1);
        }
    }
    __syncthreads();
    if (tid < 64) atomicAdd(&g_sum[b * 64 + tid], sumloc[tid]);
    // covariance MMA: warp w -> half w>>2, rows (w&3)*16
    int wid = tid >> 5, g = (tid & 31) >> 2, tg = tid & 3;
    int mh = wid >> 2, rb = (wid & 3) * 16;
    const __nv_bfloat16* Xc = Xt[mh];
    float C[8][4];
#pragma unroll
    for (int i = 0; i < 8; i++)
#pragma unroll
        for (int j = 0; j < 4; j++) C[i][j] = 0.f;
#pragma unroll
    for (int ks = 0; ks < 8; ks++) {
        int kb2 = ks * 16 + 2 * tg;
        u32 a0 = *(const u32*)&Xc[(rb + g) * CP + kb2];
        u32 a1 = *(const u32*)&Xc[(rb + g + 8) * CP + kb2];
        u32 a2 = *(const u32*)&Xc[(rb + g) * CP + kb2 + 8];
        u32 a3 = *(const u32*)&Xc[(rb + g + 8) * CP + kb2 + 8];
#pragma unroll
        for (int nt = 0; nt < 8; nt++) {
            u32 b0 = *(const u32*)&Xc[(nt * 8 + g) * CP + kb2];
            u32 b1 = *(const u32*)&Xc[(nt * 8 + g) * CP + kb2 + 8];
            mma16816(C[nt], a0, a1, a2, a3, b0, b1);
        }
    }
    float* cb = g_Cov + b * 4096;
    int c0 = rb + g;
#pragma unroll
    for (int nt = 0; nt < 8; nt++) {
        int d = nt * 8 + tg * 2;
        atomicAdd(&cb[c0 * 64 + d], C[nt][0]);
        atomicAdd(&cb[c0 * 64 + d + 1], C[nt][1]);
        atomicAdd(&cb[(c0 + 8) * 64 + d], C[nt][2]);
        atomicAdd(&cb[(c0 + 8) * 64 + d + 1], C[nt][3]);
    }
}

// ===================== layer-0 stats (standalone) ========================
__global__ void __launch_bounds__(256) prep_stats_kernel() {
    __shared__ float CovS[4096], Tr[512], sumS[64];
    int b = blockIdx.y, bx = blockIdx.x, tid = threadIdx.x;
    int c0 = bx * 8;
    for (int i = tid; i < 4096; i += 256) CovS[i] = g_Cov[b * 4096 + i];
    for (int i = tid; i < 512; i += 256) Tr[i] = g_T[b * 4096 + c0 * 64 + i];
    if (tid < 64) sumS[tid] = g_sum[b * 64 + tid];
    for (int i = tid; i < 512; i += 256) g_know[b * 4096 + bx * 512 + i] = 0.f;
    if (bx == 0 && tid < 64) g_fsum[b * 64 + tid] = 0.f;
    __syncthreads();
    int cl = tid >> 5, lane = tid & 31;
    const float* Tc = Tr + cl * 64;
    float rs = 0.f, qf = 0.f;
#pragma unroll
    for (int eo = 0; eo < 2; eo++) {
        int e = lane + eo * 32;
        float Te = Tc[e];
        rs += Te * sumS[e];
        const float* Ce = CovS + e * 64;
        float i0 = 0, i1 = 0, i2 = 0, i3 = 0;
#pragma unroll
        for (int f = 0; f < 64; f += 4) {
            i0 += Ce[f] * Tc[f];         i1 += Ce[f + 1] * Tc[f + 1];
            i2 += Ce[f + 2] * Tc[f + 2]; i3 += Ce[f + 3] * Tc[f + 3];
        }
        qf += Te * ((i0 + i1) + (i2 + i3));
    }
#pragma unroll
    for (int o = 16; o > 0; o >>= 1) {
        rs += __shfl_xor_sync(~0u, rs, o);
        qf += __shfl_xor_sync(~0u, qf, o);
    }
    if (lane == 0) {
        int c = c0 + cl;
        float tc = g_t[b * 64 + c];
        g_S1[b * 64 + c] = rs + 65536.f * tc;
        g_S2[b * 64 + c] = qf + 2.f * tc * rs + 65536.f * tc * tc;
    }
}

// ===================== effective weights =================================
__global__ void __launch_bounds__(256) prep_weff_kernel(
    int par, const float* __restrict__ gamma, const float* __restrict__ beta,
    const float* __restrict__ Wk, const float* __restrict__ bk,
    const float* __restrict__ Wv, const float* __restrict__ bv,
    const float* __restrict__ Wg, const float* __restrict__ bg)
{
    const float* Tsrc = par ? g_T2 : g_T;
    const float* tsrc = par ? g_t2 : g_t;
    __shared__ float aT[4096], af[64], wvec[64], S1s[64], S2s[64];
    int b = blockIdx.y, bx = blockIdx.x, tid = threadIdx.x;
    int s = bx >> 2, oc0 = (bx & 3) * 16;
    if (tid < 64) { S1s[tid] = g_S1[b * 64 + tid]; S2s[tid] = g_S2[b * 64 + tid]; }
    __syncthreads();
    if (tid < 64) {
        int g = tid >> 3;
        float m = 0.f, q2 = 0.f;
#pragma unroll
        for (int j = 0; j < 8; j++) { m += S1s[g * 8 + j]; q2 += S2s[g * 8 + j]; }
        float inv = 1.f / (8.f * 65536.f);
        m *= inv; q2 *= inv;
        float a = gamma[tid] * rsqrtf(q2 - m * m + 1e-5f);
        float bb = beta[tid] - m * a;
        af[tid] = a;
        wvec[tid] = a * tsrc[b * 64 + tid] + bb;
        if (bx == 0) { g_afold[b * 64 + tid] = a; g_bfold[b * 64 + tid] = bb; }
    }
    __syncthreads();
    for (int i = tid; i < 4096; i += 256) aT[i] = af[i >> 6] * Tsrc[b * 4096 + i];
    __syncthreads();
    const float* Ws = (s == 0) ? Wk : (s == 1) ? Wv : (s == 2) ? Wg : Wg + 4096;
    const float* bs = (s == 0) ? bk : (s == 1) ? bv : (s == 2) ? bg : bg + 64;
#pragma unroll
    for (int r = 0; r < 4; r++) {
        int o = tid + 256 * r;
        int oc = oc0 + (o >> 6), e = o & 63;
        const float* wr = Ws + oc * 64;
        float a0 = 0, a1 = 0, a2 = 0, a3 = 0;
#pragma unroll
        for (int c = 0; c < 64; c += 4) {
            a0 += wr[c]     * aT[c * 64 + e];
            a1 += wr[c + 1] * aT[(c + 1) * 64 + e];
            a2 += wr[c + 2] * aT[(c + 2) * 64 + e];
            a3 += wr[c + 3] * aT[(c + 3) * 64 + e];
        }
        g_Weff[b * 16384 + (s * 64 + oc) * 64 + e] = (a0 + a1) + (a2 + a3);
    }
    if (tid < 16) {
        int oc = oc0 + tid;
        const float* wr = Ws + oc * 64;
        float a0 = bs[oc], a1 = 0, a2 = 0, a3 = 0;
#pragma unroll
        for (int c = 0; c < 64; c += 4) {
            a0 += wr[c] * wvec[c];         a1 += wr[c + 1] * wvec[c + 1];
            a2 += wr[c + 2] * wvec[c + 2]; a3 += wr[c + 3] * wvec[c + 3];
        }
        g_beff[b * 256 + s * 64 + oc] = (a0 + a1) + (a2 + a3);
    }
}

// ===================== pass 2: warp-MMA + cp.async double buffer =========
constexpr int SM_WHI = 0;
constexpr int SM_WLO = 36864;
constexpr int SM_XSA = 73728;
constexpr int SM_XSB = 92160;
constexpr int SM_VT  = 110592;
constexpr int SM_KG  = 119808;
constexpr int SM_BIA = 129024;
constexpr int SMEM_P2 = 130048;

__device__ __forceinline__ void prefetch_tile(u32 xsb, const u32* gbf, int n0,
                                              int tid) {
#pragma unroll
    for (int r = 0; r < 4; r++) {
        int i = tid + 256 * r;
        int px = i >> 3, wq = i & 7;
        u32 dst = xsb + px * (FP * 2) + wq * 16;
        const u32* src = gbf + (size_t)(n0 + px) * 32 + wq * 4;
        asm volatile("cp.async.cg.shared.global [%0], [%1], 16;"
                     :: "r"(dst), "l"(src));
    }
    asm volatile("cp.async.commit_group;");
}

__global__ void __launch_bounds__(256, 1) pass2_mma_kernel() {
    extern __shared__ char smc[];
    __nv_bfloat16* WHi = (__nv_bfloat16*)(smc + SM_WHI);
    __nv_bfloat16* WLo = (__nv_bfloat16*)(smc + SM_WLO);
    __nv_bfloat16* Vt  = (__nv_bfloat16*)(smc + SM_VT);
    __nv_bfloat16* Kg  = (__nv_bfloat16*)(smc + SM_KG);
    float* biasS = (float*)(smc + SM_BIA);

    int b = blockIdx.y, tid = threadIdx.x;
    int wid = tid >> 5, g = (tid & 31) >> 2, tg = tid & 3;

    for (int i = tid; i < 16384; i += 256) {
        int oc = i >> 6, c = i & 63;
        float w = g_Weff[b * 16384 + i];
        __nv_bfloat16 h = __float2bfloat16(w);
        WHi[oc * FP + c] = h;
        WLo[oc * FP + c] = __float2bfloat16(w - __bfloat162float(h));
    }
    biasS[tid] = g_beff[b * 256 + tid];

    float Ck[4][4];
#pragma unroll
    for (int i = 0; i < 4; i++)
#pragma unroll
        for (int j = 0; j < 4; j++) Ck[i][j] = 0.f;
    float fpart[2] = {0.f, 0.f};

    const u32* gbf = g_featbf + (size_t)b * Np * 32;
    int mtk = wid >> 1, ntb = (wid & 1) * 4;
    int rA = (wid < 4) ? wid * 16 : 64 + (wid - 4) * 16;
    int rB = (wid < 4) ? 192 + wid * 16 : 128 + (wid - 4) * 16;
    bool fwarp = (wid >= 4);

    u32 xsbase[2] = {smem_u32(smc + SM_XSA), smem_u32(smc + SM_XSB)};
    __nv_bfloat16* xsptr[2] = {(__nv_bfloat16*)(smc + SM_XSA),
                               (__nv_bfloat16*)(smc + SM_XSB)};
    prefetch_tile(xsbase[0], gbf, blockIdx.x << 7, tid);
    int bufc = 0;
    __syncthreads();   // weights staged

    for (int t = blockIdx.x; t < 512; t += 74) {
        asm volatile("cp.async.wait_group 0;" ::: "memory");
        __syncthreads();
        int tn = t + 74;
        if (tn < 512) prefetch_tile(xsbase[bufc ^ 1], gbf, tn << 7, tid);
        const __nv_bfloat16* Xs = xsptr[bufc];

#pragma unroll 1
        for (int h = 0; h < 2; h++) {
            const __nv_bfloat16* Xh = Xs + h * 64 * FP;
            float C[2][8][4];
#pragma unroll
            for (int mt = 0; mt < 2; mt++)
#pragma unroll
                for (int nt = 0; nt < 8; nt++)
#pragma unroll
                    for (int q = 0; q < 4; q++) C[mt][nt][q] = 0.f;
#pragma unroll
            for (int ks = 0; ks < 4; ks++) {
                int kb2 = ks * 16 + 2 * tg;
                u32 bfr[8][2];
#pragma unroll
                for (int nt = 0; nt < 8; nt++) {
                    bfr[nt][0] = *(const u32*)&Xh[(nt * 8 + g) * FP + kb2];
                    bfr[nt][1] = *(const u32*)&Xh[(nt * 8 + g) * FP + kb2 + 8];
                }
#pragma unroll
                for (int mt = 0; mt < 2; mt++) {
                    int r = mt ? rB : rA;
                    u32 h0 = *(const u32*)&WHi[(r + g) * FP + kb2];
                    u32 h1 = *(const u32*)&WHi[(r + g + 8) * FP + kb2];
                    u32 h2 = *(const u32*)&WHi[(r + g) * FP + kb2 + 8];
                    u32 h3 = *(const u32*)&WHi[(r + g + 8) * FP + kb2 + 8];
#pragma unroll
                    for (int nt = 0; nt < 8; nt++)
                        mma16816(C[mt][nt], h0, h1, h2, h3, bfr[nt][0], bfr[nt][1]);
                    if (!(fwarp && mt == 1)) {   // f-gate rows: hi-only
                        u32 l0 = *(const u32*)&WLo[(r + g) * FP + kb2];
                        u32 l1 = *(const u32*)&WLo[(r + g + 8) * FP + kb2];
                        u32 l2 = *(const u32*)&WLo[(r + g) * FP + kb2 + 8];
                        u32 l3 = *(const u32*)&WLo[(r + g + 8) * FP + kb2 + 8];
#pragma unroll
                        for (int nt = 0; nt < 8; nt++)
                            mma16816(C[mt][nt], l0, l1, l2, l3, bfr[nt][0], bfr[nt][1]);
                    }
                }
            }
            if (wid < 4) {
                int r0 = rA + g, r1 = r0 + 8;
                float bk0 = biasS[r0], bk1 = biasS[r1];
                float bi0 = biasS[rB + g], bi1 = biasS[rB + g + 8];
#pragma unroll
                for (int nt = 0; nt < 8; nt++) {
                    int col = nt * 8 + tg * 2;
                    *(u32*)&Kg[r0 * FP + col] =
                        pkbf((C[0][nt][1] + bk0) * sigm(C[1][nt][1] + bi0),
                             (C[0][nt][0] + bk0) * sigm(C[1][nt][0] + bi0));
                    *(u32*)&Kg[r1 * FP + col] =
                        pkbf((C[0][nt][3] + bk1) * sigm(C[1][nt][3] + bi1),
                             (C[0][nt][2] + bk1) * sigm(C[1][nt][2] + bi1));
                }
            } else {
                int v0 = rA - 64 + g, v1 = v0 + 8;
                float bv0 = biasS[rA + g], bv1 = biasS[rA + g + 8];
                float bf0 = biasS[rB + g], bf1 = biasS[rB + g + 8];
#pragma unroll
                for (int nt = 0; nt < 8; nt++) {
                    int col = nt * 8 + tg * 2;
                    *(u32*)&Vt[v0 * FP + col] = pkbf(C[0][nt][1] + bv0, C[0][nt][0] + bv0);
                    *(u32*)&Vt[v1 * FP + col] = pkbf(C[0][nt][3] + bv1, C[0][nt][2] + bv1);
                    fpart[0] += sigm(C[1][nt][0] + bf0) + sigm(C[1][nt][1] + bf0);
                    fpart[1] += sigm(C[1][nt][2] + bf1) + sigm(C[1][nt][3] + bf1);
                }
            }
            __syncthreads();
#pragma unroll
            for (int ks = 0; ks < 4; ks++) {
                int kb2 = ks * 16 + 2 * tg;
                u32 a0 = *(const u32*)&Kg[(mtk * 16 + g) * FP + kb2];
                u32 a1 = *(const u32*)&Kg[(mtk * 16 + g + 8) * FP + kb2];
                u32 a2 = *(const u32*)&Kg[(mtk * 16 + g) * FP + kb2 + 8];
                u32 a3 = *(const u32*)&Kg[(mtk * 16 + g + 8) * FP + kb2 + 8];
#pragma unroll
                for (int ntl = 0; ntl < 4; ntl++) {
                    u32 b0 = *(const u32*)&Vt[((ntb + ntl) * 8 + g) * FP + kb2];
                    u32 b1 = *(const u32*)&Vt[((ntb + ntl) * 8 + g) * FP + kb2 + 8];
                    mma16816(Ck[ntl], a0, a1, a2, a3, b0, b1);
                }
            }
            __syncthreads();
        }
        bufc ^= 1;
    }
    float* kbase = g_know + b * 4096;
#pragma unroll
    for (int ntl = 0; ntl < 4; ntl++) {
        int c0 = mtk * 16 + g, d0 = (ntb + ntl) * 8 + tg * 2;
        atomicAdd(&kbase[c0 * 64 + d0],           Ck[ntl][0]);
        atomicAdd(&kbase[c0 * 64 + d0 + 1],       Ck[ntl][1]);
        atomicAdd(&kbase[(c0 + 8) * 64 + d0],     Ck[ntl][2]);
        atomicAdd(&kbase[(c0 + 8) * 64 + d0 + 1], Ck[ntl][3]);
    }
    if (wid >= 4) {
#pragma unroll
        for (int s = 0; s < 2; s++) {
            float v = fpart[s];
            v += __shfl_xor_sync(0xffffffffu, v, 1);
            v += __shfl_xor_sync(0xffffffffu, v, 2);
            if (tg == 0)
                atomicAdd(&g_fsum[b * 64 + (wid - 4) * 16 + g + s * 8], v);
        }
    }
}

// ===================== updA: mem + T1/M2 e-slice + d2 ====================
__global__ void __launch_bounds__(256) updA_kernel(
    const float* __restrict__ hidden, const float* __restrict__ Wq,
    const float* __restrict__ bq, const float* __restrict__ Wp,
    const float* __restrict__ bp, float* __restrict__ hid_out)
{
    __shared__ float memS[4096], WS[4096], T1L[512];
    __shared__ float fm[64], bf[64], uS[64], rSs[64], afS[8];
    int b = blockIdx.y, bx = blockIdx.x, tid = threadIdx.x;
    int e0 = bx * 8;
    if (tid < 64) {
        fm[tid] = g_fsum[b * 64 + tid] * (1.f / 65536.f);
        bf[tid] = g_bfold[b * 64 + tid];
    }
    if (tid < 8) afS[tid] = g_afold[b * 64 + e0 + tid];
    __syncthreads();
    const float* kb = g_know + b * 4096;
    const float* hb = hidden + (size_t)b * Lnum * 4096;
    float* ho = hid_out + (size_t)b * Lnum * 4096;
    for (int i = tid; i < 4096; i += 256) {
        int c = i >> 6;
        float m = fm[c] * hb[i] + kb[i] * (1.f / 65536.f);
        memS[i] = m;
        WS[i] = Wq[i];
        if (bx == 0) ho[i] = m;
    }
    __syncthreads();
    if (bx == 0 && tid < 64) {
        const float* wr = WS + tid * 64;
        float a0 = bq[tid], a1 = 0, a2 = 0, a3 = 0;
#pragma unroll
        for (int e = 0; e < 64; e += 4) {
            a0 += wr[e] * bf[e];         a1 += wr[e + 1] * bf[e + 1];
            a2 += wr[e + 2] * bf[e + 2]; a3 += wr[e + 3] * bf[e + 3];
        }
        uS[tid] = (a0 + a1) + (a2 + a3);
    }
    __syncthreads();
    if (bx == 0 && tid < 64) {
        float a0 = 0, a1 = 0, a2 = 0, a3 = 0;
#pragma unroll
        for (int c = 0; c < 64; c += 4) {
            a0 += memS[c * 64 + tid] * uS[c];
            a1 += memS[(c + 1) * 64 + tid] * uS[c + 1];
            a2 += memS[(c + 2) * 64 + tid] * uS[c + 2];
            a3 += memS[(c + 3) * 64 + tid] * uS[c + 3];
        }
        rSs[tid] = (a0 + a1) + (a2 + a3);
    }
    for (int i = tid; i < 512; i += 256) {
        int d = i >> 3, el = i & 7, e = e0 + el;
        float a0 = 0, a1 = 0, a2 = 0, a3 = 0;
#pragma unroll
        for (int c = 0; c < 64; c += 4) {
            a0 += memS[c * 64 + d] * WS[c * 64 + e];
            a1 += memS[(c + 1) * 64 + d] * WS[(c + 1) * 64 + e];
            a2 += memS[(c + 2) * 64 + d] * WS[(c + 2) * 64 + e];
            a3 += memS[(c + 3) * 64 + d] * WS[(c + 3) * 64 + e];
        }
        T1L[i] = ((a0 + a1) + (a2 + a3)) * afS[el];
    }
    __syncthreads();
    for (int i = tid; i < 4096; i += 256) WS[i] = Wp[i];
    __syncthreads();
    const float scale = 0.125f;
    for (int i = tid; i < 512; i += 256) {
        int el = i >> 6, o = i & 63;
        const float* wr = WS + o * 64;
        float a0 = 0, a1 = 0, a2 = 0, a3 = 0;
#pragma unroll
        for (int d = 0; d < 64; d += 4) {
            a0 += wr[d] * T1L[d * 8 + el];
            a1 += wr[d + 1] * T1L[(d + 1) * 8 + el];
            a2 += wr[d + 2] * T1L[(d + 2) * 8 + el];
            a3 += wr[d + 3] * T1L[(d + 3) * 8 + el];
        }
        g_M2[b * 4096 + (e0 + el) * 64 + o] = ((a0 + a1) + (a2 + a3)) * scale;
    }
    if (bx == 0 && tid < 64) {
        const float* wr = WS + tid * 64;
        float a0 = 0, a1 = 0, a2 = 0, a3 = 0;
#pragma unroll
        for (int d = 0; d < 64; d += 4) {
            a0 += wr[d] * rSs[d];         a1 += wr[d + 1] * rSs[d + 1];
            a2 += wr[d + 2] * rSs[d + 2]; a3 += wr[d + 3] * rSs[d + 3];
        }
        g_d2[b * 64 + tid] = ((a0 + a1) + (a2 + a3)) * scale + bp[tid];
    }
}

// ===================== updB: compose + next-layer stats + zero ===========
__global__ void __launch_bounds__(256) updB_kernel(int par) {
    const float* Tsrc = par ? g_T2 : g_T;
    float* Tdst       = par ? g_T  : g_T2;
    const float* tsrc = par ? g_t2 : g_t;
    float* tdst       = par ? g_t  : g_t2;
    __shared__ float A[4096], M2S[4096], Tr[512], tnewS[8], sumS[64];
    int b = blockIdx.y, bx = blockIdx.x, tid = threadIdx.x;
    int c0 = bx * 8;
    for (int i = tid; i < 4096; i += 256) {
        A[i] = Tsrc[b * 4096 + i];
        M2S[i] = g_M2[b * 4096 + i];
    }
    for (int i = tid; i < 512; i += 256) g_know[b * 4096 + bx * 512 + i] = 0.f;
    if (bx == 0 && tid < 64) g_fsum[b * 64 + tid] = 0.f;
    if (tid < 64) sumS[tid] = g_sum[b * 64 + tid];
    __syncthreads();
    for (int i = tid; i < 512; i += 256) {
        int cl = i >> 6, e = i & 63, c = c0 + cl;
        float a0 = A[c * 64 + e], a1 = 0, a2 = 0, a3 = 0;
#pragma unroll
        for (int m = 0; m < 64; m += 4) {
            a0 += M2S[m * 64 + c] * A[m * 64 + e];
            a1 += M2S[(m + 1) * 64 + c] * A[(m + 1) * 64 + e];
            a2 += M2S[(m + 2) * 64 + c] * A[(m + 2) * 64 + e];
            a3 += M2S[(m + 3) * 64 + c] * A[(m + 3) * 64 + e];
        }
        float v = (a0 + a1) + (a2 + a3);
        Tr[i] = v;
        Tdst[b * 4096 + c * 64 + e] = v;
    }
    if (tid < 8) {
        int c = c0 + tid;
        float a0 = tsrc[b * 64 + c] + g_d2[b * 64 + c], a1 = 0, a2 = 0, a3 = 0;
#pragma unroll
        for (int e = 0; e < 64; e += 4) {
            a0 += M2S[e * 64 + c] * tsrc[b * 64 + e];
            a1 += M2S[(e + 1) * 64 + c] * tsrc[b * 64 + e + 1];
            a2 += M2S[(e + 2) * 64 + c] * tsrc[b * 64 + e + 2];
            a3 += M2S[(e + 3) * 64 + c] * tsrc[b * 64 + e + 3];
        }
        float v = (a0 + a1) + (a2 + a3);
        tnewS[tid] = v;
        tdst[b * 64 + c] = v;
    }
    __syncthreads();
    for (int i = tid; i < 4096; i += 256) A[i] = g_Cov[b * 4096 + i];
    __syncthreads();
    int cl = tid >> 5, lane = tid & 31;
    const float* Tc = Tr + cl * 64;
    float rs = 0.f, qf = 0.f;
#pragma unroll
    for (int eo = 0; eo < 2; eo++) {
        int e = lane + eo * 32;
        float Te = Tc[e];
        rs += Te * sumS[e];
        const float* Ce = A + e * 64;
        float i0 = 0, i1 = 0, i2 = 0, i3 = 0;
#pragma unroll
        for (int f = 0; f < 64; f += 4) {
            i0 += Ce[f] * Tc[f];         i1 += Ce[f + 1] * Tc[f + 1];
            i2 += Ce[f + 2] * Tc[f + 2]; i3 += Ce[f + 3] * Tc[f + 3];
        }
        qf += Te * ((i0 + i1) + (i2 + i3));
    }
#pragma unroll
    for (int o = 16; o > 0; o >>= 1) {
        rs += __shfl_xor_sync(~0u, rs, o);
        qf += __shfl_xor_sync(~0u, qf, o);
    }
    if (lane == 0) {
        int c = c0 + cl;
        float tc = tnewS[cl];
        g_S1[b * 64 + c] = rs + 65536.f * tc;
        g_S2[b * 64 + c] = qf + 2.f * tc * rs + 65536.f * tc * tc;
    }
}

// ===================== conv_out prep + conv_out =========================
__global__ void __launch_bounds__(256) convout_prep_kernel(
    const float* __restrict__ W, const float* __restrict__ bias)
{
    int b = blockIdx.x, tid = threadIdx.x;
    __shared__ float T[4096];
    for (int i = tid; i < 4096; i += 256) T[i] = g_T[b * 4096 + i];
    __syncthreads();
    for (int j = tid; j < 1152; j += 256) {
        int o = j / 576, r = j % 576, e = r / 9, tap = r % 9;
        float a0 = 0, a1 = 0, a2 = 0, a3 = 0;
#pragma unroll
        for (int c = 0; c < 64; c += 4) {
            a0 += W[o * 576 + c * 9 + tap] * T[c * 64 + e];
            a1 += W[o * 576 + (c + 1) * 9 + tap] * T[(c + 1) * 64 + e];
            a2 += W[o * 576 + (c + 2) * 9 + tap] * T[(c + 2) * 64 + e];
            a3 += W[o * 576 + (c + 3) * 9 + tap] * T[(c + 3) * 64 + e];
        }
        g_Wout[b * 1152 + j] = (a0 + a1) + (a2 + a3);
    }
    if (tid < 18) {
        int o = tid / 9, tap = tid % 9;
        float acc = 0.f;
        for (int c = 0; c < 64; c++)
            acc += W[o * 576 + c * 9 + tap] * g_t[b * 64 + c];
        g_tb[b * 18 + tid] = acc;
    }
    if (tid < 2) g_bout[b * 2 + tid] = bias[tid];
}

__global__ void __launch_bounds__(256) conv_out_kernel(
    const float* __restrict__ x, float* __restrict__ out)
{
    __shared__ float fs[8 * 3 * 258];
    __shared__ float ws[1152];
    __shared__ float tb[18];
    int b = blockIdx.y, y = blockIdx.x, tid = threadIdx.x;
    for (int i = tid; i < 1152; i += 256) ws[i] = g_Wout[b * 1152 + i];
    if (tid < 18) tb[tid] = g_tb[b * 18 + tid];
    __syncthreads();
    float acc0 = g_bout[b * 2 + 0], acc1 = g_bout[b * 2 + 1];
#pragma unroll
    for (int r = 0; r < 3; r++) {
        int yy = y + r - 1;
        if (yy < 0 || yy >= 256) continue;
#pragma unroll
        for (int k = 0; k < 3; k++) {
            int xx = tid + k - 1;
            if (xx < 0 || xx >= 256) continue;
            acc0 += tb[r * 3 + k];
            acc1 += tb[9 + r * 3 + k];
        }
    }
    const float* fb = g_feat + (size_t)b * Cc * Np;
    for (int cc = 0; cc < 64; cc += 8) {
        __syncthreads();
        for (int i = tid; i < 6192; i += 256) {
            int c = i / 774, rem = i % 774, r = rem / 258, col = rem % 258;
            int yy = y + r - 1, xx = col - 1;
            float v = 0.f;
            if (yy >= 0 && yy < 256 && xx >= 0 && xx < 256)
                v = fb[(size_t)(cc + c) * Np + yy * 256 + xx];
            fs[i] = v;
        }
        __syncthreads();
#pragma unroll
        for (int c = 0; c < 8; c++) {
            float in[9];
#pragma unroll
            for (int r = 0; r < 3; r++)
#pragma unroll
                for (int k = 0; k < 3; k++)
                    in[r * 3 + k] = fs[c * 774 + r * 258 + tid + k];
            const float* w0 = &ws[(cc + c) * 9];
            const float* w1 = &ws[(64 + cc + c) * 9];
#pragma unroll
            for (int t = 0; t < 9; t++) { acc0 += w0[t] * in[t]; acc1 += w1[t] * in[t]; }
        }
    }
    int o = y * 256 + tid;
    out[(size_t)(b * 2 + 0) * Np + o] = acc0 + x[(size_t)(b * 2 + 0) * Np + o];
    out[(size_t)(b * 2 + 1) * Np + o] = acc1 + x[(size_t)(b * 2 + 1) * Np + o];
}

extern "C" void kernel_launch(void* const* d_in, const int* in_sizes, int n_in,
                              void* d_out, int out_size)
{
    const float* x      = (const float*)d_in[0];
    const float* hidden = (const float*)d_in[1];
    const float* W_in   = (const float*)d_in[2];
    const float* b_in   = (const float*)d_in[3];
    const float* gamma  = (const float*)d_in[4];
    const float* beta   = (const float*)d_in[5];
    const float* Wq     = (const float*)d_in[6];
    const float* bq     = (const float*)d_in[7];
    const float* Wk     = (const float*)d_in[8];
    const float* bk     = (const float*)d_in[9];
    const float* Wv     = (const float*)d_in[10];
    const float* bv     = (const float*)d_in[11];
    const float* Wg     = (const float*)d_in[12];
    const float* bg     = (const float*)d_in[13];
    const float* Wp     = (const float*)d_in[14];
    const float* bp     = (const float*)d_in[15];
    const float* W_out  = (const float*)d_in[16];
    const float* b_out  = (const float*)d_in[17];
    float* out = (float*)d_out;
    float* hid_out = out + 262144;

    cudaFuncSetAttribute(pass2_mma_kernel,
                         cudaFuncAttributeMaxDynamicSharedMemorySize, SMEM_P2);

    zero_init_kernel<<<1, 256>>>();
    conv_in_kernel<<<dim3(256, 2), 256>>>(x, W_in, b_in);
    prep_stats_kernel<<<dim3(8, 2), 256>>>();
    for (int l = 0; l < Lnum; l++) {
        int par = l & 1;
        prep_weff_kernel<<<dim3(16, 2), 256>>>(
            par, gamma + l * 64, beta + l * 64,
            Wk + l * 4096, bk + l * 64, Wv + l * 4096, bv + l * 64,
            Wg + l * 8192, bg + l * 128);
        pass2_mma_kernel<<<dim3(74, 2), 256, SMEM_P2>>>();
        updA_kernel<<<dim3(8, 2), 256>>>(hidden + l * 4096, Wq + l * 4096,
                                         bq + l * 64, Wp + l * 4096,
                                         bp + l * 64, hid_out + l * 4096);
        updB_kernel<<<dim3(8, 2), 256>>>(par);
    }
    convout_prep_kernel<<<2, 256>>>(W_out, b_out);
    conv_out_kernel<<<dim3(256, 2), 256>>>(x, out);
}